// round 1
// baseline (speedup 1.0000x reference)
#include <cuda_runtime.h>
#include <math.h>
#include <stdint.h>

// ---------------- problem constants (from setup_inputs, deterministic) ----------
#define LXX     2048
#define LCC     4096
#define DM      1024
#define NH      16
#define HDIM    64
#define HID     2816
#define LTOT    6144          // LX + LC rows through LN1/QKV
#define LOUT    4096          // 2048 x-rows + 2048 ctx-sel rows
#define POS_X   4096
#define POS_C   0
#define HWSP    2048
#define MAXPOS  6144          // max rope position + 1

// ---------------- scratch (device globals; no runtime allocation) ---------------
__device__ float g_hn   [LTOT * DM];        // LN1 output (x rows 0..2047, ctx rows 2048..6143)
__device__ float g_qkv  [LTOT * 3 * DM];    // QKV projection
__device__ float g_qxr  [LXX * DM];         // rope(qx, 4096)
__device__ float g_kxr  [LXX * DM];         // rope(kx, 4096)
__device__ float g_kcr  [LCC * DM];         // rope(kc, 0)
__device__ float g_qselr[2048 * DM];        // rope(q_sel, 2048)
__device__ float g_attn [LOUT * DM];        // rows 0..2047: a1+a2 ; rows 2048..4095: a3
__device__ float g_h1   [LOUT * DM];        // after out-proj + residual
__device__ float g_h1n  [LOUT * DM];        // LN2(h1)
__device__ float g_gate [LOUT * HID];
__device__ float g_up   [LOUT * HID];
__device__ float g_cos  [MAXPOS * 32];
__device__ float g_sin  [MAXPOS * 32];

// ---------------- rope cos/sin table (fp64 angles) ------------------------------
__global__ void build_rope_table() {
    int idx = blockIdx.x * blockDim.x + threadIdx.x;   // < MAXPOS*32
    if (idx >= MAXPOS * 32) return;
    int pos = idx >> 5, j = idx & 31;
    double inv = pow(10000.0, -((double)(2 * j)) / 64.0);
    double ang = (double)pos * inv;
    g_cos[idx] = (float)cos(ang);
    g_sin[idx] = (float)sin(ang);
}

// ---------------- LayerNorm over 1024 cols, one block per row -------------------
__global__ void ln_kernel(const float* __restrict__ in, float* __restrict__ out,
                          const float* __restrict__ gam, const float* __restrict__ bet) {
    __shared__ float sh[32];
    __shared__ float s_mean, s_rstd;
    int row = blockIdx.x, t = threadIdx.x;
    const float* x = in + (size_t)row * DM;
    float v[4];
    float s = 0.f;
#pragma unroll
    for (int i = 0; i < 4; i++) { v[i] = x[t + 256 * i]; s += v[i]; }
#pragma unroll
    for (int o = 16; o; o >>= 1) s += __shfl_xor_sync(0xffffffffu, s, o);
    if ((t & 31) == 0) sh[t >> 5] = s;
    __syncthreads();
    if (t < 32) {
        float z = (t < 8) ? sh[t] : 0.f;
#pragma unroll
        for (int o = 4; o; o >>= 1) z += __shfl_xor_sync(0xffffffffu, z, o);
        if (t == 0) s_mean = z * (1.f / 1024.f);
    }
    __syncthreads();
    float mean = s_mean;
    float q = 0.f;
#pragma unroll
    for (int i = 0; i < 4; i++) { float d = v[i] - mean; q += d * d; }
#pragma unroll
    for (int o = 16; o; o >>= 1) q += __shfl_xor_sync(0xffffffffu, q, o);
    if ((t & 31) == 0) sh[t >> 5] = q;
    __syncthreads();
    if (t < 32) {
        float z = (t < 8) ? sh[t] : 0.f;
#pragma unroll
        for (int o = 4; o; o >>= 1) z += __shfl_xor_sync(0xffffffffu, z, o);
        if (t == 0) s_rstd = rsqrtf(z * (1.f / 1024.f) + 1e-5f);
    }
    __syncthreads();
    float rstd = s_rstd;
#pragma unroll
    for (int i = 0; i < 4; i++) {
        int c = t + 256 * i;
        out[(size_t)row * DM + c] = (v[i] - mean) * rstd * gam[c] + bet[c];
    }
}

// ---------------- RoPE: reads [l][lds] head-blocked, writes [l][1024] -----------
__global__ void rope_kernel(const float* __restrict__ src, int lds,
                            float* __restrict__ dst, int L, int pos0) {
    int idx = blockIdx.x * blockDim.x + threadIdx.x;   // L*16*32
    if (idx >= L * 512) return;
    int j = idx & 31, h = (idx >> 5) & 15, l = idx >> 9;
    int pos = pos0 + l;
    float c = g_cos[pos * 32 + j], s = g_sin[pos * 32 + j];
    const float* p = src + (size_t)l * lds + h * HDIM;
    float t1 = p[j], t2 = p[j + 32];
    float* q = dst + (size_t)l * DM + h * HDIM;
    q[j]      = t1 * c - t2 * s;
    q[j + 32] = t2 * c + t1 * s;
}

// ---------------- SGEMM: C = A(MxK) * B(KxN) [+bias] [+residual] ----------------
// 128x128 block, BK=8, 256 threads, 8x8 micro-tile. M%128==0, N%128==0, K%8==0.
__global__ void sgemm_kernel(const float* __restrict__ A, const float* __restrict__ B,
                             float* __restrict__ C,
                             const float* __restrict__ bias,
                             const float* __restrict__ res0,
                             const float* __restrict__ res1, int split,
                             int M, int N, int K) {
    __shared__ float As[8][128];
    __shared__ float Bs[8][128];
    int tid = threadIdx.x;
    int m0 = blockIdx.y * 128, n0 = blockIdx.x * 128;
    int ty = tid >> 4, tx = tid & 15;
    int aRow = tid >> 1, aCol = (tid & 1) * 4;
    int bRow = tid >> 5, bCol = (tid & 31) * 4;
    float acc[8][8] = {};
    for (int k0 = 0; k0 < K; k0 += 8) {
        float4 av = *(const float4*)(A + (size_t)(m0 + aRow) * K + k0 + aCol);
        float4 bv = *(const float4*)(B + (size_t)(k0 + bRow) * N + n0 + bCol);
        As[aCol + 0][aRow] = av.x; As[aCol + 1][aRow] = av.y;
        As[aCol + 2][aRow] = av.z; As[aCol + 3][aRow] = av.w;
        *(float4*)&Bs[bRow][bCol] = bv;
        __syncthreads();
#pragma unroll
        for (int k = 0; k < 8; k++) {
            float a[8], b[8];
            *(float4*)(a)     = *(const float4*)&As[k][ty * 8];
            *(float4*)(a + 4) = *(const float4*)&As[k][ty * 8 + 4];
            *(float4*)(b)     = *(const float4*)&Bs[k][tx * 8];
            *(float4*)(b + 4) = *(const float4*)&Bs[k][tx * 8 + 4];
#pragma unroll
            for (int i = 0; i < 8; i++)
#pragma unroll
                for (int j = 0; j < 8; j++) acc[i][j] += a[i] * b[j];
        }
        __syncthreads();
    }
#pragma unroll
    for (int i = 0; i < 8; i++) {
        int row = m0 + ty * 8 + i;
        const float* rp = nullptr;
        if (res0) rp = ((row < split) ? res0 : res1) + (size_t)row * N;
#pragma unroll
        for (int j = 0; j < 8; j++) {
            int col = n0 + tx * 8 + j;
            float v = acc[i][j];
            if (bias) v += bias[col];
            if (rp)   v += rp[col];
            C[(size_t)row * N + col] = v;
        }
    }
}

// ---------------- Flash attention, fp32, BQ=64, BK=64, 256 threads --------------
// Q pre-scaled by 1/8 at load. grid = (LQ/64, NH).
__global__ void attn_kernel(const float* __restrict__ Q, int ldq,
                            const float* __restrict__ K, int ldk,
                            const float* __restrict__ V, int ldv,
                            float* __restrict__ O, int ldo,
                            int LK, int causal, int accumulate) {
    extern __shared__ float smem[];
    float* Qt = smem;                 // [64][68] transposed (d-major)
    float* Kt = Qt + 64 * 68;         // [64][68]
    float* Pt = Kt + 64 * 68;         // [64][68]
    float* Vs = Pt + 64 * 68;         // [64][64]
    int tid = threadIdx.x;
    int ty = tid >> 4, tx = tid & 15;
    int q0 = blockIdx.x * 64;
    int h  = blockIdx.y;
    const float* Qh = Q + h * HDIM;
    const float* Kh = K + h * HDIM;
    const float* Vh = V + h * HDIM;

#pragma unroll
    for (int it = 0; it < 4; it++) {
        int idx = tid + it * 256;          // 0..1023
        int qi = idx >> 4;
        int d4 = (idx & 15) << 2;
        float4 v = *(const float4*)(Qh + (size_t)(q0 + qi) * ldq + d4);
        Qt[(d4 + 0) * 68 + qi] = v.x * 0.125f;
        Qt[(d4 + 1) * 68 + qi] = v.y * 0.125f;
        Qt[(d4 + 2) * 68 + qi] = v.z * 0.125f;
        Qt[(d4 + 3) * 68 + qi] = v.w * 0.125f;
    }

    float acc[4][4] = {};
    float m_i[4], l_i[4];
#pragma unroll
    for (int i = 0; i < 4; i++) { m_i[i] = -1e30f; l_i[i] = 0.f; }

    int ntiles = causal ? ((int)blockIdx.x + 1) : (LK >> 6);
    for (int kt = 0; kt < ntiles; kt++) {
        int k0 = kt << 6;
        __syncthreads();   // prior PV done (and first-iter Qt visible)
#pragma unroll
        for (int it = 0; it < 4; it++) {
            int idx = tid + it * 256;
            int ki = idx >> 4;
            int d4 = (idx & 15) << 2;
            float4 kv = *(const float4*)(Kh + (size_t)(k0 + ki) * ldk + d4);
            Kt[(d4 + 0) * 68 + ki] = kv.x; Kt[(d4 + 1) * 68 + ki] = kv.y;
            Kt[(d4 + 2) * 68 + ki] = kv.z; Kt[(d4 + 3) * 68 + ki] = kv.w;
            float4 vv = *(const float4*)(Vh + (size_t)(k0 + ki) * ldv + d4);
            *(float4*)&Vs[ki * 64 + d4] = vv;
        }
        __syncthreads();

        float s[4][4] = {};
#pragma unroll
        for (int d = 0; d < 64; d++) {
            float4 a4 = *(const float4*)&Qt[d * 68 + ty * 4];
            float4 b4 = *(const float4*)&Kt[d * 68 + tx * 4];
            float av[4] = {a4.x, a4.y, a4.z, a4.w};
            float bv[4] = {b4.x, b4.y, b4.z, b4.w};
#pragma unroll
            for (int i = 0; i < 4; i++)
#pragma unroll
                for (int j = 0; j < 4; j++) s[i][j] += av[i] * bv[j];
        }
        if (causal && kt == (int)blockIdx.x) {
#pragma unroll
            for (int i = 0; i < 4; i++)
#pragma unroll
                for (int j = 0; j < 4; j++)
                    if (k0 + tx * 4 + j > q0 + ty * 4 + i) s[i][j] = -1e30f;
        }
#pragma unroll
        for (int i = 0; i < 4; i++) {
            float mx = fmaxf(fmaxf(s[i][0], s[i][1]), fmaxf(s[i][2], s[i][3]));
#pragma unroll
            for (int o = 1; o < 16; o <<= 1) mx = fmaxf(mx, __shfl_xor_sync(0xffffffffu, mx, o));
            float mnew = fmaxf(m_i[i], mx);
            float alpha = __expf(m_i[i] - mnew);
            float rs = 0.f;
#pragma unroll
            for (int j = 0; j < 4; j++) { s[i][j] = __expf(s[i][j] - mnew); rs += s[i][j]; }
#pragma unroll
            for (int o = 1; o < 16; o <<= 1) rs += __shfl_xor_sync(0xffffffffu, rs, o);
            l_i[i] = l_i[i] * alpha + rs;
            m_i[i] = mnew;
#pragma unroll
            for (int j = 0; j < 4; j++) acc[i][j] *= alpha;
        }
#pragma unroll
        for (int i = 0; i < 4; i++)
#pragma unroll
            for (int j = 0; j < 4; j++)
                Pt[(tx * 4 + j) * 68 + (ty * 4 + i)] = s[i][j];
        __syncthreads();
#pragma unroll
        for (int k = 0; k < 64; k++) {
            float4 a4 = *(const float4*)&Pt[k * 68 + ty * 4];
            float4 b4 = *(const float4*)&Vs[k * 64 + tx * 4];
            float av[4] = {a4.x, a4.y, a4.z, a4.w};
            float bv[4] = {b4.x, b4.y, b4.z, b4.w};
#pragma unroll
            for (int i = 0; i < 4; i++)
#pragma unroll
                for (int j = 0; j < 4; j++) acc[i][j] += av[i] * bv[j];
        }
    }
#pragma unroll
    for (int i = 0; i < 4; i++) {
        float inv = 1.f / l_i[i];
        int row = q0 + ty * 4 + i;
        float* op = O + (size_t)row * ldo + h * HDIM + tx * 4;
        if (accumulate) {
#pragma unroll
            for (int j = 0; j < 4; j++) op[j] += acc[i][j] * inv;
        } else {
            float4 v = make_float4(acc[i][0] * inv, acc[i][1] * inv,
                                   acc[i][2] * inv, acc[i][3] * inv);
            *(float4*)op = v;
        }
    }
}

// ---------------- silu(g)*u in place into g -------------------------------------
__global__ void silu_mul_kernel(float* __restrict__ g, const float* __restrict__ u, int n) {
    int i = blockIdx.x * blockDim.x + threadIdx.x;
    if (i < n) {
        float x = g[i];
        g[i] = (x / (1.f + __expf(-x))) * u[i];
    }
}

// ---------------- host orchestration --------------------------------------------
static const int ATTN_SMEM = (3 * 64 * 68 + 64 * 64) * 4;   // 68608 B

extern "C" void kernel_launch(void* const* d_in, const int* in_sizes, int n_in,
                              void* d_out, int out_size) {
    const float* x     = (const float*)d_in[0];
    const float* ctx   = (const float*)d_in[1];
    const float* qkv_w = (const float*)d_in[2];
    const float* qkv_b = (const float*)d_in[3];
    const float* out_w = (const float*)d_in[4];
    const float* out_b = (const float*)d_in[5];
    const float* w1    = (const float*)d_in[6];
    const float* w3    = (const float*)d_in[7];
    const float* w2    = (const float*)d_in[8];
    const float* n1g   = (const float*)d_in[9];
    const float* n1b   = (const float*)d_in[10];
    const float* n2g   = (const float*)d_in[11];
    const float* n2b   = (const float*)d_in[12];
    float* out = (float*)d_out;

    cudaFuncSetAttribute(attn_kernel, cudaFuncAttributeMaxDynamicSharedMemorySize, ATTN_SMEM);

    void* p;
    cudaGetSymbolAddress(&p, g_hn);    float* hn    = (float*)p;
    cudaGetSymbolAddress(&p, g_qkv);   float* qkv   = (float*)p;
    cudaGetSymbolAddress(&p, g_qxr);   float* qxr   = (float*)p;
    cudaGetSymbolAddress(&p, g_kxr);   float* kxr   = (float*)p;
    cudaGetSymbolAddress(&p, g_kcr);   float* kcr   = (float*)p;
    cudaGetSymbolAddress(&p, g_qselr); float* qselr = (float*)p;
    cudaGetSymbolAddress(&p, g_attn);  float* attn  = (float*)p;
    cudaGetSymbolAddress(&p, g_h1);    float* h1    = (float*)p;
    cudaGetSymbolAddress(&p, g_h1n);   float* h1n   = (float*)p;
    cudaGetSymbolAddress(&p, g_gate);  float* gate  = (float*)p;
    cudaGetSymbolAddress(&p, g_up);    float* up    = (float*)p;

    // rope tables
    build_rope_table<<<(MAXPOS * 32 + 255) / 256, 256>>>();

    // LN1 for x and context into combined buffer
    ln_kernel<<<LXX, 256>>>(x,   hn,                 n1g, n1b);
    ln_kernel<<<LCC, 256>>>(ctx, hn + (size_t)LXX * DM, n1g, n1b);

    // QKV projection over all 6144 rows
    {
        dim3 grid(3 * DM / 128, LTOT / 128);
        sgemm_kernel<<<grid, 256>>>(hn, qkv_w, qkv, qkv_b, nullptr, nullptr, 0,
                                    LTOT, 3 * DM, DM);
    }

    // RoPE
    rope_kernel<<<(LXX * 512 + 255) / 256, 256>>>(qkv,                         3 * DM, qxr,   LXX, POS_X);
    rope_kernel<<<(LXX * 512 + 255) / 256, 256>>>(qkv + DM,                    3 * DM, kxr,   LXX, POS_X);
    rope_kernel<<<(LCC * 512 + 255) / 256, 256>>>(qkv + (size_t)LXX * 3 * DM + DM, 3 * DM, kcr, LCC, POS_C);
    rope_kernel<<<(2048 * 512 + 255) / 256, 256>>>(qkv + (size_t)(LXX + HWSP) * 3 * DM, 3 * DM, qselr, 2048, HWSP);

    const float* vx = qkv + 2 * DM;                            // rows 0..2047
    const float* vc = qkv + (size_t)LXX * 3 * DM + 2 * DM;     // rows 2048..6143

    // a1: qx vs kc/vc (non-causal), write rows 0..2047 of attn
    attn_kernel<<<dim3(LXX / 64, NH), 256, ATTN_SMEM>>>(qxr, DM, kcr, DM, vc, 3 * DM,
                                                        attn, DM, LCC, 0, 0);
    // a2: qx vs kx/vx (causal), accumulate
    attn_kernel<<<dim3(LXX / 64, NH), 256, ATTN_SMEM>>>(qxr, DM, kxr, DM, vx, 3 * DM,
                                                        attn, DM, LXX, 1, 1);
    // a3: q_sel vs kc/vc (non-causal), rows 2048..4095
    attn_kernel<<<dim3(2048 / 64, NH), 256, ATTN_SMEM>>>(qselr, DM, kcr, DM, vc, 3 * DM,
                                                         attn + (size_t)2048 * DM, DM, LCC, 0, 0);

    // out projection + bias + residual (rows<2048: x ; rows>=2048: context[row])
    {
        dim3 grid(DM / 128, LOUT / 128);
        sgemm_kernel<<<grid, 256>>>(attn, out_w, h1, out_b, x, ctx, 2048,
                                    LOUT, DM, DM);
    }

    // LN2
    ln_kernel<<<LOUT, 256>>>(h1, h1n, n2g, n2b);

    // FFN
    {
        dim3 grid(HID / 128, LOUT / 128);
        sgemm_kernel<<<grid, 256>>>(h1n, w1, gate, nullptr, nullptr, nullptr, 0,
                                    LOUT, HID, DM);
        sgemm_kernel<<<grid, 256>>>(h1n, w3, up, nullptr, nullptr, nullptr, 0,
                                    LOUT, HID, DM);
    }
    silu_mul_kernel<<<(LOUT * HID + 255) / 256, 256>>>(gate, up, LOUT * HID);
    {
        dim3 grid(DM / 128, LOUT / 128);
        sgemm_kernel<<<grid, 256>>>(gate, w2, out, nullptr, h1, h1, LOUT,
                                    LOUT, DM, HID);
    }
}

// round 3
// speedup vs baseline: 1.2667x; 1.2667x over previous
#include <cuda_runtime.h>
#include <cuda_bf16.h>
#include <math.h>
#include <stdint.h>

// ---------------- problem constants (from setup_inputs, deterministic) ----------
#define LXX     2048
#define LCC     4096
#define DM      1024
#define NH      16
#define HDIM    64
#define HID     2816
#define LTOT    6144
#define LOUT    4096
#define POS_X   4096
#define POS_C   0
#define HWSP    2048
#define MAXPOS  6144

// ---------------- scratch (device globals; no runtime allocation) ---------------
__device__ float g_hn   [LTOT * DM];
__device__ float g_qkv  [LTOT * 3 * DM];
__device__ float g_qxr  [LXX * DM];
__device__ float g_kxr  [LXX * DM];
__device__ float g_kcr  [LCC * DM];
__device__ float g_qselr[2048 * DM];
__device__ float g_attn [LOUT * DM];
__device__ float g_h1   [LOUT * DM];
__device__ float g_h1n  [LOUT * DM];
__device__ float g_gate [LOUT * HID];
__device__ float g_up   [LOUT * HID];
__device__ float g_cos  [MAXPOS * 32];
__device__ float g_sin  [MAXPOS * 32];

// split-bf16 activation scratch (max rows*cols = LOUT*HID)
__device__ __nv_bfloat16 g_act_hi[LOUT * HID];
__device__ __nv_bfloat16 g_act_lo[LOUT * HID];
// split-bf16 transposed weights [N][K]
__device__ __nv_bfloat16 g_wqkv_hi[3 * DM * DM], g_wqkv_lo[3 * DM * DM];
__device__ __nv_bfloat16 g_wout_hi[DM * DM],     g_wout_lo[DM * DM];
__device__ __nv_bfloat16 g_w1_hi [HID * DM],     g_w1_lo [HID * DM];
__device__ __nv_bfloat16 g_w3_hi [HID * DM],     g_w3_lo [HID * DM];
__device__ __nv_bfloat16 g_w2_hi [DM * HID],     g_w2_lo [DM * HID];

// ---------------- mma.sync helpers (portable: sm_80+ PTX, no tcgen05) -----------
__device__ __forceinline__ uint32_t smem_to_u32(const void* p) {
    uint32_t a;
    asm("{ .reg .u64 t; cvta.to.shared.u64 t, %1; cvt.u32.u64 %0, t; }" : "=r"(a) : "l"(p));
    return a;
}
#define SMEM_SWIZZLE_128B(b) ((b) ^ (((b) >> 3) & 0x70))

__device__ __forceinline__ void ldsm_x4(uint32_t* r, uint32_t addr) {
    asm volatile("ldmatrix.sync.aligned.m8n8.x4.shared.b16 {%0,%1,%2,%3}, [%4];"
        : "=r"(r[0]), "=r"(r[1]), "=r"(r[2]), "=r"(r[3]) : "r"(addr));
}
__device__ __forceinline__ void mma_bf16(float* c, const uint32_t* a, const uint32_t* b) {
    asm volatile("mma.sync.aligned.m16n8k16.row.col.f32.bf16.bf16.f32 "
        "{%0,%1,%2,%3}, {%4,%5,%6,%7}, {%8,%9}, {%0,%1,%2,%3};"
        : "+f"(c[0]), "+f"(c[1]), "+f"(c[2]), "+f"(c[3])
        : "r"(a[0]), "r"(a[1]), "r"(a[2]), "r"(a[3]), "r"(b[0]), "r"(b[1]));
}

// ---------------- rope cos/sin table (fp64 angles) -------------------------------
__global__ void build_rope_table() {
    int idx = blockIdx.x * blockDim.x + threadIdx.x;
    if (idx >= MAXPOS * 32) return;
    int pos = idx >> 5, j = idx & 31;
    double inv = pow(10000.0, -((double)(2 * j)) / 64.0);
    double ang = (double)pos * inv;
    g_cos[idx] = (float)cos(ang);
    g_sin[idx] = (float)sin(ang);
}

// ---------------- LayerNorm over 1024 cols ---------------------------------------
__global__ void ln_kernel(const float* __restrict__ in, float* __restrict__ out,
                          const float* __restrict__ gam, const float* __restrict__ bet) {
    __shared__ float sh[32];
    __shared__ float s_mean, s_rstd;
    int row = blockIdx.x, t = threadIdx.x;
    const float* x = in + (size_t)row * DM;
    float v[4];
    float s = 0.f;
#pragma unroll
    for (int i = 0; i < 4; i++) { v[i] = x[t + 256 * i]; s += v[i]; }
#pragma unroll
    for (int o = 16; o; o >>= 1) s += __shfl_xor_sync(0xffffffffu, s, o);
    if ((t & 31) == 0) sh[t >> 5] = s;
    __syncthreads();
    if (t < 32) {
        float z = (t < 8) ? sh[t] : 0.f;
#pragma unroll
        for (int o = 4; o; o >>= 1) z += __shfl_xor_sync(0xffffffffu, z, o);
        if (t == 0) s_mean = z * (1.f / 1024.f);
    }
    __syncthreads();
    float mean = s_mean;
    float q = 0.f;
#pragma unroll
    for (int i = 0; i < 4; i++) { float d = v[i] - mean; q += d * d; }
#pragma unroll
    for (int o = 16; o; o >>= 1) q += __shfl_xor_sync(0xffffffffu, q, o);
    if ((t & 31) == 0) sh[t >> 5] = q;
    __syncthreads();
    if (t < 32) {
        float z = (t < 8) ? sh[t] : 0.f;
#pragma unroll
        for (int o = 4; o; o >>= 1) z += __shfl_xor_sync(0xffffffffu, z, o);
        if (t == 0) s_rstd = rsqrtf(z * (1.f / 1024.f) + 1e-5f);
    }
    __syncthreads();
    float rstd = s_rstd;
#pragma unroll
    for (int i = 0; i < 4; i++) {
        int c = t + 256 * i;
        out[(size_t)row * DM + c] = (v[i] - mean) * rstd * gam[c] + bet[c];
    }
}

// ---------------- RoPE ------------------------------------------------------------
__global__ void rope_kernel(const float* __restrict__ src, int lds,
                            float* __restrict__ dst, int L, int pos0) {
    int idx = blockIdx.x * blockDim.x + threadIdx.x;
    if (idx >= L * 512) return;
    int j = idx & 31, h = (idx >> 5) & 15, l = idx >> 9;
    int pos = pos0 + l;
    float c = g_cos[pos * 32 + j], s = g_sin[pos * 32 + j];
    const float* p = src + (size_t)l * lds + h * HDIM;
    float t1 = p[j], t2 = p[j + 32];
    float* q = dst + (size_t)l * DM + h * HDIM;
    q[j]      = t1 * c - t2 * s;
    q[j + 32] = t2 * c + t1 * s;
}

// ---------------- fp32 -> split bf16 (elementwise) --------------------------------
__global__ void act_split_kernel(const float* __restrict__ in,
                                 __nv_bfloat16* __restrict__ hi,
                                 __nv_bfloat16* __restrict__ lo, int n2) {
    int i = blockIdx.x * blockDim.x + threadIdx.x;
    if (i >= n2) return;
    float2 v = ((const float2*)in)[i];
    __nv_bfloat16 hx = __float2bfloat16(v.x);
    __nv_bfloat16 hy = __float2bfloat16(v.y);
    __nv_bfloat162 h, l;
    h.x = hx; h.y = hy;
    l.x = __float2bfloat16(v.x - __bfloat162float(hx));
    l.y = __float2bfloat16(v.y - __bfloat162float(hy));
    ((__nv_bfloat162*)hi)[i] = h;
    ((__nv_bfloat162*)lo)[i] = l;
}

// ---------------- weight transpose + split: [K][N] fp32 -> [N][K] bf16 hi/lo ------
__global__ void wt_split_kernel(const float* __restrict__ w,
                                __nv_bfloat16* __restrict__ hi,
                                __nv_bfloat16* __restrict__ lo, int K, int N) {
    __shared__ float t[32][33];
    int n0 = blockIdx.x * 32, k0 = blockIdx.y * 32;
    int tx = threadIdx.x, ty = threadIdx.y;
#pragma unroll
    for (int i = 0; i < 32; i += 8)
        t[ty + i][tx] = w[(size_t)(k0 + ty + i) * N + n0 + tx];
    __syncthreads();
#pragma unroll
    for (int i = 0; i < 32; i += 8) {
        int n = n0 + ty + i, k = k0 + tx;
        float v = t[tx][ty + i];
        __nv_bfloat16 h = __float2bfloat16(v);
        hi[(size_t)n * K + k] = h;
        lo[(size_t)n * K + k] = __float2bfloat16(v - __bfloat162float(h));
    }
}

// ---------------- mma.sync split-bf16 GEMM ----------------------------------------
// C[M][N] = A[M][K] * Bt[N][K]^T, fp32 accum, 3 passes (Ah*Bh + Ah*Bl + Al*Bh).
// CTA tile 128x128, BK=64, 256 threads = 8 warps (2x4), warp tile 64x32.
static const int GEMM_SMEM = 4 * 16384;   // Ahi, Alo, Bhi, Blo : 128x64 bf16 each

__global__ void __launch_bounds__(256)
mma_gemm_kernel(const __nv_bfloat16* __restrict__ Ahi, const __nv_bfloat16* __restrict__ Alo,
                const __nv_bfloat16* __restrict__ Bhi, const __nv_bfloat16* __restrict__ Blo,
                float* __restrict__ C, const float* __restrict__ bias,
                const float* __restrict__ res0, const float* __restrict__ res1, int split,
                int M, int N, int K) {
    extern __shared__ char smem[];
    char* pA_hi = smem;
    char* pA_lo = pA_hi + 16384;
    char* pB_hi = pA_lo + 16384;
    char* pB_lo = pB_hi + 16384;
    uint32_t sA_hi = smem_to_u32(pA_hi);
    uint32_t sA_lo = sA_hi + 16384;
    uint32_t sB_hi = sA_lo + 16384;
    uint32_t sB_lo = sB_hi + 16384;

    int tid = threadIdx.x;
    int wid = tid >> 5, lane = tid & 31;
    int wr = wid >> 2, wc = wid & 3;              // 2 x 4 warp grid
    int m0 = blockIdx.y * 128, n0 = blockIdx.x * 128;

    int lr  = lane & 7;
    int lq  = lane >> 3;
    int qlo = lq & 1, qhi = lq >> 1;

    // per-lane swizzled base byte offsets for ldmatrix
    // A (row-major, 16-row m-tiles): rows split by qlo, k-halves by qhi
    uint32_t aoff[4];
#pragma unroll
    for (int mt = 0; mt < 4; mt++) {
        int row = wr * 64 + mt * 16 + qlo * 8 + lr;
        aoff[mt] = (uint32_t)(row * 128) + (uint32_t)((qhi * 16) ^ ((row & 7) * 16));
    }
    // B ([N][K] col-major of B, 8-row n-tile pairs): rows split by qhi, k-halves by qlo
    uint32_t boff[2];
#pragma unroll
    for (int np = 0; np < 2; np++) {
        int row = wc * 32 + np * 16 + qhi * 8 + lr;
        boff[np] = (uint32_t)(row * 128) + (uint32_t)((qlo * 16) ^ ((row & 7) * 16));
    }

    float acc[4][4][4] = {};   // [mt][nt][frag]

    int nchunks = K >> 6;
    for (int kc = 0; kc < nchunks; kc++) {
        int kc0 = kc << 6;
#pragma unroll
        for (int it = 0; it < 4; it++) {
            int idx = tid + it * 256;       // 0..1023
            int r = idx >> 3;
            int q = idx & 7;
            uint32_t so = SMEM_SWIZZLE_128B((uint32_t)(r * 128 + q * 16));
            *(uint4*)(pA_hi + so) = *(const uint4*)(Ahi + (size_t)(m0 + r) * K + kc0 + q * 8);
            *(uint4*)(pA_lo + so) = *(const uint4*)(Alo + (size_t)(m0 + r) * K + kc0 + q * 8);
            *(uint4*)(pB_hi + so) = *(const uint4*)(Bhi + (size_t)(n0 + r) * K + kc0 + q * 8);
            *(uint4*)(pB_lo + so) = *(const uint4*)(Blo + (size_t)(n0 + r) * K + kc0 + q * 8);
        }
        __syncthreads();

#pragma unroll
        for (int ks = 0; ks < 4; ks++) {
            uint32_t kx = (uint32_t)(ks << 5);
            uint32_t bh[2][4], bl[2][4];
#pragma unroll
            for (int np = 0; np < 2; np++) {
                ldsm_x4(bh[np], sB_hi + (boff[np] ^ kx));
                ldsm_x4(bl[np], sB_lo + (boff[np] ^ kx));
            }
#pragma unroll
            for (int mt = 0; mt < 4; mt++) {
                uint32_t ah[4];
                ldsm_x4(ah, sA_hi + (aoff[mt] ^ kx));
#pragma unroll
                for (int nt = 0; nt < 4; nt++) {
                    mma_bf16(acc[mt][nt], ah, &bh[nt >> 1][(nt & 1) * 2]);
                    mma_bf16(acc[mt][nt], ah, &bl[nt >> 1][(nt & 1) * 2]);
                }
                uint32_t al[4];
                ldsm_x4(al, sA_lo + (aoff[mt] ^ kx));
#pragma unroll
                for (int nt = 0; nt < 4; nt++)
                    mma_bf16(acc[mt][nt], al, &bh[nt >> 1][(nt & 1) * 2]);
            }
        }
        __syncthreads();
    }

    // epilogue: fragment owner lane (g = lane>>2 row, tg = lane&3 col-pair)
    int g = lane >> 2, tg = lane & 3;
#pragma unroll
    for (int mt = 0; mt < 4; mt++) {
#pragma unroll
        for (int half = 0; half < 2; half++) {
            int row = m0 + wr * 64 + mt * 16 + g + half * 8;
            const float* rp = nullptr;
            if (res0) rp = ((row < split) ? res0 : res1) + (size_t)row * N;
            float* cp = C + (size_t)row * N;
#pragma unroll
            for (int nt = 0; nt < 4; nt++) {
                int col = n0 + wc * 32 + nt * 8 + tg * 2;
                float2 v;
                v.x = acc[mt][nt][half * 2 + 0];
                v.y = acc[mt][nt][half * 2 + 1];
                if (bias) { v.x += bias[col]; v.y += bias[col + 1]; }
                if (rp)   { v.x += rp[col];   v.y += rp[col + 1]; }
                *(float2*)(cp + col) = v;
            }
        }
    }
}

// ---------------- Flash attention, fp32, BQ=64, BK=64, 256 threads ----------------
__global__ void attn_kernel(const float* __restrict__ Q, int ldq,
                            const float* __restrict__ K, int ldk,
                            const float* __restrict__ V, int ldv,
                            float* __restrict__ O, int ldo,
                            int LK, int causal, int accumulate) {
    extern __shared__ float fsm[];
    float* Qt = fsm;
    float* Kt = Qt + 64 * 68;
    float* Pt = Kt + 64 * 68;
    float* Vs = Pt + 64 * 68;
    int tid = threadIdx.x;
    int ty = tid >> 4, tx = tid & 15;
    int q0 = blockIdx.x * 64;
    int h  = blockIdx.y;
    const float* Qh = Q + h * HDIM;
    const float* Kh = K + h * HDIM;
    const float* Vh = V + h * HDIM;

#pragma unroll
    for (int it = 0; it < 4; it++) {
        int idx = tid + it * 256;
        int qi = idx >> 4;
        int d4 = (idx & 15) << 2;
        float4 v = *(const float4*)(Qh + (size_t)(q0 + qi) * ldq + d4);
        Qt[(d4 + 0) * 68 + qi] = v.x * 0.125f;
        Qt[(d4 + 1) * 68 + qi] = v.y * 0.125f;
        Qt[(d4 + 2) * 68 + qi] = v.z * 0.125f;
        Qt[(d4 + 3) * 68 + qi] = v.w * 0.125f;
    }

    float acc[4][4] = {};
    float m_i[4], l_i[4];
#pragma unroll
    for (int i = 0; i < 4; i++) { m_i[i] = -1e30f; l_i[i] = 0.f; }

    int ntiles = causal ? ((int)blockIdx.x + 1) : (LK >> 6);
    for (int kt = 0; kt < ntiles; kt++) {
        int k0 = kt << 6;
        __syncthreads();
#pragma unroll
        for (int it = 0; it < 4; it++) {
            int idx = tid + it * 256;
            int ki = idx >> 4;
            int d4 = (idx & 15) << 2;
            float4 kv = *(const float4*)(Kh + (size_t)(k0 + ki) * ldk + d4);
            Kt[(d4 + 0) * 68 + ki] = kv.x; Kt[(d4 + 1) * 68 + ki] = kv.y;
            Kt[(d4 + 2) * 68 + ki] = kv.z; Kt[(d4 + 3) * 68 + ki] = kv.w;
            float4 vv = *(const float4*)(Vh + (size_t)(k0 + ki) * ldv + d4);
            *(float4*)&Vs[ki * 64 + d4] = vv;
        }
        __syncthreads();

        float s[4][4] = {};
#pragma unroll
        for (int d = 0; d < 64; d++) {
            float4 a4 = *(const float4*)&Qt[d * 68 + ty * 4];
            float4 b4 = *(const float4*)&Kt[d * 68 + tx * 4];
            float av[4] = {a4.x, a4.y, a4.z, a4.w};
            float bv[4] = {b4.x, b4.y, b4.z, b4.w};
#pragma unroll
            for (int i = 0; i < 4; i++)
#pragma unroll
                for (int j = 0; j < 4; j++) s[i][j] += av[i] * bv[j];
        }
        if (causal && kt == (int)blockIdx.x) {
#pragma unroll
            for (int i = 0; i < 4; i++)
#pragma unroll
                for (int j = 0; j < 4; j++)
                    if (k0 + tx * 4 + j > q0 + ty * 4 + i) s[i][j] = -1e30f;
        }
#pragma unroll
        for (int i = 0; i < 4; i++) {
            float mx = fmaxf(fmaxf(s[i][0], s[i][1]), fmaxf(s[i][2], s[i][3]));
#pragma unroll
            for (int o = 1; o < 16; o <<= 1) mx = fmaxf(mx, __shfl_xor_sync(0xffffffffu, mx, o));
            float mnew = fmaxf(m_i[i], mx);
            float alpha = __expf(m_i[i] - mnew);
            float rs = 0.f;
#pragma unroll
            for (int j = 0; j < 4; j++) { s[i][j] = __expf(s[i][j] - mnew); rs += s[i][j]; }
#pragma unroll
            for (int o = 1; o < 16; o <<= 1) rs += __shfl_xor_sync(0xffffffffu, rs, o);
            l_i[i] = l_i[i] * alpha + rs;
            m_i[i] = mnew;
#pragma unroll
            for (int j = 0; j < 4; j++) acc[i][j] *= alpha;
        }
#pragma unroll
        for (int i = 0; i < 4; i++)
#pragma unroll
            for (int j = 0; j < 4; j++)
                Pt[(tx * 4 + j) * 68 + (ty * 4 + i)] = s[i][j];
        __syncthreads();
#pragma unroll
        for (int k = 0; k < 64; k++) {
            float4 a4 = *(const float4*)&Pt[k * 68 + ty * 4];
            float4 b4 = *(const float4*)&Vs[k * 64 + tx * 4];
            float av[4] = {a4.x, a4.y, a4.z, a4.w};
            float bv[4] = {b4.x, b4.y, b4.z, b4.w};
#pragma unroll
            for (int i = 0; i < 4; i++)
#pragma unroll
                for (int j = 0; j < 4; j++) acc[i][j] += av[i] * bv[j];
        }
    }
#pragma unroll
    for (int i = 0; i < 4; i++) {
        float inv = 1.f / l_i[i];
        int row = q0 + ty * 4 + i;
        float* op = O + (size_t)row * ldo + h * HDIM + tx * 4;
        if (accumulate) {
#pragma unroll
            for (int j = 0; j < 4; j++) op[j] += acc[i][j] * inv;
        } else {
            float4 v = make_float4(acc[i][0] * inv, acc[i][1] * inv,
                                   acc[i][2] * inv, acc[i][3] * inv);
            *(float4*)op = v;
        }
    }
}

// ---------------- silu(g)*u in place into g ---------------------------------------
__global__ void silu_mul_kernel(float* __restrict__ g, const float* __restrict__ u, int n) {
    int i = blockIdx.x * blockDim.x + threadIdx.x;
    if (i < n) {
        float x = g[i];
        g[i] = (x / (1.f + __expf(-x))) * u[i];
    }
}

// ---------------- host orchestration ----------------------------------------------
static const int ATTN_SMEM = (3 * 64 * 68 + 64 * 64) * 4;

extern "C" void kernel_launch(void* const* d_in, const int* in_sizes, int n_in,
                              void* d_out, int out_size) {
    const float* x     = (const float*)d_in[0];
    const float* ctx   = (const float*)d_in[1];
    const float* qkv_w = (const float*)d_in[2];
    const float* qkv_b = (const float*)d_in[3];
    const float* out_w = (const float*)d_in[4];
    const float* out_b = (const float*)d_in[5];
    const float* w1    = (const float*)d_in[6];
    const float* w3    = (const float*)d_in[7];
    const float* w2    = (const float*)d_in[8];
    const float* n1g   = (const float*)d_in[9];
    const float* n1b   = (const float*)d_in[10];
    const float* n2g   = (const float*)d_in[11];
    const float* n2b   = (const float*)d_in[12];
    float* out = (float*)d_out;

    cudaFuncSetAttribute(attn_kernel, cudaFuncAttributeMaxDynamicSharedMemorySize, ATTN_SMEM);
    cudaFuncSetAttribute(mma_gemm_kernel, cudaFuncAttributeMaxDynamicSharedMemorySize, GEMM_SMEM);

    void* p;
    cudaGetSymbolAddress(&p, g_hn);    float* hn    = (float*)p;
    cudaGetSymbolAddress(&p, g_qkv);   float* qkv   = (float*)p;
    cudaGetSymbolAddress(&p, g_qxr);   float* qxr   = (float*)p;
    cudaGetSymbolAddress(&p, g_kxr);   float* kxr   = (float*)p;
    cudaGetSymbolAddress(&p, g_kcr);   float* kcr   = (float*)p;
    cudaGetSymbolAddress(&p, g_qselr); float* qselr = (float*)p;
    cudaGetSymbolAddress(&p, g_attn);  float* attn  = (float*)p;
    cudaGetSymbolAddress(&p, g_h1);    float* h1    = (float*)p;
    cudaGetSymbolAddress(&p, g_h1n);   float* h1n   = (float*)p;
    cudaGetSymbolAddress(&p, g_gate);  float* gate  = (float*)p;
    cudaGetSymbolAddress(&p, g_up);    float* up    = (float*)p;
    cudaGetSymbolAddress(&p, g_act_hi); __nv_bfloat16* ahi = (__nv_bfloat16*)p;
    cudaGetSymbolAddress(&p, g_act_lo); __nv_bfloat16* alo = (__nv_bfloat16*)p;
    cudaGetSymbolAddress(&p, g_wqkv_hi); __nv_bfloat16* wqhi = (__nv_bfloat16*)p;
    cudaGetSymbolAddress(&p, g_wqkv_lo); __nv_bfloat16* wqlo = (__nv_bfloat16*)p;
    cudaGetSymbolAddress(&p, g_wout_hi); __nv_bfloat16* wohi = (__nv_bfloat16*)p;
    cudaGetSymbolAddress(&p, g_wout_lo); __nv_bfloat16* wolo = (__nv_bfloat16*)p;
    cudaGetSymbolAddress(&p, g_w1_hi);  __nv_bfloat16* w1hi = (__nv_bfloat16*)p;
    cudaGetSymbolAddress(&p, g_w1_lo);  __nv_bfloat16* w1lo = (__nv_bfloat16*)p;
    cudaGetSymbolAddress(&p, g_w3_hi);  __nv_bfloat16* w3hi = (__nv_bfloat16*)p;
    cudaGetSymbolAddress(&p, g_w3_lo);  __nv_bfloat16* w3lo = (__nv_bfloat16*)p;
    cudaGetSymbolAddress(&p, g_w2_hi);  __nv_bfloat16* w2hi = (__nv_bfloat16*)p;
    cudaGetSymbolAddress(&p, g_w2_lo);  __nv_bfloat16* w2lo = (__nv_bfloat16*)p;

    dim3 tb(32, 8);
    build_rope_table<<<(MAXPOS * 32 + 255) / 256, 256>>>();

    // weight transpose+split
    wt_split_kernel<<<dim3(3 * DM / 32, DM / 32), tb>>>(qkv_w, wqhi, wqlo, DM, 3 * DM);
    wt_split_kernel<<<dim3(DM / 32, DM / 32),     tb>>>(out_w, wohi, wolo, DM, DM);
    wt_split_kernel<<<dim3(HID / 32, DM / 32),    tb>>>(w1, w1hi, w1lo, DM, HID);
    wt_split_kernel<<<dim3(HID / 32, DM / 32),    tb>>>(w3, w3hi, w3lo, DM, HID);
    wt_split_kernel<<<dim3(DM / 32, HID / 32),    tb>>>(w2, w2hi, w2lo, HID, DM);

    // LN1
    ln_kernel<<<LXX, 256>>>(x,   hn,                    n1g, n1b);
    ln_kernel<<<LCC, 256>>>(ctx, hn + (size_t)LXX * DM, n1g, n1b);

    // QKV projection
    act_split_kernel<<<(LTOT * DM / 2 + 255) / 256, 256>>>(hn, ahi, alo, LTOT * DM / 2);
    mma_gemm_kernel<<<dim3(3 * DM / 128, LTOT / 128), 256, GEMM_SMEM>>>(
        ahi, alo, wqhi, wqlo, qkv, qkv_b, nullptr, nullptr, 0, LTOT, 3 * DM, DM);

    // RoPE
    rope_kernel<<<(LXX * 512 + 255) / 256, 256>>>(qkv,                              3 * DM, qxr,   LXX, POS_X);
    rope_kernel<<<(LXX * 512 + 255) / 256, 256>>>(qkv + DM,                         3 * DM, kxr,   LXX, POS_X);
    rope_kernel<<<(LCC * 512 + 255) / 256, 256>>>(qkv + (size_t)LXX * 3 * DM + DM,  3 * DM, kcr,   LCC, POS_C);
    rope_kernel<<<(2048 * 512 + 255) / 256, 256>>>(qkv + (size_t)(LXX + HWSP) * 3 * DM, 3 * DM, qselr, 2048, HWSP);

    const float* vx = qkv + 2 * DM;
    const float* vc = qkv + (size_t)LXX * 3 * DM + 2 * DM;

    attn_kernel<<<dim3(LXX / 64, NH), 256, ATTN_SMEM>>>(qxr, DM, kcr, DM, vc, 3 * DM,
                                                        attn, DM, LCC, 0, 0);
    attn_kernel<<<dim3(LXX / 64, NH), 256, ATTN_SMEM>>>(qxr, DM, kxr, DM, vx, 3 * DM,
                                                        attn, DM, LXX, 1, 1);
    attn_kernel<<<dim3(2048 / 64, NH), 256, ATTN_SMEM>>>(qselr, DM, kcr, DM, vc, 3 * DM,
                                                         attn + (size_t)2048 * DM, DM, LCC, 0, 0);

    // out projection + bias + residual
    act_split_kernel<<<(LOUT * DM / 2 + 255) / 256, 256>>>(attn, ahi, alo, LOUT * DM / 2);
    mma_gemm_kernel<<<dim3(DM / 128, LOUT / 128), 256, GEMM_SMEM>>>(
        ahi, alo, wohi, wolo, h1, out_b, x, ctx, 2048, LOUT, DM, DM);

    // LN2 + FFN
    ln_kernel<<<LOUT, 256>>>(h1, h1n, n2g, n2b);
    act_split_kernel<<<(LOUT * DM / 2 + 255) / 256, 256>>>(h1n, ahi, alo, LOUT * DM / 2);
    mma_gemm_kernel<<<dim3(HID / 128, LOUT / 128), 256, GEMM_SMEM>>>(
        ahi, alo, w1hi, w1lo, gate, nullptr, nullptr, nullptr, 0, LOUT, HID, DM);
    mma_gemm_kernel<<<dim3(HID / 128, LOUT / 128), 256, GEMM_SMEM>>>(
        ahi, alo, w3hi, w3lo, up, nullptr, nullptr, nullptr, 0, LOUT, HID, DM);
    silu_mul_kernel<<<(LOUT * HID + 255) / 256, 256>>>(gate, up, LOUT * HID);
    act_split_kernel<<<(LOUT * HID / 2 + 255) / 256, 256>>>(gate, ahi, alo, LOUT * HID / 2);
    mma_gemm_kernel<<<dim3(DM / 128, LOUT / 128), 256, GEMM_SMEM>>>(
        ahi, alo, w2hi, w2lo, out, nullptr, h1, h1, LOUT, LOUT, DM, HID);
}

// round 5
// speedup vs baseline: 2.1952x; 1.7331x over previous
#include <cuda_runtime.h>
#include <cuda_bf16.h>
#include <math.h>
#include <stdint.h>

// ---------------- problem constants (from setup_inputs, deterministic) ----------
#define LXX     2048
#define LCC     4096
#define DM      1024
#define NH      16
#define HDIM    64
#define HID     2816
#define LTOT    6144
#define LOUT    4096
#define POS_X   4096
#define POS_C   0
#define HWSP    2048
#define MAXPOS  6144

// ---------------- scratch (device globals; no runtime allocation) ---------------
__device__ float g_hn   [LTOT * DM];
__device__ float g_qkv  [LTOT * 3 * DM];
__device__ float g_attn [LOUT * DM];
__device__ float g_h1   [LOUT * DM];
__device__ float g_h1n  [LOUT * DM];
__device__ float g_gate [LOUT * HID];
__device__ float g_up   [LOUT * HID];
__device__ float g_cos  [MAXPOS * 32];
__device__ float g_sin  [MAXPOS * 32];

// split-bf16 activation scratch (max rows*cols = LOUT*HID)
__device__ __nv_bfloat16 g_act_hi[LOUT * HID];
__device__ __nv_bfloat16 g_act_lo[LOUT * HID];
// split-bf16 transposed weights [N][K]
__device__ __nv_bfloat16 g_wqkv_hi[3 * DM * DM], g_wqkv_lo[3 * DM * DM];
__device__ __nv_bfloat16 g_wout_hi[DM * DM],     g_wout_lo[DM * DM];
__device__ __nv_bfloat16 g_w1_hi [HID * DM],     g_w1_lo [HID * DM];
__device__ __nv_bfloat16 g_w3_hi [HID * DM],     g_w3_lo [HID * DM];
__device__ __nv_bfloat16 g_w2_hi [DM * HID],     g_w2_lo [DM * HID];

// split-bf16 attention operands
__device__ __nv_bfloat16 g_qx_hi[LXX * DM],  g_qx_lo[LXX * DM];
__device__ __nv_bfloat16 g_kx_hi[LXX * DM],  g_kx_lo[LXX * DM];
__device__ __nv_bfloat16 g_kc_hi[LCC * DM],  g_kc_lo[LCC * DM];
__device__ __nv_bfloat16 g_qs_hi[2048 * DM], g_qs_lo[2048 * DM];
__device__ __nv_bfloat16 g_v_hi [LTOT * DM], g_v_lo [LTOT * DM];

// ---------------- mma.sync helpers (portable: sm_80+ PTX) ------------------------
__device__ __forceinline__ uint32_t smem_to_u32(const void* p) {
    uint32_t a;
    asm("{ .reg .u64 t; cvta.to.shared.u64 t, %1; cvt.u32.u64 %0, t; }" : "=r"(a) : "l"(p));
    return a;
}
#define SMEM_SWIZZLE_128B(b) ((b) ^ (((b) >> 3) & 0x70))

__device__ __forceinline__ void ldsm_x4(uint32_t* r, uint32_t addr) {
    asm volatile("ldmatrix.sync.aligned.m8n8.x4.shared.b16 {%0,%1,%2,%3}, [%4];"
        : "=r"(r[0]), "=r"(r[1]), "=r"(r[2]), "=r"(r[3]) : "r"(addr));
}
__device__ __forceinline__ void ldsm_x4_t(uint32_t* r, uint32_t addr) {
    asm volatile("ldmatrix.sync.aligned.m8n8.x4.trans.shared.b16 {%0,%1,%2,%3}, [%4];"
        : "=r"(r[0]), "=r"(r[1]), "=r"(r[2]), "=r"(r[3]) : "r"(addr));
}
__device__ __forceinline__ void mma_bf16(float* c, const uint32_t* a, const uint32_t* b) {
    asm volatile("mma.sync.aligned.m16n8k16.row.col.f32.bf16.bf16.f32 "
        "{%0,%1,%2,%3}, {%4,%5,%6,%7}, {%8,%9}, {%0,%1,%2,%3};"
        : "+f"(c[0]), "+f"(c[1]), "+f"(c[2]), "+f"(c[3])
        : "r"(a[0]), "r"(a[1]), "r"(a[2]), "r"(a[3]), "r"(b[0]), "r"(b[1]));
}

// fast exp on FMA pipe (x <= 0), rel err ~2e-6
__device__ __forceinline__ float fexp(float x) {
    x = fmaxf(x, -87.0f);
    float t = x * 1.4426950408889634f;
    float r = t + 12582912.0f;
    float n = r - 12582912.0f;
    float f = t - n;
    float p = 0.0013298820f;
    p = fmaf(p, f, 0.0096181291f);
    p = fmaf(p, f, 0.0555041087f);
    p = fmaf(p, f, 0.2402265069f);
    p = fmaf(p, f, 0.6931471806f);
    p = fmaf(p, f, 1.0f);
    int ni = (int)n;
    return p * __int_as_float((ni + 127) << 23);
}

__device__ __forceinline__ void split2(float x, float y, uint32_t& h, uint32_t& l) {
    __nv_bfloat16 hx = __float2bfloat16(x), hy = __float2bfloat16(y);
    __nv_bfloat16 lx = __float2bfloat16(x - __bfloat162float(hx));
    __nv_bfloat16 ly = __float2bfloat16(y - __bfloat162float(hy));
    __nv_bfloat162 hh(hx, hy), ll(lx, ly);
    h = *(uint32_t*)&hh;
    l = *(uint32_t*)&ll;
}

// ---------------- rope cos/sin table (fp64 angles) -------------------------------
__global__ void build_rope_table() {
    int idx = blockIdx.x * blockDim.x + threadIdx.x;
    if (idx >= MAXPOS * 32) return;
    int pos = idx >> 5, j = idx & 31;
    double inv = pow(10000.0, -((double)(2 * j)) / 64.0);
    double ang = (double)pos * inv;
    g_cos[idx] = (float)cos(ang);
    g_sin[idx] = (float)sin(ang);
}

// ---------------- LayerNorm over 1024 cols ---------------------------------------
__global__ void ln_kernel(const float* __restrict__ in, float* __restrict__ out,
                          const float* __restrict__ gam, const float* __restrict__ bet) {
    __shared__ float sh[32];
    __shared__ float s_mean, s_rstd;
    int row = blockIdx.x, t = threadIdx.x;
    const float* x = in + (size_t)row * DM;
    float v[4];
    float s = 0.f;
#pragma unroll
    for (int i = 0; i < 4; i++) { v[i] = x[t + 256 * i]; s += v[i]; }
#pragma unroll
    for (int o = 16; o; o >>= 1) s += __shfl_xor_sync(0xffffffffu, s, o);
    if ((t & 31) == 0) sh[t >> 5] = s;
    __syncthreads();
    if (t < 32) {
        float z = (t < 8) ? sh[t] : 0.f;
#pragma unroll
        for (int o = 4; o; o >>= 1) z += __shfl_xor_sync(0xffffffffu, z, o);
        if (t == 0) s_mean = z * (1.f / 1024.f);
    }
    __syncthreads();
    float mean = s_mean;
    float q = 0.f;
#pragma unroll
    for (int i = 0; i < 4; i++) { float d = v[i] - mean; q += d * d; }
#pragma unroll
    for (int o = 16; o; o >>= 1) q += __shfl_xor_sync(0xffffffffu, q, o);
    if ((t & 31) == 0) sh[t >> 5] = q;
    __syncthreads();
    if (t < 32) {
        float z = (t < 8) ? sh[t] : 0.f;
#pragma unroll
        for (int o = 4; o; o >>= 1) z += __shfl_xor_sync(0xffffffffu, z, o);
        if (t == 0) s_rstd = rsqrtf(z * (1.f / 1024.f) + 1e-5f);
    }
    __syncthreads();
    float rstd = s_rstd;
#pragma unroll
    for (int i = 0; i < 4; i++) {
        int c = t + 256 * i;
        out[(size_t)row * DM + c] = (v[i] - mean) * rstd * gam[c] + bet[c];
    }
}

// ---------------- RoPE fused with split-bf16 --------------------------------------
__global__ void rope_split_kernel(const float* __restrict__ src, int lds,
                                  __nv_bfloat16* __restrict__ hi,
                                  __nv_bfloat16* __restrict__ lo,
                                  int L, int pos0, float scale) {
    int idx = blockIdx.x * blockDim.x + threadIdx.x;
    if (idx >= L * 512) return;
    int j = idx & 31, h = (idx >> 5) & 15, l = idx >> 9;
    int pos = pos0 + l;
    float c = g_cos[pos * 32 + j], s = g_sin[pos * 32 + j];
    const float* p = src + (size_t)l * lds + h * HDIM;
    float t1 = p[j], t2 = p[j + 32];
    float r1 = (t1 * c - t2 * s) * scale;
    float r2 = (t2 * c + t1 * s) * scale;
    size_t o = (size_t)l * DM + h * HDIM;
    __nv_bfloat16 h1 = __float2bfloat16(r1);
    __nv_bfloat16 h2 = __float2bfloat16(r2);
    hi[o + j]      = h1;
    hi[o + j + 32] = h2;
    lo[o + j]      = __float2bfloat16(r1 - __bfloat162float(h1));
    lo[o + j + 32] = __float2bfloat16(r2 - __bfloat162float(h2));
}

// ---------------- V split: strided fp32 -> contiguous split bf16 ------------------
__global__ void v_split_kernel(const float* __restrict__ qkv,
                               __nv_bfloat16* __restrict__ hi,
                               __nv_bfloat16* __restrict__ lo) {
    int i = blockIdx.x * blockDim.x + threadIdx.x;   // < LTOT*512
    if (i >= LTOT * 512) return;
    int r = i >> 9, c2 = i & 511;
    float2 v = *(const float2*)(qkv + (size_t)r * 3 * DM + 2 * DM + c2 * 2);
    __nv_bfloat16 hx = __float2bfloat16(v.x), hy = __float2bfloat16(v.y);
    __nv_bfloat162 h(hx, hy);
    __nv_bfloat162 l(__float2bfloat16(v.x - __bfloat162float(hx)),
                     __float2bfloat16(v.y - __bfloat162float(hy)));
    ((__nv_bfloat162*)hi)[(size_t)r * 512 + c2] = h;
    ((__nv_bfloat162*)lo)[(size_t)r * 512 + c2] = l;
}

// ---------------- fp32 -> split bf16 (elementwise) --------------------------------
__global__ void act_split_kernel(const float* __restrict__ in,
                                 __nv_bfloat16* __restrict__ hi,
                                 __nv_bfloat16* __restrict__ lo, int n2) {
    int i = blockIdx.x * blockDim.x + threadIdx.x;
    if (i >= n2) return;
    float2 v = ((const float2*)in)[i];
    __nv_bfloat16 hx = __float2bfloat16(v.x);
    __nv_bfloat16 hy = __float2bfloat16(v.y);
    __nv_bfloat162 h, l;
    h.x = hx; h.y = hy;
    l.x = __float2bfloat16(v.x - __bfloat162float(hx));
    l.y = __float2bfloat16(v.y - __bfloat162float(hy));
    ((__nv_bfloat162*)hi)[i] = h;
    ((__nv_bfloat162*)lo)[i] = l;
}

// ---------------- weight transpose + split: [K][N] fp32 -> [N][K] bf16 hi/lo ------
__global__ void wt_split_kernel(const float* __restrict__ w,
                                __nv_bfloat16* __restrict__ hi,
                                __nv_bfloat16* __restrict__ lo, int K, int N) {
    __shared__ float t[32][33];
    int n0 = blockIdx.x * 32, k0 = blockIdx.y * 32;
    int tx = threadIdx.x, ty = threadIdx.y;
#pragma unroll
    for (int i = 0; i < 32; i += 8)
        t[ty + i][tx] = w[(size_t)(k0 + ty + i) * N + n0 + tx];
    __syncthreads();
#pragma unroll
    for (int i = 0; i < 32; i += 8) {
        int n = n0 + ty + i, k = k0 + tx;
        float v = t[tx][ty + i];
        __nv_bfloat16 h = __float2bfloat16(v);
        hi[(size_t)n * K + k] = h;
        lo[(size_t)n * K + k] = __float2bfloat16(v - __bfloat162float(h));
    }
}

// ---------------- mma.sync split-bf16 GEMM ----------------------------------------
static const int GEMM_SMEM = 4 * 16384;

__global__ void __launch_bounds__(256)
mma_gemm_kernel(const __nv_bfloat16* __restrict__ Ahi, const __nv_bfloat16* __restrict__ Alo,
                const __nv_bfloat16* __restrict__ Bhi, const __nv_bfloat16* __restrict__ Blo,
                float* __restrict__ C, const float* __restrict__ bias,
                const float* __restrict__ res0, const float* __restrict__ res1, int split,
                int M, int N, int K) {
    extern __shared__ char smem[];
    char* pA_hi = smem;
    char* pA_lo = pA_hi + 16384;
    char* pB_hi = pA_lo + 16384;
    char* pB_lo = pB_hi + 16384;
    uint32_t sA_hi = smem_to_u32(pA_hi);
    uint32_t sA_lo = sA_hi + 16384;
    uint32_t sB_hi = sA_lo + 16384;
    uint32_t sB_lo = sB_hi + 16384;

    int tid = threadIdx.x;
    int wid = tid >> 5, lane = tid & 31;
    int wr = wid >> 2, wc = wid & 3;
    int m0 = blockIdx.y * 128, n0 = blockIdx.x * 128;

    int lr  = lane & 7;
    int lq  = lane >> 3;
    int qlo = lq & 1, qhi = lq >> 1;

    uint32_t aoff[4];
#pragma unroll
    for (int mt = 0; mt < 4; mt++) {
        int row = wr * 64 + mt * 16 + qlo * 8 + lr;
        aoff[mt] = (uint32_t)(row * 128) + (uint32_t)((qhi * 16) ^ ((row & 7) * 16));
    }
    uint32_t boff[2];
#pragma unroll
    for (int np = 0; np < 2; np++) {
        int row = wc * 32 + np * 16 + qhi * 8 + lr;
        boff[np] = (uint32_t)(row * 128) + (uint32_t)((qlo * 16) ^ ((row & 7) * 16));
    }

    float acc[4][4][4] = {};

    int nchunks = K >> 6;
    for (int kc = 0; kc < nchunks; kc++) {
        int kc0 = kc << 6;
#pragma unroll
        for (int it = 0; it < 4; it++) {
            int idx = tid + it * 256;
            int r = idx >> 3;
            int q = idx & 7;
            uint32_t so = SMEM_SWIZZLE_128B((uint32_t)(r * 128 + q * 16));
            *(uint4*)(pA_hi + so) = *(const uint4*)(Ahi + (size_t)(m0 + r) * K + kc0 + q * 8);
            *(uint4*)(pA_lo + so) = *(const uint4*)(Alo + (size_t)(m0 + r) * K + kc0 + q * 8);
            *(uint4*)(pB_hi + so) = *(const uint4*)(Bhi + (size_t)(n0 + r) * K + kc0 + q * 8);
            *(uint4*)(pB_lo + so) = *(const uint4*)(Blo + (size_t)(n0 + r) * K + kc0 + q * 8);
        }
        __syncthreads();

#pragma unroll
        for (int ks = 0; ks < 4; ks++) {
            uint32_t kx = (uint32_t)(ks << 5);
            uint32_t bh[2][4], bl[2][4];
#pragma unroll
            for (int np = 0; np < 2; np++) {
                ldsm_x4(bh[np], sB_hi + (boff[np] ^ kx));
                ldsm_x4(bl[np], sB_lo + (boff[np] ^ kx));
            }
#pragma unroll
            for (int mt = 0; mt < 4; mt++) {
                uint32_t ah[4];
                ldsm_x4(ah, sA_hi + (aoff[mt] ^ kx));
#pragma unroll
                for (int nt = 0; nt < 4; nt++) {
                    mma_bf16(acc[mt][nt], ah, &bh[nt >> 1][(nt & 1) * 2]);
                    mma_bf16(acc[mt][nt], ah, &bl[nt >> 1][(nt & 1) * 2]);
                }
                uint32_t al[4];
                ldsm_x4(al, sA_lo + (aoff[mt] ^ kx));
#pragma unroll
                for (int nt = 0; nt < 4; nt++)
                    mma_bf16(acc[mt][nt], al, &bh[nt >> 1][(nt & 1) * 2]);
            }
        }
        __syncthreads();
    }

    int g = lane >> 2, tg = lane & 3;
#pragma unroll
    for (int mt = 0; mt < 4; mt++) {
#pragma unroll
        for (int half = 0; half < 2; half++) {
            int row = m0 + wr * 64 + mt * 16 + g + half * 8;
            const float* rp = nullptr;
            if (res0) rp = ((row < split) ? res0 : res1) + (size_t)row * N;
            float* cp = C + (size_t)row * N;
#pragma unroll
            for (int nt = 0; nt < 4; nt++) {
                int col = n0 + wc * 32 + nt * 8 + tg * 2;
                float2 v;
                v.x = acc[mt][nt][half * 2 + 0];
                v.y = acc[mt][nt][half * 2 + 1];
                if (bias) { v.x += bias[col]; v.y += bias[col + 1]; }
                if (rp)   { v.x += rp[col];   v.y += rp[col + 1]; }
                *(float2*)(cp + col) = v;
            }
        }
    }
}

// ---------------- mma.sync flash attention -----------------------------------------
// BQ=64, BK=64, HD=64. 128 threads = 4 warps, warp owns 16 q-rows.
// Q pre-scaled by 1/8 in split buffers. S and PV: split-bf16 3 passes each.
__global__ void __launch_bounds__(128)
attn_mma(const __nv_bfloat16* __restrict__ Qhi, const __nv_bfloat16* __restrict__ Qlo,
         const __nv_bfloat16* __restrict__ Khi, const __nv_bfloat16* __restrict__ Klo,
         const __nv_bfloat16* __restrict__ Vhi, const __nv_bfloat16* __restrict__ Vlo,
         float* __restrict__ O, int LK, int causal, int accumulate) {
    __shared__ char sm[4 * 8192];
    char* pKhi = sm;
    char* pKlo = sm + 8192;
    char* pVhi = sm + 16384;
    char* pVlo = sm + 24576;
    uint32_t sKhi = smem_to_u32(pKhi);
    uint32_t sKlo = sKhi + 8192;
    uint32_t sVhi = sKlo + 8192;
    uint32_t sVlo = sVhi + 8192;

    int tid = threadIdx.x;
    int wid = tid >> 5, lane = tid & 31;
    int g = lane >> 2, tg = lane & 3;
    int lr = lane & 7, qlo = (lane >> 3) & 1, qhi = lane >> 4;
    int q0 = blockIdx.x * 64;
    int h  = blockIdx.y;

    // ---- stage Q into K buffers, extract fragments ----
#pragma unroll
    for (int it = 0; it < 4; it++) {
        int e = tid + it * 128;           // 0..511
        int row = e >> 3, q = e & 7;
        uint32_t off = (uint32_t)(row * 128) + (uint32_t)((q * 16) ^ ((row & 7) * 16));
        *(uint4*)(pKhi + off) = *(const uint4*)(Qhi + (size_t)(q0 + row) * DM + h * HDIM + q * 8);
        *(uint4*)(pKlo + off) = *(const uint4*)(Qlo + (size_t)(q0 + row) * DM + h * HDIM + q * 8);
    }
    __syncthreads();
    uint32_t qfh[4][4], qfl[4][4];
    {
        int arow = wid * 16 + qlo * 8 + lr;
        uint32_t abase = (uint32_t)(arow * 128) + (uint32_t)((qhi * 16) ^ ((arow & 7) * 16));
#pragma unroll
        for (int ks = 0; ks < 4; ks++) {
            ldsm_x4(qfh[ks], sKhi + (abase ^ (uint32_t)(ks << 5)));
            ldsm_x4(qfl[ks], sKlo + (abase ^ (uint32_t)(ks << 5)));
        }
    }
    __syncthreads();

    float o[8][4] = {};
    float m0r = -1e30f, m1r = -1e30f, l0r = 0.f, l1r = 0.f;

    int ntiles = causal ? ((int)blockIdx.x + 1) : (LK >> 6);
    for (int kt = 0; kt < ntiles; kt++) {
        int k0 = kt << 6;
        // ---- load K,V hi/lo tiles ----
#pragma unroll
        for (int it = 0; it < 4; it++) {
            int e = tid + it * 128;
            int row = e >> 3, q = e & 7;
            uint32_t off = (uint32_t)(row * 128) + (uint32_t)((q * 16) ^ ((row & 7) * 16));
            size_t gidx = (size_t)(k0 + row) * DM + h * HDIM + q * 8;
            *(uint4*)(pKhi + off) = *(const uint4*)(Khi + gidx);
            *(uint4*)(pKlo + off) = *(const uint4*)(Klo + gidx);
            *(uint4*)(pVhi + off) = *(const uint4*)(Vhi + gidx);
            *(uint4*)(pVlo + off) = *(const uint4*)(Vlo + gidx);
        }
        __syncthreads();

        // ---- S = Q K^T (3 split passes) ----
        // B-fragment mat order: octet bit0 -> k-half (qlo*16 col), bit1 -> key-row half (qhi*8)
        float s[8][4] = {};
#pragma unroll
        for (int ks = 0; ks < 4; ks++) {
            uint32_t kx = (uint32_t)(ks << 5);
            uint32_t bf[4][4];
#pragma unroll
            for (int np = 0; np < 4; np++) {
                int br = np * 16 + qhi * 8 + lr;
                uint32_t boff = (uint32_t)(br * 128) +
                                (uint32_t)(((qlo * 16) ^ (int)kx) ^ ((br & 7) * 16));
                ldsm_x4(bf[np], sKhi + boff);
            }
#pragma unroll
            for (int nt = 0; nt < 8; nt++) {
                mma_bf16(s[nt], qfh[ks], &bf[nt >> 1][(nt & 1) * 2]);
                mma_bf16(s[nt], qfl[ks], &bf[nt >> 1][(nt & 1) * 2]);
            }
#pragma unroll
            for (int np = 0; np < 4; np++) {
                int br = np * 16 + qhi * 8 + lr;
                uint32_t boff = (uint32_t)(br * 128) +
                                (uint32_t)(((qlo * 16) ^ (int)kx) ^ ((br & 7) * 16));
                ldsm_x4(bf[np], sKlo + boff);
            }
#pragma unroll
            for (int nt = 0; nt < 8; nt++)
                mma_bf16(s[nt], qfh[ks], &bf[nt >> 1][(nt & 1) * 2]);
        }

        // ---- causal mask (diagonal tile only) ----
        if (causal && kt == (int)blockIdx.x) {
            int r0 = q0 + wid * 16 + g, r1 = r0 + 8;
#pragma unroll
            for (int nt = 0; nt < 8; nt++) {
                int kbase = k0 + nt * 8 + tg * 2;
                if (kbase > r0)     s[nt][0] = -1e30f;
                if (kbase + 1 > r0) s[nt][1] = -1e30f;
                if (kbase > r1)     s[nt][2] = -1e30f;
                if (kbase + 1 > r1) s[nt][3] = -1e30f;
            }
        }

        // ---- online softmax ----
        float mx0 = -1e30f, mx1 = -1e30f;
#pragma unroll
        for (int nt = 0; nt < 8; nt++) {
            mx0 = fmaxf(mx0, fmaxf(s[nt][0], s[nt][1]));
            mx1 = fmaxf(mx1, fmaxf(s[nt][2], s[nt][3]));
        }
        mx0 = fmaxf(mx0, __shfl_xor_sync(0xffffffffu, mx0, 1));
        mx0 = fmaxf(mx0, __shfl_xor_sync(0xffffffffu, mx0, 2));
        mx1 = fmaxf(mx1, __shfl_xor_sync(0xffffffffu, mx1, 1));
        mx1 = fmaxf(mx1, __shfl_xor_sync(0xffffffffu, mx1, 2));
        float mn0 = fmaxf(m0r, mx0), mn1 = fmaxf(m1r, mx1);
        float al0 = fexp(m0r - mn0), al1 = fexp(m1r - mn1);
        float sum0 = 0.f, sum1 = 0.f;
#pragma unroll
        for (int nt = 0; nt < 8; nt++) {
            s[nt][0] = fexp(s[nt][0] - mn0);
            s[nt][1] = fexp(s[nt][1] - mn0);
            s[nt][2] = fexp(s[nt][2] - mn1);
            s[nt][3] = fexp(s[nt][3] - mn1);
            sum0 += s[nt][0] + s[nt][1];
            sum1 += s[nt][2] + s[nt][3];
        }
        sum0 += __shfl_xor_sync(0xffffffffu, sum0, 1);
        sum0 += __shfl_xor_sync(0xffffffffu, sum0, 2);
        sum1 += __shfl_xor_sync(0xffffffffu, sum1, 1);
        sum1 += __shfl_xor_sync(0xffffffffu, sum1, 2);
        l0r = l0r * al0 + sum0; m0r = mn0;
        l1r = l1r * al1 + sum1; m1r = mn1;
#pragma unroll
        for (int nt = 0; nt < 8; nt++) {
            o[nt][0] *= al0; o[nt][1] *= al0;
            o[nt][2] *= al1; o[nt][3] *= al1;
        }

        // ---- O += P V (3 split passes), V via ldmatrix.trans ----
#pragma unroll
        for (int kb = 0; kb < 4; kb++) {
            uint32_t ph[4], pl[4];
            split2(s[2 * kb][0],     s[2 * kb][1],     ph[0], pl[0]);
            split2(s[2 * kb][2],     s[2 * kb][3],     ph[1], pl[1]);
            split2(s[2 * kb + 1][0], s[2 * kb + 1][1], ph[2], pl[2]);
            split2(s[2 * kb + 1][2], s[2 * kb + 1][3], ph[3], pl[3]);
            uint32_t vf[4][4];
            int vr = kb * 16 + qlo * 8 + lr;
            uint32_t vrow = (uint32_t)(vr * 128);
            uint32_t vsw  = (uint32_t)((vr & 7) * 16);
#pragma unroll
            for (int np = 0; np < 4; np++)
                ldsm_x4_t(vf[np], sVhi + vrow + (((uint32_t)(np * 32 + qhi * 16)) ^ vsw));
#pragma unroll
            for (int nt = 0; nt < 8; nt++) {
                mma_bf16(o[nt], ph, &vf[nt >> 1][(nt & 1) * 2]);
                mma_bf16(o[nt], pl, &vf[nt >> 1][(nt & 1) * 2]);
            }
#pragma unroll
            for (int np = 0; np < 4; np++)
                ldsm_x4_t(vf[np], sVlo + vrow + (((uint32_t)(np * 32 + qhi * 16)) ^ vsw));
#pragma unroll
            for (int nt = 0; nt < 8; nt++)
                mma_bf16(o[nt], ph, &vf[nt >> 1][(nt & 1) * 2]);
        }
        __syncthreads();
    }

    // ---- epilogue ----
    float inv0 = 1.f / l0r, inv1 = 1.f / l1r;
    int row0 = q0 + wid * 16 + g;
    int row1 = row0 + 8;
#pragma unroll
    for (int nt = 0; nt < 8; nt++) {
        int col = h * HDIM + nt * 8 + tg * 2;
        float* p0 = O + (size_t)row0 * DM + col;
        float* p1 = O + (size_t)row1 * DM + col;
        float2 v0 = make_float2(o[nt][0] * inv0, o[nt][1] * inv0);
        float2 v1 = make_float2(o[nt][2] * inv1, o[nt][3] * inv1);
        if (accumulate) {
            float2 a0 = *(float2*)p0, a1 = *(float2*)p1;
            v0.x += a0.x; v0.y += a0.y;
            v1.x += a1.x; v1.y += a1.y;
        }
        *(float2*)p0 = v0;
        *(float2*)p1 = v1;
    }
}

// ---------------- silu(g)*u in place into g ---------------------------------------
__global__ void silu_mul_kernel(float* __restrict__ g, const float* __restrict__ u, int n) {
    int i = blockIdx.x * blockDim.x + threadIdx.x;
    if (i < n) {
        float x = g[i];
        g[i] = (x / (1.f + __expf(-x))) * u[i];
    }
}

// ---------------- host orchestration ----------------------------------------------
extern "C" void kernel_launch(void* const* d_in, const int* in_sizes, int n_in,
                              void* d_out, int out_size) {
    const float* x     = (const float*)d_in[0];
    const float* ctx   = (const float*)d_in[1];
    const float* qkv_w = (const float*)d_in[2];
    const float* qkv_b = (const float*)d_in[3];
    const float* out_w = (const float*)d_in[4];
    const float* out_b = (const float*)d_in[5];
    const float* w1    = (const float*)d_in[6];
    const float* w3    = (const float*)d_in[7];
    const float* w2    = (const float*)d_in[8];
    const float* n1g   = (const float*)d_in[9];
    const float* n1b   = (const float*)d_in[10];
    const float* n2g   = (const float*)d_in[11];
    const float* n2b   = (const float*)d_in[12];
    float* out = (float*)d_out;

    cudaFuncSetAttribute(mma_gemm_kernel, cudaFuncAttributeMaxDynamicSharedMemorySize, GEMM_SMEM);

    void* p;
    cudaGetSymbolAddress(&p, g_hn);    float* hn    = (float*)p;
    cudaGetSymbolAddress(&p, g_qkv);   float* qkv   = (float*)p;
    cudaGetSymbolAddress(&p, g_attn);  float* attn  = (float*)p;
    cudaGetSymbolAddress(&p, g_h1);    float* h1    = (float*)p;
    cudaGetSymbolAddress(&p, g_h1n);   float* h1n   = (float*)p;
    cudaGetSymbolAddress(&p, g_gate);  float* gate  = (float*)p;
    cudaGetSymbolAddress(&p, g_up);    float* up    = (float*)p;
    cudaGetSymbolAddress(&p, g_act_hi); __nv_bfloat16* ahi = (__nv_bfloat16*)p;
    cudaGetSymbolAddress(&p, g_act_lo); __nv_bfloat16* alo = (__nv_bfloat16*)p;
    cudaGetSymbolAddress(&p, g_wqkv_hi); __nv_bfloat16* wqhi = (__nv_bfloat16*)p;
    cudaGetSymbolAddress(&p, g_wqkv_lo); __nv_bfloat16* wqlo = (__nv_bfloat16*)p;
    cudaGetSymbolAddress(&p, g_wout_hi); __nv_bfloat16* wohi = (__nv_bfloat16*)p;
    cudaGetSymbolAddress(&p, g_wout_lo); __nv_bfloat16* wolo = (__nv_bfloat16*)p;
    cudaGetSymbolAddress(&p, g_w1_hi);  __nv_bfloat16* w1hi = (__nv_bfloat16*)p;
    cudaGetSymbolAddress(&p, g_w1_lo);  __nv_bfloat16* w1lo = (__nv_bfloat16*)p;
    cudaGetSymbolAddress(&p, g_w3_hi);  __nv_bfloat16* w3hi = (__nv_bfloat16*)p;
    cudaGetSymbolAddress(&p, g_w3_lo);  __nv_bfloat16* w3lo = (__nv_bfloat16*)p;
    cudaGetSymbolAddress(&p, g_w2_hi);  __nv_bfloat16* w2hi = (__nv_bfloat16*)p;
    cudaGetSymbolAddress(&p, g_w2_lo);  __nv_bfloat16* w2lo = (__nv_bfloat16*)p;
    cudaGetSymbolAddress(&p, g_qx_hi);  __nv_bfloat16* qxhi = (__nv_bfloat16*)p;
    cudaGetSymbolAddress(&p, g_qx_lo);  __nv_bfloat16* qxlo = (__nv_bfloat16*)p;
    cudaGetSymbolAddress(&p, g_kx_hi);  __nv_bfloat16* kxhi = (__nv_bfloat16*)p;
    cudaGetSymbolAddress(&p, g_kx_lo);  __nv_bfloat16* kxlo = (__nv_bfloat16*)p;
    cudaGetSymbolAddress(&p, g_kc_hi);  __nv_bfloat16* kchi = (__nv_bfloat16*)p;
    cudaGetSymbolAddress(&p, g_kc_lo);  __nv_bfloat16* kclo = (__nv_bfloat16*)p;
    cudaGetSymbolAddress(&p, g_qs_hi);  __nv_bfloat16* qshi = (__nv_bfloat16*)p;
    cudaGetSymbolAddress(&p, g_qs_lo);  __nv_bfloat16* qslo = (__nv_bfloat16*)p;
    cudaGetSymbolAddress(&p, g_v_hi);   __nv_bfloat16* vhi  = (__nv_bfloat16*)p;
    cudaGetSymbolAddress(&p, g_v_lo);   __nv_bfloat16* vlo  = (__nv_bfloat16*)p;

    dim3 tb(32, 8);
    build_rope_table<<<(MAXPOS * 32 + 255) / 256, 256>>>();

    // weight transpose+split
    wt_split_kernel<<<dim3(3 * DM / 32, DM / 32), tb>>>(qkv_w, wqhi, wqlo, DM, 3 * DM);
    wt_split_kernel<<<dim3(DM / 32, DM / 32),     tb>>>(out_w, wohi, wolo, DM, DM);
    wt_split_kernel<<<dim3(HID / 32, DM / 32),    tb>>>(w1, w1hi, w1lo, DM, HID);
    wt_split_kernel<<<dim3(HID / 32, DM / 32),    tb>>>(w3, w3hi, w3lo, DM, HID);
    wt_split_kernel<<<dim3(DM / 32, HID / 32),    tb>>>(w2, w2hi, w2lo, HID, DM);

    // LN1
    ln_kernel<<<LXX, 256>>>(x,   hn,                    n1g, n1b);
    ln_kernel<<<LCC, 256>>>(ctx, hn + (size_t)LXX * DM, n1g, n1b);

    // QKV projection
    act_split_kernel<<<(LTOT * DM / 2 + 255) / 256, 256>>>(hn, ahi, alo, LTOT * DM / 2);
    mma_gemm_kernel<<<dim3(3 * DM / 128, LTOT / 128), 256, GEMM_SMEM>>>(
        ahi, alo, wqhi, wqlo, qkv, qkv_b, nullptr, nullptr, 0, LTOT, 3 * DM, DM);

    // RoPE + split (q-side pre-scaled by 1/8)
    rope_split_kernel<<<(LXX * 512 + 255) / 256, 256>>>(qkv, 3 * DM, qxhi, qxlo, LXX, POS_X, 0.125f);
    rope_split_kernel<<<(LXX * 512 + 255) / 256, 256>>>(qkv + DM, 3 * DM, kxhi, kxlo, LXX, POS_X, 1.f);
    rope_split_kernel<<<(LCC * 512 + 255) / 256, 256>>>(qkv + (size_t)LXX * 3 * DM + DM, 3 * DM, kchi, kclo, LCC, POS_C, 1.f);
    rope_split_kernel<<<(2048 * 512 + 255) / 256, 256>>>(qkv + (size_t)(LXX + HWSP) * 3 * DM, 3 * DM, qshi, qslo, 2048, HWSP, 0.125f);
    v_split_kernel<<<(LTOT * 512 + 255) / 256, 256>>>(qkv, vhi, vlo);

    const size_t vcoff = (size_t)LXX * DM;

    // a1: qx vs kc/vc (non-causal)
    attn_mma<<<dim3(LXX / 64, NH), 128>>>(qxhi, qxlo, kchi, kclo,
                                          vhi + vcoff, vlo + vcoff, attn, LCC, 0, 0);
    // a2: qx vs kx/vx (causal, accumulate)
    attn_mma<<<dim3(LXX / 64, NH), 128>>>(qxhi, qxlo, kxhi, kxlo,
                                          vhi, vlo, attn, LXX, 1, 1);
    // a3: q_sel vs kc/vc (non-causal)
    attn_mma<<<dim3(2048 / 64, NH), 128>>>(qshi, qslo, kchi, kclo,
                                           vhi + vcoff, vlo + vcoff,
                                           attn + (size_t)2048 * DM, LCC, 0, 0);

    // out projection + bias + residual
    act_split_kernel<<<(LOUT * DM / 2 + 255) / 256, 256>>>(attn, ahi, alo, LOUT * DM / 2);
    mma_gemm_kernel<<<dim3(DM / 128, LOUT / 128), 256, GEMM_SMEM>>>(
        ahi, alo, wohi, wolo, h1, out_b, x, ctx, 2048, LOUT, DM, DM);

    // LN2 + FFN
    ln_kernel<<<LOUT, 256>>>(h1, h1n, n2g, n2b);
    act_split_kernel<<<(LOUT * DM / 2 + 255) / 256, 256>>>(h1n, ahi, alo, LOUT * DM / 2);
    mma_gemm_kernel<<<dim3(HID / 128, LOUT / 128), 256, GEMM_SMEM>>>(
        ahi, alo, w1hi, w1lo, gate, nullptr, nullptr, nullptr, 0, LOUT, HID, DM);
    mma_gemm_kernel<<<dim3(HID / 128, LOUT / 128), 256, GEMM_SMEM>>>(
        ahi, alo, w3hi, w3lo, up, nullptr, nullptr, nullptr, 0, LOUT, HID, DM);
    silu_mul_kernel<<<(LOUT * HID + 255) / 256, 256>>>(gate, up, LOUT * HID);
    act_split_kernel<<<(LOUT * HID / 2 + 255) / 256, 256>>>(gate, ahi, alo, LOUT * HID / 2);
    mma_gemm_kernel<<<dim3(DM / 128, LOUT / 128), 256, GEMM_SMEM>>>(
        ahi, alo, w2hi, w2lo, out, nullptr, h1, h1, LOUT, LOUT, DM, HID);
}

// round 6
// speedup vs baseline: 2.8734x; 1.3089x over previous
#include <cuda_runtime.h>
#include <cuda_bf16.h>
#include <math.h>
#include <stdint.h>

// ---------------- problem constants (from setup_inputs, deterministic) ----------
#define LXX     2048
#define LCC     4096
#define DM      1024
#define NH      16
#define HDIM    64
#define HID     2816
#define LTOT    6144
#define LOUT    4096
#define POS_X   4096
#define POS_C   0
#define HWSP    2048
#define MAXPOS  6144

// ---------------- scratch (device globals; no runtime allocation) ---------------
__device__ float g_qkv   [LTOT * 3 * DM];
__device__ float g_attn  [LXX * DM];          // a1 fp32 staging (rows 0..2047)
__device__ float g_h1    [LOUT * DM];
__device__ float g_gateup[LOUT * 2 * HID];
__device__ float g_cos   [MAXPOS * 32];
__device__ float g_sin   [MAXPOS * 32];

// split-bf16 activation scratch (max rows*cols = LOUT*HID)
__device__ __nv_bfloat16 g_act_hi[LOUT * HID];
__device__ __nv_bfloat16 g_act_lo[LOUT * HID];
// split-bf16 transposed weights [N][K]
__device__ __nv_bfloat16 g_wqkv_hi[3 * DM * DM], g_wqkv_lo[3 * DM * DM];
__device__ __nv_bfloat16 g_wout_hi[DM * DM],     g_wout_lo[DM * DM];
__device__ __nv_bfloat16 g_w13_hi[2 * HID * DM], g_w13_lo[2 * HID * DM];
__device__ __nv_bfloat16 g_w2_hi [DM * HID],     g_w2_lo [DM * HID];

// split-bf16 attention operands
__device__ __nv_bfloat16 g_qx_hi[LXX * DM],  g_qx_lo[LXX * DM];
__device__ __nv_bfloat16 g_kx_hi[LXX * DM],  g_kx_lo[LXX * DM];
__device__ __nv_bfloat16 g_kc_hi[LCC * DM],  g_kc_lo[LCC * DM];
__device__ __nv_bfloat16 g_qs_hi[2048 * DM], g_qs_lo[2048 * DM];
__device__ __nv_bfloat16 g_v_hi [LTOT * DM], g_v_lo [LTOT * DM];

// ---------------- helpers (portable: sm_80+ PTX) ----------------------------------
__device__ __forceinline__ uint32_t smem_to_u32(const void* p) {
    uint32_t a;
    asm("{ .reg .u64 t; cvta.to.shared.u64 t, %1; cvt.u32.u64 %0, t; }" : "=r"(a) : "l"(p));
    return a;
}
#define SMEM_SWIZZLE_128B(b) ((b) ^ (((b) >> 3) & 0x70))

__device__ __forceinline__ void cp16(uint32_t s, const void* g) {
    asm volatile("cp.async.cg.shared.global [%0], [%1], 16;" :: "r"(s), "l"(g) : "memory");
}
__device__ __forceinline__ void cp_commit() {
    asm volatile("cp.async.commit_group;" ::: "memory");
}
template<int N> __device__ __forceinline__ void cp_wait() {
    asm volatile("cp.async.wait_group %0;" :: "n"(N) : "memory");
}

__device__ __forceinline__ void ldsm_x4(uint32_t* r, uint32_t addr) {
    asm volatile("ldmatrix.sync.aligned.m8n8.x4.shared.b16 {%0,%1,%2,%3}, [%4];"
        : "=r"(r[0]), "=r"(r[1]), "=r"(r[2]), "=r"(r[3]) : "r"(addr));
}
__device__ __forceinline__ void ldsm_x4_t(uint32_t* r, uint32_t addr) {
    asm volatile("ldmatrix.sync.aligned.m8n8.x4.trans.shared.b16 {%0,%1,%2,%3}, [%4];"
        : "=r"(r[0]), "=r"(r[1]), "=r"(r[2]), "=r"(r[3]) : "r"(addr));
}
__device__ __forceinline__ void mma_bf16(float* c, const uint32_t* a, const uint32_t* b) {
    asm volatile("mma.sync.aligned.m16n8k16.row.col.f32.bf16.bf16.f32 "
        "{%0,%1,%2,%3}, {%4,%5,%6,%7}, {%8,%9}, {%0,%1,%2,%3};"
        : "+f"(c[0]), "+f"(c[1]), "+f"(c[2]), "+f"(c[3])
        : "r"(a[0]), "r"(a[1]), "r"(a[2]), "r"(a[3]), "r"(b[0]), "r"(b[1]));
}

// fast exp on FMA pipe (x <= 0), rel err ~2e-6
__device__ __forceinline__ float fexp(float x) {
    x = fmaxf(x, -87.0f);
    float t = x * 1.4426950408889634f;
    float r = t + 12582912.0f;
    float n = r - 12582912.0f;
    float f = t - n;
    float p = 0.0013298820f;
    p = fmaf(p, f, 0.0096181291f);
    p = fmaf(p, f, 0.0555041087f);
    p = fmaf(p, f, 0.2402265069f);
    p = fmaf(p, f, 0.6931471806f);
    p = fmaf(p, f, 1.0f);
    int ni = (int)n;
    return p * __int_as_float((ni + 127) << 23);
}

__device__ __forceinline__ void split2(float x, float y, uint32_t& h, uint32_t& l) {
    __nv_bfloat16 hx = __float2bfloat16(x), hy = __float2bfloat16(y);
    __nv_bfloat16 lx = __float2bfloat16(x - __bfloat162float(hx));
    __nv_bfloat16 ly = __float2bfloat16(y - __bfloat162float(hy));
    __nv_bfloat162 hh(hx, hy), ll(lx, ly);
    h = *(uint32_t*)&hh;
    l = *(uint32_t*)&ll;
}

// ---------------- rope cos/sin table (fp64 angles) -------------------------------
__global__ void build_rope_table() {
    int idx = blockIdx.x * blockDim.x + threadIdx.x;
    if (idx >= MAXPOS * 32) return;
    int pos = idx >> 5, j = idx & 31;
    double inv = pow(10000.0, -((double)(2 * j)) / 64.0);
    double ang = (double)pos * inv;
    g_cos[idx] = (float)cos(ang);
    g_sin[idx] = (float)sin(ang);
}

// ---------------- LayerNorm fused with split-bf16 output --------------------------
__global__ void ln_split_kernel(const float* __restrict__ in,
                                __nv_bfloat16* __restrict__ hi,
                                __nv_bfloat16* __restrict__ lo,
                                const float* __restrict__ gam,
                                const float* __restrict__ bet) {
    __shared__ float sh[32];
    __shared__ float s_mean, s_rstd;
    int row = blockIdx.x, t = threadIdx.x;
    const float* x = in + (size_t)row * DM;
    float v[4];
    float s = 0.f;
#pragma unroll
    for (int i = 0; i < 4; i++) { v[i] = x[t + 256 * i]; s += v[i]; }
#pragma unroll
    for (int o = 16; o; o >>= 1) s += __shfl_xor_sync(0xffffffffu, s, o);
    if ((t & 31) == 0) sh[t >> 5] = s;
    __syncthreads();
    if (t < 32) {
        float z = (t < 8) ? sh[t] : 0.f;
#pragma unroll
        for (int o = 4; o; o >>= 1) z += __shfl_xor_sync(0xffffffffu, z, o);
        if (t == 0) s_mean = z * (1.f / 1024.f);
    }
    __syncthreads();
    float mean = s_mean;
    float q = 0.f;
#pragma unroll
    for (int i = 0; i < 4; i++) { float d = v[i] - mean; q += d * d; }
#pragma unroll
    for (int o = 16; o; o >>= 1) q += __shfl_xor_sync(0xffffffffu, q, o);
    if ((t & 31) == 0) sh[t >> 5] = q;
    __syncthreads();
    if (t < 32) {
        float z = (t < 8) ? sh[t] : 0.f;
#pragma unroll
        for (int o = 4; o; o >>= 1) z += __shfl_xor_sync(0xffffffffu, z, o);
        if (t == 0) s_rstd = rsqrtf(z * (1.f / 1024.f) + 1e-5f);
    }
    __syncthreads();
    float rstd = s_rstd;
#pragma unroll
    for (int i = 0; i < 4; i++) {
        int c = t + 256 * i;
        float r = (v[i] - mean) * rstd * gam[c] + bet[c];
        __nv_bfloat16 hb = __float2bfloat16(r);
        hi[(size_t)row * DM + c] = hb;
        lo[(size_t)row * DM + c] = __float2bfloat16(r - __bfloat162float(hb));
    }
}

// ---------------- RoPE fused with split-bf16 --------------------------------------
__global__ void rope_split_kernel(const float* __restrict__ src, int lds,
                                  __nv_bfloat16* __restrict__ hi,
                                  __nv_bfloat16* __restrict__ lo,
                                  int L, int pos0, float scale) {
    int idx = blockIdx.x * blockDim.x + threadIdx.x;
    if (idx >= L * 512) return;
    int j = idx & 31, h = (idx >> 5) & 15, l = idx >> 9;
    int pos = pos0 + l;
    float c = g_cos[pos * 32 + j], s = g_sin[pos * 32 + j];
    const float* p = src + (size_t)l * lds + h * HDIM;
    float t1 = p[j], t2 = p[j + 32];
    float r1 = (t1 * c - t2 * s) * scale;
    float r2 = (t2 * c + t1 * s) * scale;
    size_t o = (size_t)l * DM + h * HDIM;
    __nv_bfloat16 h1 = __float2bfloat16(r1);
    __nv_bfloat16 h2 = __float2bfloat16(r2);
    hi[o + j]      = h1;
    hi[o + j + 32] = h2;
    lo[o + j]      = __float2bfloat16(r1 - __bfloat162float(h1));
    lo[o + j + 32] = __float2bfloat16(r2 - __bfloat162float(h2));
}

// ---------------- V split: strided fp32 -> contiguous split bf16 ------------------
__global__ void v_split_kernel(const float* __restrict__ qkv,
                               __nv_bfloat16* __restrict__ hi,
                               __nv_bfloat16* __restrict__ lo) {
    int i = blockIdx.x * blockDim.x + threadIdx.x;
    if (i >= LTOT * 512) return;
    int r = i >> 9, c2 = i & 511;
    float2 v = *(const float2*)(qkv + (size_t)r * 3 * DM + 2 * DM + c2 * 2);
    __nv_bfloat16 hx = __float2bfloat16(v.x), hy = __float2bfloat16(v.y);
    __nv_bfloat162 h(hx, hy);
    __nv_bfloat162 l(__float2bfloat16(v.x - __bfloat162float(hx)),
                     __float2bfloat16(v.y - __bfloat162float(hy)));
    ((__nv_bfloat162*)hi)[(size_t)r * 512 + c2] = h;
    ((__nv_bfloat162*)lo)[(size_t)r * 512 + c2] = l;
}

// ---------------- weight transpose + split: [K][N] fp32 -> [N][K] bf16 hi/lo ------
__global__ void wt_split_kernel(const float* __restrict__ w,
                                __nv_bfloat16* __restrict__ hi,
                                __nv_bfloat16* __restrict__ lo, int K, int N) {
    __shared__ float t[32][33];
    int n0 = blockIdx.x * 32, k0 = blockIdx.y * 32;
    int tx = threadIdx.x, ty = threadIdx.y;
#pragma unroll
    for (int i = 0; i < 32; i += 8)
        t[ty + i][tx] = w[(size_t)(k0 + ty + i) * N + n0 + tx];
    __syncthreads();
#pragma unroll
    for (int i = 0; i < 32; i += 8) {
        int n = n0 + ty + i, k = k0 + tx;
        float v = t[tx][ty + i];
        __nv_bfloat16 h = __float2bfloat16(v);
        hi[(size_t)n * K + k] = h;
        lo[(size_t)n * K + k] = __float2bfloat16(v - __bfloat162float(h));
    }
}

// ---------------- silu(g)*u fused with split ---------------------------------------
__global__ void silu_mul_split_kernel(const float* __restrict__ gu,
                                      __nv_bfloat16* __restrict__ hi,
                                      __nv_bfloat16* __restrict__ lo) {
    int col = blockIdx.x * 256 + threadIdx.x;     // < HID
    int row = blockIdx.y;
    float g = gu[(size_t)row * (2 * HID) + col];
    float u = gu[(size_t)row * (2 * HID) + HID + col];
    float r = (g / (1.f + __expf(-g))) * u;
    __nv_bfloat16 hb = __float2bfloat16(r);
    hi[(size_t)row * HID + col] = hb;
    lo[(size_t)row * HID + col] = __float2bfloat16(r - __bfloat162float(hb));
}

// ---------------- mma.sync split-bf16 GEMM, cp.async 2-stage pipeline --------------
// C[M][N] = A[M][K] * Bt[N][K]^T; CTA 128x128, BK=64, 256 thr, warp 64x32.
static const int GEMM_SMEM = 2 * 4 * 16384;   // 131072

__global__ void __launch_bounds__(256)
mma_gemm_kernel(const __nv_bfloat16* __restrict__ Ahi, const __nv_bfloat16* __restrict__ Alo,
                const __nv_bfloat16* __restrict__ Bhi, const __nv_bfloat16* __restrict__ Blo,
                float* __restrict__ C, const float* __restrict__ bias,
                const float* __restrict__ res0, const float* __restrict__ res1, int split,
                int M, int N, int K) {
    extern __shared__ char smem[];
    uint32_t sbase = smem_to_u32(smem);

    int tid = threadIdx.x;
    int wid = tid >> 5, lane = tid & 31;
    int wr = wid >> 2, wc = wid & 3;
    int m0 = blockIdx.y * 128, n0 = blockIdx.x * 128;

    int lr  = lane & 7;
    int lq  = lane >> 3;
    int qlo = lq & 1, qhi = lq >> 1;

    uint32_t aoff[4];
#pragma unroll
    for (int mt = 0; mt < 4; mt++) {
        int row = wr * 64 + mt * 16 + qlo * 8 + lr;
        aoff[mt] = (uint32_t)(row * 128) + (uint32_t)((qhi * 16) ^ ((row & 7) * 16));
    }
    uint32_t boff[2];
#pragma unroll
    for (int np = 0; np < 2; np++) {
        int row = wc * 32 + np * 16 + qhi * 8 + lr;
        boff[np] = (uint32_t)(row * 128) + (uint32_t)((qlo * 16) ^ ((row & 7) * 16));
    }

    auto issue = [&](int st, int kc0) {
        uint32_t base = sbase + (uint32_t)st * 65536;
#pragma unroll
        for (int it = 0; it < 4; it++) {
            int idx = tid + it * 256;
            int r = idx >> 3, q = idx & 7;
            uint32_t so = SMEM_SWIZZLE_128B((uint32_t)(r * 128 + q * 16));
            cp16(base + so,         Ahi + (size_t)(m0 + r) * K + kc0 + q * 8);
            cp16(base + 16384 + so, Alo + (size_t)(m0 + r) * K + kc0 + q * 8);
            cp16(base + 32768 + so, Bhi + (size_t)(n0 + r) * K + kc0 + q * 8);
            cp16(base + 49152 + so, Blo + (size_t)(n0 + r) * K + kc0 + q * 8);
        }
        cp_commit();
    };

    float acc[4][4][4] = {};
    int nchunks = K >> 6;

    issue(0, 0);
    for (int kc = 0; kc < nchunks; kc++) {
        int st = kc & 1;
        if (kc + 1 < nchunks) { issue(st ^ 1, (kc + 1) << 6); cp_wait<1>(); }
        else                  { cp_wait<0>(); }
        __syncthreads();

        uint32_t sA_hi = sbase + (uint32_t)st * 65536;
        uint32_t sA_lo = sA_hi + 16384;
        uint32_t sB_hi = sA_lo + 16384;
        uint32_t sB_lo = sB_hi + 16384;

#pragma unroll
        for (int ks = 0; ks < 4; ks++) {
            uint32_t kx = (uint32_t)(ks << 5);
            uint32_t bh[2][4], bl[2][4];
#pragma unroll
            for (int np = 0; np < 2; np++) {
                ldsm_x4(bh[np], sB_hi + (boff[np] ^ kx));
                ldsm_x4(bl[np], sB_lo + (boff[np] ^ kx));
            }
#pragma unroll
            for (int mt = 0; mt < 4; mt++) {
                uint32_t ah[4], al[4];
                ldsm_x4(ah, sA_hi + (aoff[mt] ^ kx));
                ldsm_x4(al, sA_lo + (aoff[mt] ^ kx));
#pragma unroll
                for (int nt = 0; nt < 4; nt++)
                    mma_bf16(acc[mt][nt], ah, &bh[nt >> 1][(nt & 1) * 2]);
#pragma unroll
                for (int nt = 0; nt < 4; nt++)
                    mma_bf16(acc[mt][nt], ah, &bl[nt >> 1][(nt & 1) * 2]);
#pragma unroll
                for (int nt = 0; nt < 4; nt++)
                    mma_bf16(acc[mt][nt], al, &bh[nt >> 1][(nt & 1) * 2]);
            }
        }
        __syncthreads();
    }

    int g = lane >> 2, tg = lane & 3;
#pragma unroll
    for (int mt = 0; mt < 4; mt++) {
#pragma unroll
        for (int half = 0; half < 2; half++) {
            int row = m0 + wr * 64 + mt * 16 + g + half * 8;
            const float* rp = nullptr;
            if (res0) rp = ((row < split) ? res0 : res1) + (size_t)row * N;
            float* cp = C + (size_t)row * N;
#pragma unroll
            for (int nt = 0; nt < 4; nt++) {
                int col = n0 + wc * 32 + nt * 8 + tg * 2;
                float2 v;
                v.x = acc[mt][nt][half * 2 + 0];
                v.y = acc[mt][nt][half * 2 + 1];
                if (bias) { v.x += bias[col]; v.y += bias[col + 1]; }
                if (rp)   { v.x += rp[col];   v.y += rp[col + 1]; }
                *(float2*)(cp + col) = v;
            }
        }
    }
}

// ---------------- mma.sync flash attention, cp.async 2-stage ------------------------
// mode 0: write fp32 O; mode 1: read fp32 O, add, write split; mode 2: write split
static const int ATTN_SMEM = 2 * 4 * 8192;    // 65536

__global__ void __launch_bounds__(128)
attn_mma(const __nv_bfloat16* __restrict__ Qhi, const __nv_bfloat16* __restrict__ Qlo,
         const __nv_bfloat16* __restrict__ Khi, const __nv_bfloat16* __restrict__ Klo,
         const __nv_bfloat16* __restrict__ Vhi, const __nv_bfloat16* __restrict__ Vlo,
         float* __restrict__ O,
         __nv_bfloat16* __restrict__ Ohi, __nv_bfloat16* __restrict__ Olo,
         int LK, int causal, int mode) {
    extern __shared__ char smema[];
    uint32_t sb = smem_to_u32(smema);

    int tid = threadIdx.x;
    int wid = tid >> 5, lane = tid & 31;
    int g = lane >> 2, tg = lane & 3;
    int lr = lane & 7, qlo = (lane >> 3) & 1, qhi = lane >> 4;
    int q0 = blockIdx.x * 64;
    int h  = blockIdx.y;

    // ---- stage Q into stage-0 buffers, extract fragments ----
#pragma unroll
    for (int it = 0; it < 4; it++) {
        int e = tid + it * 128;
        int row = e >> 3, q = e & 7;
        uint32_t off = (uint32_t)(row * 128) + (uint32_t)((q * 16) ^ ((row & 7) * 16));
        *(uint4*)(smema + off)        = *(const uint4*)(Qhi + (size_t)(q0 + row) * DM + h * HDIM + q * 8);
        *(uint4*)(smema + 8192 + off) = *(const uint4*)(Qlo + (size_t)(q0 + row) * DM + h * HDIM + q * 8);
    }
    __syncthreads();
    uint32_t qfh[4][4], qfl[4][4];
    {
        int arow = wid * 16 + qlo * 8 + lr;
        uint32_t abase = (uint32_t)(arow * 128) + (uint32_t)((qhi * 16) ^ ((arow & 7) * 16));
#pragma unroll
        for (int ks = 0; ks < 4; ks++) {
            ldsm_x4(qfh[ks], sb + (abase ^ (uint32_t)(ks << 5)));
            ldsm_x4(qfl[ks], sb + 8192 + (abase ^ (uint32_t)(ks << 5)));
        }
    }
    __syncthreads();

    auto issue = [&](int st, int k0) {
        uint32_t base = sb + (uint32_t)st * 32768;
#pragma unroll
        for (int it = 0; it < 4; it++) {
            int e = tid + it * 128;
            int row = e >> 3, q = e & 7;
            uint32_t off = (uint32_t)(row * 128) + (uint32_t)((q * 16) ^ ((row & 7) * 16));
            size_t gidx = (size_t)(k0 + row) * DM + h * HDIM + q * 8;
            cp16(base + off,         Khi + gidx);
            cp16(base + 8192 + off,  Klo + gidx);
            cp16(base + 16384 + off, Vhi + gidx);
            cp16(base + 24576 + off, Vlo + gidx);
        }
        cp_commit();
    };

    float o[8][4] = {};
    float m0r = -1e30f, m1r = -1e30f, l0r = 0.f, l1r = 0.f;

    int ntiles = causal ? ((int)blockIdx.x + 1) : (LK >> 6);
    issue(0, 0);
    for (int kt = 0; kt < ntiles; kt++) {
        int k0 = kt << 6;
        int st = kt & 1;
        if (kt + 1 < ntiles) { issue(st ^ 1, (kt + 1) << 6); cp_wait<1>(); }
        else                 { cp_wait<0>(); }
        __syncthreads();

        uint32_t sKhi = sb + (uint32_t)st * 32768;
        uint32_t sKlo = sKhi + 8192;
        uint32_t sVhi = sKlo + 8192;
        uint32_t sVlo = sVhi + 8192;

        // ---- S = Q K^T (3 split passes) ----
        float s[8][4] = {};
#pragma unroll
        for (int ks = 0; ks < 4; ks++) {
            uint32_t kx = (uint32_t)(ks << 5);
            uint32_t bf[4][4];
#pragma unroll
            for (int np = 0; np < 4; np++) {
                int br = np * 16 + qhi * 8 + lr;
                uint32_t boff = (uint32_t)(br * 128) +
                                (uint32_t)(((qlo * 16) ^ (int)kx) ^ ((br & 7) * 16));
                ldsm_x4(bf[np], sKhi + boff);
            }
#pragma unroll
            for (int nt = 0; nt < 8; nt++)
                mma_bf16(s[nt], qfh[ks], &bf[nt >> 1][(nt & 1) * 2]);
#pragma unroll
            for (int nt = 0; nt < 8; nt++)
                mma_bf16(s[nt], qfl[ks], &bf[nt >> 1][(nt & 1) * 2]);
#pragma unroll
            for (int np = 0; np < 4; np++) {
                int br = np * 16 + qhi * 8 + lr;
                uint32_t boff = (uint32_t)(br * 128) +
                                (uint32_t)(((qlo * 16) ^ (int)kx) ^ ((br & 7) * 16));
                ldsm_x4(bf[np], sKlo + boff);
            }
#pragma unroll
            for (int nt = 0; nt < 8; nt++)
                mma_bf16(s[nt], qfh[ks], &bf[nt >> 1][(nt & 1) * 2]);
        }

        // ---- causal mask (diagonal tile only) ----
        if (causal && kt == (int)blockIdx.x) {
            int r0 = q0 + wid * 16 + g, r1 = r0 + 8;
#pragma unroll
            for (int nt = 0; nt < 8; nt++) {
                int kbase = k0 + nt * 8 + tg * 2;
                if (kbase > r0)     s[nt][0] = -1e30f;
                if (kbase + 1 > r0) s[nt][1] = -1e30f;
                if (kbase > r1)     s[nt][2] = -1e30f;
                if (kbase + 1 > r1) s[nt][3] = -1e30f;
            }
        }

        // ---- online softmax ----
        float mx0 = -1e30f, mx1 = -1e30f;
#pragma unroll
        for (int nt = 0; nt < 8; nt++) {
            mx0 = fmaxf(mx0, fmaxf(s[nt][0], s[nt][1]));
            mx1 = fmaxf(mx1, fmaxf(s[nt][2], s[nt][3]));
        }
        mx0 = fmaxf(mx0, __shfl_xor_sync(0xffffffffu, mx0, 1));
        mx0 = fmaxf(mx0, __shfl_xor_sync(0xffffffffu, mx0, 2));
        mx1 = fmaxf(mx1, __shfl_xor_sync(0xffffffffu, mx1, 1));
        mx1 = fmaxf(mx1, __shfl_xor_sync(0xffffffffu, mx1, 2));
        float mn0 = fmaxf(m0r, mx0), mn1 = fmaxf(m1r, mx1);
        float al0 = fexp(m0r - mn0), al1 = fexp(m1r - mn1);
        float sum0 = 0.f, sum1 = 0.f;
#pragma unroll
        for (int nt = 0; nt < 8; nt++) {
            s[nt][0] = fexp(s[nt][0] - mn0);
            s[nt][1] = fexp(s[nt][1] - mn0);
            s[nt][2] = fexp(s[nt][2] - mn1);
            s[nt][3] = fexp(s[nt][3] - mn1);
            sum0 += s[nt][0] + s[nt][1];
            sum1 += s[nt][2] + s[nt][3];
        }
        sum0 += __shfl_xor_sync(0xffffffffu, sum0, 1);
        sum0 += __shfl_xor_sync(0xffffffffu, sum0, 2);
        sum1 += __shfl_xor_sync(0xffffffffu, sum1, 1);
        sum1 += __shfl_xor_sync(0xffffffffu, sum1, 2);
        l0r = l0r * al0 + sum0; m0r = mn0;
        l1r = l1r * al1 + sum1; m1r = mn1;
#pragma unroll
        for (int nt = 0; nt < 8; nt++) {
            o[nt][0] *= al0; o[nt][1] *= al0;
            o[nt][2] *= al1; o[nt][3] *= al1;
        }

        // ---- O += P V (3 split passes), V via ldmatrix.trans ----
#pragma unroll
        for (int kb = 0; kb < 4; kb++) {
            uint32_t ph[4], pl[4];
            split2(s[2 * kb][0],     s[2 * kb][1],     ph[0], pl[0]);
            split2(s[2 * kb][2],     s[2 * kb][3],     ph[1], pl[1]);
            split2(s[2 * kb + 1][0], s[2 * kb + 1][1], ph[2], pl[2]);
            split2(s[2 * kb + 1][2], s[2 * kb + 1][3], ph[3], pl[3]);
            uint32_t vfh[4][4], vfl[4][4];
            int vr = kb * 16 + qlo * 8 + lr;
            uint32_t vrow = (uint32_t)(vr * 128);
            uint32_t vsw  = (uint32_t)((vr & 7) * 16);
#pragma unroll
            for (int np = 0; np < 4; np++) {
                ldsm_x4_t(vfh[np], sVhi + vrow + (((uint32_t)(np * 32 + qhi * 16)) ^ vsw));
                ldsm_x4_t(vfl[np], sVlo + vrow + (((uint32_t)(np * 32 + qhi * 16)) ^ vsw));
            }
#pragma unroll
            for (int nt = 0; nt < 8; nt++)
                mma_bf16(o[nt], ph, &vfh[nt >> 1][(nt & 1) * 2]);
#pragma unroll
            for (int nt = 0; nt < 8; nt++)
                mma_bf16(o[nt], pl, &vfh[nt >> 1][(nt & 1) * 2]);
#pragma unroll
            for (int nt = 0; nt < 8; nt++)
                mma_bf16(o[nt], ph, &vfl[nt >> 1][(nt & 1) * 2]);
        }
        __syncthreads();
    }

    // ---- epilogue ----
    float inv0 = 1.f / l0r, inv1 = 1.f / l1r;
    int row0 = q0 + wid * 16 + g;
    int row1 = row0 + 8;
#pragma unroll
    for (int nt = 0; nt < 8; nt++) {
        int col = h * HDIM + nt * 8 + tg * 2;
        float v00 = o[nt][0] * inv0, v01 = o[nt][1] * inv0;
        float v10 = o[nt][2] * inv1, v11 = o[nt][3] * inv1;
        if (mode == 0) {
            *(float2*)(O + (size_t)row0 * DM + col) = make_float2(v00, v01);
            *(float2*)(O + (size_t)row1 * DM + col) = make_float2(v10, v11);
        } else {
            if (mode == 1) {
                float2 a0 = *(float2*)(O + (size_t)row0 * DM + col);
                float2 a1 = *(float2*)(O + (size_t)row1 * DM + col);
                v00 += a0.x; v01 += a0.y; v10 += a1.x; v11 += a1.y;
            }
            uint32_t h0, l0, h1, l1;
            split2(v00, v01, h0, l0);
            split2(v10, v11, h1, l1);
            *(uint32_t*)(Ohi + (size_t)row0 * DM + col) = h0;
            *(uint32_t*)(Olo + (size_t)row0 * DM + col) = l0;
            *(uint32_t*)(Ohi + (size_t)row1 * DM + col) = h1;
            *(uint32_t*)(Olo + (size_t)row1 * DM + col) = l1;
        }
    }
}

// ---------------- host orchestration ----------------------------------------------
extern "C" void kernel_launch(void* const* d_in, const int* in_sizes, int n_in,
                              void* d_out, int out_size) {
    const float* x     = (const float*)d_in[0];
    const float* ctx   = (const float*)d_in[1];
    const float* qkv_w = (const float*)d_in[2];
    const float* qkv_b = (const float*)d_in[3];
    const float* out_w = (const float*)d_in[4];
    const float* out_b = (const float*)d_in[5];
    const float* w1    = (const float*)d_in[6];
    const float* w3    = (const float*)d_in[7];
    const float* w2    = (const float*)d_in[8];
    const float* n1g   = (const float*)d_in[9];
    const float* n1b   = (const float*)d_in[10];
    const float* n2g   = (const float*)d_in[11];
    const float* n2b   = (const float*)d_in[12];
    float* out = (float*)d_out;

    cudaFuncSetAttribute(mma_gemm_kernel, cudaFuncAttributeMaxDynamicSharedMemorySize, GEMM_SMEM);
    cudaFuncSetAttribute(attn_mma, cudaFuncAttributeMaxDynamicSharedMemorySize, ATTN_SMEM);

    void* p;
    cudaGetSymbolAddress(&p, g_qkv);    float* qkv    = (float*)p;
    cudaGetSymbolAddress(&p, g_attn);   float* attn   = (float*)p;
    cudaGetSymbolAddress(&p, g_h1);     float* h1     = (float*)p;
    cudaGetSymbolAddress(&p, g_gateup); float* gateup = (float*)p;
    cudaGetSymbolAddress(&p, g_act_hi); __nv_bfloat16* ahi = (__nv_bfloat16*)p;
    cudaGetSymbolAddress(&p, g_act_lo); __nv_bfloat16* alo = (__nv_bfloat16*)p;
    cudaGetSymbolAddress(&p, g_wqkv_hi); __nv_bfloat16* wqhi = (__nv_bfloat16*)p;
    cudaGetSymbolAddress(&p, g_wqkv_lo); __nv_bfloat16* wqlo = (__nv_bfloat16*)p;
    cudaGetSymbolAddress(&p, g_wout_hi); __nv_bfloat16* wohi = (__nv_bfloat16*)p;
    cudaGetSymbolAddress(&p, g_wout_lo); __nv_bfloat16* wolo = (__nv_bfloat16*)p;
    cudaGetSymbolAddress(&p, g_w13_hi); __nv_bfloat16* w13hi = (__nv_bfloat16*)p;
    cudaGetSymbolAddress(&p, g_w13_lo); __nv_bfloat16* w13lo = (__nv_bfloat16*)p;
    cudaGetSymbolAddress(&p, g_w2_hi);  __nv_bfloat16* w2hi = (__nv_bfloat16*)p;
    cudaGetSymbolAddress(&p, g_w2_lo);  __nv_bfloat16* w2lo = (__nv_bfloat16*)p;
    cudaGetSymbolAddress(&p, g_qx_hi);  __nv_bfloat16* qxhi = (__nv_bfloat16*)p;
    cudaGetSymbolAddress(&p, g_qx_lo);  __nv_bfloat16* qxlo = (__nv_bfloat16*)p;
    cudaGetSymbolAddress(&p, g_kx_hi);  __nv_bfloat16* kxhi = (__nv_bfloat16*)p;
    cudaGetSymbolAddress(&p, g_kx_lo);  __nv_bfloat16* kxlo = (__nv_bfloat16*)p;
    cudaGetSymbolAddress(&p, g_kc_hi);  __nv_bfloat16* kchi = (__nv_bfloat16*)p;
    cudaGetSymbolAddress(&p, g_kc_lo);  __nv_bfloat16* kclo = (__nv_bfloat16*)p;
    cudaGetSymbolAddress(&p, g_qs_hi);  __nv_bfloat16* qshi = (__nv_bfloat16*)p;
    cudaGetSymbolAddress(&p, g_qs_lo);  __nv_bfloat16* qslo = (__nv_bfloat16*)p;
    cudaGetSymbolAddress(&p, g_v_hi);   __nv_bfloat16* vhi  = (__nv_bfloat16*)p;
    cudaGetSymbolAddress(&p, g_v_lo);   __nv_bfloat16* vlo  = (__nv_bfloat16*)p;

    dim3 tb(32, 8);
    build_rope_table<<<(MAXPOS * 32 + 255) / 256, 256>>>();

    // weight transpose+split (w1,w3 packed into one [5632][1024] buffer)
    wt_split_kernel<<<dim3(3 * DM / 32, DM / 32), tb>>>(qkv_w, wqhi, wqlo, DM, 3 * DM);
    wt_split_kernel<<<dim3(DM / 32, DM / 32),     tb>>>(out_w, wohi, wolo, DM, DM);
    wt_split_kernel<<<dim3(HID / 32, DM / 32),    tb>>>(w1, w13hi, w13lo, DM, HID);
    wt_split_kernel<<<dim3(HID / 32, DM / 32),    tb>>>(w3, w13hi + (size_t)HID * DM,
                                                        w13lo + (size_t)HID * DM, DM, HID);
    wt_split_kernel<<<dim3(DM / 32, HID / 32),    tb>>>(w2, w2hi, w2lo, HID, DM);

    // LN1 fused with split -> act buffers [LTOT][DM]
    ln_split_kernel<<<LXX, 256>>>(x,   ahi,                    alo,                    n1g, n1b);
    ln_split_kernel<<<LCC, 256>>>(ctx, ahi + (size_t)LXX * DM, alo + (size_t)LXX * DM, n1g, n1b);

    // QKV projection
    mma_gemm_kernel<<<dim3(3 * DM / 128, LTOT / 128), 256, GEMM_SMEM>>>(
        ahi, alo, wqhi, wqlo, qkv, qkv_b, nullptr, nullptr, 0, LTOT, 3 * DM, DM);

    // RoPE + split (q-side pre-scaled by 1/8), V split
    rope_split_kernel<<<(LXX * 512 + 255) / 256, 256>>>(qkv, 3 * DM, qxhi, qxlo, LXX, POS_X, 0.125f);
    rope_split_kernel<<<(LXX * 512 + 255) / 256, 256>>>(qkv + DM, 3 * DM, kxhi, kxlo, LXX, POS_X, 1.f);
    rope_split_kernel<<<(LCC * 512 + 255) / 256, 256>>>(qkv + (size_t)LXX * 3 * DM + DM, 3 * DM, kchi, kclo, LCC, POS_C, 1.f);
    rope_split_kernel<<<(2048 * 512 + 255) / 256, 256>>>(qkv + (size_t)(LXX + HWSP) * 3 * DM, 3 * DM, qshi, qslo, 2048, HWSP, 0.125f);
    v_split_kernel<<<(LTOT * 512 + 255) / 256, 256>>>(qkv, vhi, vlo);

    const size_t vcoff = (size_t)LXX * DM;

    // a1 (mode 0: fp32 staging) ; a2 (mode 1: +a1, split out) ; a3 (mode 2: split out)
    attn_mma<<<dim3(LXX / 64, NH), 128, ATTN_SMEM>>>(qxhi, qxlo, kchi, kclo,
        vhi + vcoff, vlo + vcoff, attn, nullptr, nullptr, LCC, 0, 0);
    attn_mma<<<dim3(LXX / 64, NH), 128, ATTN_SMEM>>>(qxhi, qxlo, kxhi, kxlo,
        vhi, vlo, attn, ahi, alo, LXX, 1, 1);
    attn_mma<<<dim3(2048 / 64, NH), 128, ATTN_SMEM>>>(qshi, qslo, kchi, kclo,
        vhi + vcoff, vlo + vcoff, nullptr,
        ahi + (size_t)2048 * DM, alo + (size_t)2048 * DM, LCC, 0, 2);

    // out projection + bias + residual
    mma_gemm_kernel<<<dim3(DM / 128, LOUT / 128), 256, GEMM_SMEM>>>(
        ahi, alo, wohi, wolo, h1, out_b, x, ctx, 2048, LOUT, DM, DM);

    // LN2 fused with split
    ln_split_kernel<<<LOUT, 256>>>(h1, ahi, alo, n2g, n2b);

    // FFN: combined w1|w3 GEMM -> gateup, fused silu*mul+split, w2 GEMM
    mma_gemm_kernel<<<dim3(2 * HID / 128, LOUT / 128), 256, GEMM_SMEM>>>(
        ahi, alo, w13hi, w13lo, gateup, nullptr, nullptr, nullptr, 0, LOUT, 2 * HID, DM);
    silu_mul_split_kernel<<<dim3(HID / 256, LOUT), 256>>>(gateup, ahi, alo);
    mma_gemm_kernel<<<dim3(DM / 128, LOUT / 128), 256, GEMM_SMEM>>>(
        ahi, alo, w2hi, w2lo, out, nullptr, h1, h1, LOUT, LOUT, DM, HID);
}

// round 7
// speedup vs baseline: 3.4102x; 1.1868x over previous
#include <cuda_runtime.h>
#include <cuda_bf16.h>
#include <cuda_fp16.h>
#include <math.h>
#include <stdint.h>

// ---------------- problem constants (from setup_inputs, deterministic) ----------
#define LXX     2048
#define LCC     4096
#define DM      1024
#define NH      16
#define HDIM    64
#define HID     2816
#define LTOT    6144
#define LOUT    4096
#define POS_X   4096
#define POS_C   0
#define HWSP    2048
#define MAXPOS  6144

#define WSCALE     64.0f
#define WSCALE_INV 0.015625f

// ---------------- scratch (device globals; no runtime allocation) ---------------
__device__ float g_qkv   [LTOT * 3 * DM];
__device__ float g_attn  [LXX * DM];          // a1 fp32 staging
__device__ float g_h1    [LOUT * DM];
__device__ float g_gateup[LOUT * 2 * HID];
__device__ float g_cos   [MAXPOS * 32];
__device__ float g_sin   [MAXPOS * 32];

// fp16 single-precision activation buffer (A operand of all weight GEMMs)
__device__ __half g_act_h[LOUT * HID];
// fp16 split weights [N][K], pre-scaled by WSCALE
__device__ __half g_wqkv_h[3 * DM * DM], g_wqkv_l[3 * DM * DM];
__device__ __half g_wout_h[DM * DM],     g_wout_l[DM * DM];
__device__ __half g_w13_h[2 * HID * DM], g_w13_l[2 * HID * DM];
__device__ __half g_w2_h [DM * HID],     g_w2_l [DM * HID];

// split-bf16 attention operands (attention stays bf16 3-pass)
__device__ __nv_bfloat16 g_qx_hi[LXX * DM],  g_qx_lo[LXX * DM];
__device__ __nv_bfloat16 g_kx_hi[LXX * DM],  g_kx_lo[LXX * DM];
__device__ __nv_bfloat16 g_kc_hi[LCC * DM],  g_kc_lo[LCC * DM];
__device__ __nv_bfloat16 g_qs_hi[2048 * DM], g_qs_lo[2048 * DM];
__device__ __nv_bfloat16 g_v_hi [LTOT * DM], g_v_lo [LTOT * DM];

// ---------------- helpers (portable: sm_80+ PTX) ----------------------------------
__device__ __forceinline__ uint32_t smem_to_u32(const void* p) {
    uint32_t a;
    asm("{ .reg .u64 t; cvta.to.shared.u64 t, %1; cvt.u32.u64 %0, t; }" : "=r"(a) : "l"(p));
    return a;
}
#define SMEM_SWIZZLE_128B(b) ((b) ^ (((b) >> 3) & 0x70))

__device__ __forceinline__ void cp16(uint32_t s, const void* g) {
    asm volatile("cp.async.cg.shared.global [%0], [%1], 16;" :: "r"(s), "l"(g) : "memory");
}
__device__ __forceinline__ void cp_commit() {
    asm volatile("cp.async.commit_group;" ::: "memory");
}
template<int N> __device__ __forceinline__ void cp_wait() {
    asm volatile("cp.async.wait_group %0;" :: "n"(N) : "memory");
}

__device__ __forceinline__ void ldsm_x4(uint32_t* r, uint32_t addr) {
    asm volatile("ldmatrix.sync.aligned.m8n8.x4.shared.b16 {%0,%1,%2,%3}, [%4];"
        : "=r"(r[0]), "=r"(r[1]), "=r"(r[2]), "=r"(r[3]) : "r"(addr));
}
__device__ __forceinline__ void ldsm_x4_t(uint32_t* r, uint32_t addr) {
    asm volatile("ldmatrix.sync.aligned.m8n8.x4.trans.shared.b16 {%0,%1,%2,%3}, [%4];"
        : "=r"(r[0]), "=r"(r[1]), "=r"(r[2]), "=r"(r[3]) : "r"(addr));
}
__device__ __forceinline__ void mma_bf16(float* c, const uint32_t* a, const uint32_t* b) {
    asm volatile("mma.sync.aligned.m16n8k16.row.col.f32.bf16.bf16.f32 "
        "{%0,%1,%2,%3}, {%4,%5,%6,%7}, {%8,%9}, {%0,%1,%2,%3};"
        : "+f"(c[0]), "+f"(c[1]), "+f"(c[2]), "+f"(c[3])
        : "r"(a[0]), "r"(a[1]), "r"(a[2]), "r"(a[3]), "r"(b[0]), "r"(b[1]));
}
__device__ __forceinline__ void mma_f16(float* c, const uint32_t* a, const uint32_t* b) {
    asm volatile("mma.sync.aligned.m16n8k16.row.col.f32.f16.f16.f32 "
        "{%0,%1,%2,%3}, {%4,%5,%6,%7}, {%8,%9}, {%0,%1,%2,%3};"
        : "+f"(c[0]), "+f"(c[1]), "+f"(c[2]), "+f"(c[3])
        : "r"(a[0]), "r"(a[1]), "r"(a[2]), "r"(a[3]), "r"(b[0]), "r"(b[1]));
}

// fast exp on FMA pipe (x <= 0), rel err ~2e-6
__device__ __forceinline__ float fexp(float x) {
    x = fmaxf(x, -87.0f);
    float t = x * 1.4426950408889634f;
    float r = t + 12582912.0f;
    float n = r - 12582912.0f;
    float f = t - n;
    float p = 0.0013298820f;
    p = fmaf(p, f, 0.0096181291f);
    p = fmaf(p, f, 0.0555041087f);
    p = fmaf(p, f, 0.2402265069f);
    p = fmaf(p, f, 0.6931471806f);
    p = fmaf(p, f, 1.0f);
    int ni = (int)n;
    return p * __int_as_float((ni + 127) << 23);
}

__device__ __forceinline__ void split2(float x, float y, uint32_t& h, uint32_t& l) {
    __nv_bfloat16 hx = __float2bfloat16(x), hy = __float2bfloat16(y);
    __nv_bfloat16 lx = __float2bfloat16(x - __bfloat162float(hx));
    __nv_bfloat16 ly = __float2bfloat16(y - __bfloat162float(hy));
    __nv_bfloat162 hh(hx, hy), ll(lx, ly);
    h = *(uint32_t*)&hh;
    l = *(uint32_t*)&ll;
}

// ---------------- rope cos/sin table (fp64 angles) -------------------------------
__global__ void build_rope_table() {
    int idx = blockIdx.x * blockDim.x + threadIdx.x;
    if (idx >= MAXPOS * 32) return;
    int pos = idx >> 5, j = idx & 31;
    double inv = pow(10000.0, -((double)(2 * j)) / 64.0);
    double ang = (double)pos * inv;
    g_cos[idx] = (float)cos(ang);
    g_sin[idx] = (float)sin(ang);
}

// ---------------- LayerNorm fused with fp16 output ---------------------------------
__global__ void ln_f16_kernel(const float* __restrict__ in,
                              __half* __restrict__ out,
                              const float* __restrict__ gam,
                              const float* __restrict__ bet) {
    __shared__ float sh[32];
    __shared__ float s_mean, s_rstd;
    int row = blockIdx.x, t = threadIdx.x;
    const float* x = in + (size_t)row * DM;
    float v[4];
    float s = 0.f;
#pragma unroll
    for (int i = 0; i < 4; i++) { v[i] = x[t + 256 * i]; s += v[i]; }
#pragma unroll
    for (int o = 16; o; o >>= 1) s += __shfl_xor_sync(0xffffffffu, s, o);
    if ((t & 31) == 0) sh[t >> 5] = s;
    __syncthreads();
    if (t < 32) {
        float z = (t < 8) ? sh[t] : 0.f;
#pragma unroll
        for (int o = 4; o; o >>= 1) z += __shfl_xor_sync(0xffffffffu, z, o);
        if (t == 0) s_mean = z * (1.f / 1024.f);
    }
    __syncthreads();
    float mean = s_mean;
    float q = 0.f;
#pragma unroll
    for (int i = 0; i < 4; i++) { float d = v[i] - mean; q += d * d; }
#pragma unroll
    for (int o = 16; o; o >>= 1) q += __shfl_xor_sync(0xffffffffu, q, o);
    if ((t & 31) == 0) sh[t >> 5] = q;
    __syncthreads();
    if (t < 32) {
        float z = (t < 8) ? sh[t] : 0.f;
#pragma unroll
        for (int o = 4; o; o >>= 1) z += __shfl_xor_sync(0xffffffffu, z, o);
        if (t == 0) s_rstd = rsqrtf(z * (1.f / 1024.f) + 1e-5f);
    }
    __syncthreads();
    float rstd = s_rstd;
#pragma unroll
    for (int i = 0; i < 4; i++) {
        int c = t + 256 * i;
        float r = (v[i] - mean) * rstd * gam[c] + bet[c];
        out[(size_t)row * DM + c] = __float2half(r);
    }
}

// ---------------- RoPE fused with split-bf16 --------------------------------------
__global__ void rope_split_kernel(const float* __restrict__ src, int lds,
                                  __nv_bfloat16* __restrict__ hi,
                                  __nv_bfloat16* __restrict__ lo,
                                  int L, int pos0, float scale) {
    int idx = blockIdx.x * blockDim.x + threadIdx.x;
    if (idx >= L * 512) return;
    int j = idx & 31, h = (idx >> 5) & 15, l = idx >> 9;
    int pos = pos0 + l;
    float c = g_cos[pos * 32 + j], s = g_sin[pos * 32 + j];
    const float* p = src + (size_t)l * lds + h * HDIM;
    float t1 = p[j], t2 = p[j + 32];
    float r1 = (t1 * c - t2 * s) * scale;
    float r2 = (t2 * c + t1 * s) * scale;
    size_t o = (size_t)l * DM + h * HDIM;
    __nv_bfloat16 h1 = __float2bfloat16(r1);
    __nv_bfloat16 h2 = __float2bfloat16(r2);
    hi[o + j]      = h1;
    hi[o + j + 32] = h2;
    lo[o + j]      = __float2bfloat16(r1 - __bfloat162float(h1));
    lo[o + j + 32] = __float2bfloat16(r2 - __bfloat162float(h2));
}

// ---------------- V split: strided fp32 -> contiguous split bf16 ------------------
__global__ void v_split_kernel(const float* __restrict__ qkv,
                               __nv_bfloat16* __restrict__ hi,
                               __nv_bfloat16* __restrict__ lo) {
    int i = blockIdx.x * blockDim.x + threadIdx.x;
    if (i >= LTOT * 512) return;
    int r = i >> 9, c2 = i & 511;
    float2 v = *(const float2*)(qkv + (size_t)r * 3 * DM + 2 * DM + c2 * 2);
    __nv_bfloat16 hx = __float2bfloat16(v.x), hy = __float2bfloat16(v.y);
    __nv_bfloat162 h(hx, hy);
    __nv_bfloat162 l(__float2bfloat16(v.x - __bfloat162float(hx)),
                     __float2bfloat16(v.y - __bfloat162float(hy)));
    ((__nv_bfloat162*)hi)[(size_t)r * 512 + c2] = h;
    ((__nv_bfloat162*)lo)[(size_t)r * 512 + c2] = l;
}

// ---------------- weight transpose + fp16 split (pre-scaled by WSCALE) ------------
__global__ void wt_split_f16_kernel(const float* __restrict__ w,
                                    __half* __restrict__ hi,
                                    __half* __restrict__ lo, int K, int N) {
    __shared__ float t[32][33];
    int n0 = blockIdx.x * 32, k0 = blockIdx.y * 32;
    int tx = threadIdx.x, ty = threadIdx.y;
#pragma unroll
    for (int i = 0; i < 32; i += 8)
        t[ty + i][tx] = w[(size_t)(k0 + ty + i) * N + n0 + tx];
    __syncthreads();
#pragma unroll
    for (int i = 0; i < 32; i += 8) {
        int n = n0 + ty + i, k = k0 + tx;
        float v = t[tx][ty + i] * WSCALE;
        __half h = __float2half(v);
        hi[(size_t)n * K + k] = h;
        lo[(size_t)n * K + k] = __float2half(v - __half2float(h));
    }
}

// ---------------- silu(g)*u fused with fp16 output ---------------------------------
__global__ void silu_mul_f16_kernel(const float* __restrict__ gu,
                                    __half* __restrict__ out) {
    int col = blockIdx.x * 256 + threadIdx.x;     // < HID
    int row = blockIdx.y;
    float g = gu[(size_t)row * (2 * HID) + col];
    float u = gu[(size_t)row * (2 * HID) + HID + col];
    float r = (g / (1.f + __expf(-g))) * u;
    out[(size_t)row * HID + col] = __float2half(r);
}

// ---------------- fp16 2-pass GEMM, cp.async 2-stage pipeline ----------------------
// C[M][N] = (1/WSCALE) * A[M][K] * (Bh+Bl)[N][K]^T; A fp16 single, B fp16 hi/lo.
// CTA 128x128, BK=64, 256 thr, warp 64x32.
static const int GEMM_SMEM = 2 * 3 * 16384;   // 98304

__global__ void __launch_bounds__(256, 2)
mma_gemm_kernel(const __half* __restrict__ A,
                const __half* __restrict__ Bh, const __half* __restrict__ Bl,
                float* __restrict__ C, const float* __restrict__ bias,
                const float* __restrict__ res0, const float* __restrict__ res1, int split,
                int M, int N, int K) {
    extern __shared__ char smem[];
    uint32_t sbase = smem_to_u32(smem);

    int tid = threadIdx.x;
    int wid = tid >> 5, lane = tid & 31;
    int wr = wid >> 2, wc = wid & 3;
    int m0 = blockIdx.y * 128, n0 = blockIdx.x * 128;

    int lr  = lane & 7;
    int lq  = lane >> 3;
    int qlo = lq & 1, qhi = lq >> 1;

    uint32_t aoff[4];
#pragma unroll
    for (int mt = 0; mt < 4; mt++) {
        int row = wr * 64 + mt * 16 + qlo * 8 + lr;
        aoff[mt] = (uint32_t)(row * 128) + (uint32_t)((qhi * 16) ^ ((row & 7) * 16));
    }
    uint32_t boff[2];
#pragma unroll
    for (int np = 0; np < 2; np++) {
        int row = wc * 32 + np * 16 + qhi * 8 + lr;
        boff[np] = (uint32_t)(row * 128) + (uint32_t)((qlo * 16) ^ ((row & 7) * 16));
    }

    auto issue = [&](int st, int kc0) {
        uint32_t base = sbase + (uint32_t)st * 49152;
#pragma unroll
        for (int it = 0; it < 4; it++) {
            int idx = tid + it * 256;
            int r = idx >> 3, q = idx & 7;
            uint32_t so = SMEM_SWIZZLE_128B((uint32_t)(r * 128 + q * 16));
            cp16(base + so,         A  + (size_t)(m0 + r) * K + kc0 + q * 8);
            cp16(base + 16384 + so, Bh + (size_t)(n0 + r) * K + kc0 + q * 8);
            cp16(base + 32768 + so, Bl + (size_t)(n0 + r) * K + kc0 + q * 8);
        }
        cp_commit();
    };

    float acc[4][4][4] = {};
    int nchunks = K >> 6;

    issue(0, 0);
    for (int kc = 0; kc < nchunks; kc++) {
        int st = kc & 1;
        if (kc + 1 < nchunks) { issue(st ^ 1, (kc + 1) << 6); cp_wait<1>(); }
        else                  { cp_wait<0>(); }
        __syncthreads();

        uint32_t sA  = sbase + (uint32_t)st * 49152;
        uint32_t sBh = sA + 16384;
        uint32_t sBl = sBh + 16384;

#pragma unroll
        for (int ks = 0; ks < 4; ks++) {
            uint32_t kx = (uint32_t)(ks << 5);
            uint32_t bh[2][4], bl[2][4];
#pragma unroll
            for (int np = 0; np < 2; np++) {
                ldsm_x4(bh[np], sBh + (boff[np] ^ kx));
                ldsm_x4(bl[np], sBl + (boff[np] ^ kx));
            }
#pragma unroll
            for (int mt = 0; mt < 4; mt++) {
                uint32_t ah[4];
                ldsm_x4(ah, sA + (aoff[mt] ^ kx));
#pragma unroll
                for (int nt = 0; nt < 4; nt++)
                    mma_f16(acc[mt][nt], ah, &bh[nt >> 1][(nt & 1) * 2]);
#pragma unroll
                for (int nt = 0; nt < 4; nt++)
                    mma_f16(acc[mt][nt], ah, &bl[nt >> 1][(nt & 1) * 2]);
            }
        }
        __syncthreads();
    }

    int g = lane >> 2, tg = lane & 3;
#pragma unroll
    for (int mt = 0; mt < 4; mt++) {
#pragma unroll
        for (int half = 0; half < 2; half++) {
            int row = m0 + wr * 64 + mt * 16 + g + half * 8;
            const float* rp = nullptr;
            if (res0) rp = ((row < split) ? res0 : res1) + (size_t)row * N;
            float* cp = C + (size_t)row * N;
#pragma unroll
            for (int nt = 0; nt < 4; nt++) {
                int col = n0 + wc * 32 + nt * 8 + tg * 2;
                float2 v;
                v.x = acc[mt][nt][half * 2 + 0] * WSCALE_INV;
                v.y = acc[mt][nt][half * 2 + 1] * WSCALE_INV;
                if (bias) { v.x += bias[col]; v.y += bias[col + 1]; }
                if (rp)   { v.x += rp[col];   v.y += rp[col + 1]; }
                *(float2*)(cp + col) = v;
            }
        }
    }
}

// ---------------- mma.sync flash attention (bf16 3-pass), cp.async 2-stage ---------
// mode 0: write fp32 O; mode 1: read fp32 O, add, write fp16; mode 2: write fp16
static const int ATTN_SMEM = 2 * 4 * 8192;    // 65536

__global__ void __launch_bounds__(128)
attn_mma(const __nv_bfloat16* __restrict__ Qhi, const __nv_bfloat16* __restrict__ Qlo,
         const __nv_bfloat16* __restrict__ Khi, const __nv_bfloat16* __restrict__ Klo,
         const __nv_bfloat16* __restrict__ Vhi, const __nv_bfloat16* __restrict__ Vlo,
         float* __restrict__ O, __half* __restrict__ Oh,
         int LK, int causal, int mode) {
    extern __shared__ char smema[];
    uint32_t sb = smem_to_u32(smema);

    int tid = threadIdx.x;
    int wid = tid >> 5, lane = tid & 31;
    int g = lane >> 2, tg = lane & 3;
    int lr = lane & 7, qlo = (lane >> 3) & 1, qhi = lane >> 4;
    int q0 = blockIdx.x * 64;
    int h  = blockIdx.y;

    // ---- stage Q into stage-0 buffers, extract fragments ----
#pragma unroll
    for (int it = 0; it < 4; it++) {
        int e = tid + it * 128;
        int row = e >> 3, q = e & 7;
        uint32_t off = (uint32_t)(row * 128) + (uint32_t)((q * 16) ^ ((row & 7) * 16));
        *(uint4*)(smema + off)        = *(const uint4*)(Qhi + (size_t)(q0 + row) * DM + h * HDIM + q * 8);
        *(uint4*)(smema + 8192 + off) = *(const uint4*)(Qlo + (size_t)(q0 + row) * DM + h * HDIM + q * 8);
    }
    __syncthreads();
    uint32_t qfh[4][4], qfl[4][4];
    {
        int arow = wid * 16 + qlo * 8 + lr;
        uint32_t abase = (uint32_t)(arow * 128) + (uint32_t)((qhi * 16) ^ ((arow & 7) * 16));
#pragma unroll
        for (int ks = 0; ks < 4; ks++) {
            ldsm_x4(qfh[ks], sb + (abase ^ (uint32_t)(ks << 5)));
            ldsm_x4(qfl[ks], sb + 8192 + (abase ^ (uint32_t)(ks << 5)));
        }
    }
    __syncthreads();

    auto issue = [&](int st, int k0) {
        uint32_t base = sb + (uint32_t)st * 32768;
#pragma unroll
        for (int it = 0; it < 4; it++) {
            int e = tid + it * 128;
            int row = e >> 3, q = e & 7;
            uint32_t off = (uint32_t)(row * 128) + (uint32_t)((q * 16) ^ ((row & 7) * 16));
            size_t gidx = (size_t)(k0 + row) * DM + h * HDIM + q * 8;
            cp16(base + off,         Khi + gidx);
            cp16(base + 8192 + off,  Klo + gidx);
            cp16(base + 16384 + off, Vhi + gidx);
            cp16(base + 24576 + off, Vlo + gidx);
        }
        cp_commit();
    };

    float o[8][4] = {};
    float m0r = -1e30f, m1r = -1e30f, l0r = 0.f, l1r = 0.f;

    int ntiles = causal ? ((int)blockIdx.x + 1) : (LK >> 6);
    issue(0, 0);
    for (int kt = 0; kt < ntiles; kt++) {
        int k0 = kt << 6;
        int st = kt & 1;
        if (kt + 1 < ntiles) { issue(st ^ 1, (kt + 1) << 6); cp_wait<1>(); }
        else                 { cp_wait<0>(); }
        __syncthreads();

        uint32_t sKhi = sb + (uint32_t)st * 32768;
        uint32_t sKlo = sKhi + 8192;
        uint32_t sVhi = sKlo + 8192;
        uint32_t sVlo = sVhi + 8192;

        // ---- S = Q K^T (3 split passes) ----
        float s[8][4] = {};
#pragma unroll
        for (int ks = 0; ks < 4; ks++) {
            uint32_t kx = (uint32_t)(ks << 5);
            uint32_t bf[4][4];
#pragma unroll
            for (int np = 0; np < 4; np++) {
                int br = np * 16 + qhi * 8 + lr;
                uint32_t boff = (uint32_t)(br * 128) +
                                (uint32_t)(((qlo * 16) ^ (int)kx) ^ ((br & 7) * 16));
                ldsm_x4(bf[np], sKhi + boff);
            }
#pragma unroll
            for (int nt = 0; nt < 8; nt++)
                mma_bf16(s[nt], qfh[ks], &bf[nt >> 1][(nt & 1) * 2]);
#pragma unroll
            for (int nt = 0; nt < 8; nt++)
                mma_bf16(s[nt], qfl[ks], &bf[nt >> 1][(nt & 1) * 2]);
#pragma unroll
            for (int np = 0; np < 4; np++) {
                int br = np * 16 + qhi * 8 + lr;
                uint32_t boff = (uint32_t)(br * 128) +
                                (uint32_t)(((qlo * 16) ^ (int)kx) ^ ((br & 7) * 16));
                ldsm_x4(bf[np], sKlo + boff);
            }
#pragma unroll
            for (int nt = 0; nt < 8; nt++)
                mma_bf16(s[nt], qfh[ks], &bf[nt >> 1][(nt & 1) * 2]);
        }

        // ---- causal mask (diagonal tile only) ----
        if (causal && kt == (int)blockIdx.x) {
            int r0 = q0 + wid * 16 + g, r1 = r0 + 8;
#pragma unroll
            for (int nt = 0; nt < 8; nt++) {
                int kbase = k0 + nt * 8 + tg * 2;
                if (kbase > r0)     s[nt][0] = -1e30f;
                if (kbase + 1 > r0) s[nt][1] = -1e30f;
                if (kbase > r1)     s[nt][2] = -1e30f;
                if (kbase + 1 > r1) s[nt][3] = -1e30f;
            }
        }

        // ---- online softmax ----
        float mx0 = -1e30f, mx1 = -1e30f;
#pragma unroll
        for (int nt = 0; nt < 8; nt++) {
            mx0 = fmaxf(mx0, fmaxf(s[nt][0], s[nt][1]));
            mx1 = fmaxf(mx1, fmaxf(s[nt][2], s[nt][3]));
        }
        mx0 = fmaxf(mx0, __shfl_xor_sync(0xffffffffu, mx0, 1));
        mx0 = fmaxf(mx0, __shfl_xor_sync(0xffffffffu, mx0, 2));
        mx1 = fmaxf(mx1, __shfl_xor_sync(0xffffffffu, mx1, 1));
        mx1 = fmaxf(mx1, __shfl_xor_sync(0xffffffffu, mx1, 2));
        float mn0 = fmaxf(m0r, mx0), mn1 = fmaxf(m1r, mx1);
        float al0 = fexp(m0r - mn0), al1 = fexp(m1r - mn1);
        float sum0 = 0.f, sum1 = 0.f;
#pragma unroll
        for (int nt = 0; nt < 8; nt++) {
            s[nt][0] = fexp(s[nt][0] - mn0);
            s[nt][1] = fexp(s[nt][1] - mn0);
            s[nt][2] = fexp(s[nt][2] - mn1);
            s[nt][3] = fexp(s[nt][3] - mn1);
            sum0 += s[nt][0] + s[nt][1];
            sum1 += s[nt][2] + s[nt][3];
        }
        sum0 += __shfl_xor_sync(0xffffffffu, sum0, 1);
        sum0 += __shfl_xor_sync(0xffffffffu, sum0, 2);
        sum1 += __shfl_xor_sync(0xffffffffu, sum1, 1);
        sum1 += __shfl_xor_sync(0xffffffffu, sum1, 2);
        l0r = l0r * al0 + sum0; m0r = mn0;
        l1r = l1r * al1 + sum1; m1r = mn1;
#pragma unroll
        for (int nt = 0; nt < 8; nt++) {
            o[nt][0] *= al0; o[nt][1] *= al0;
            o[nt][2] *= al1; o[nt][3] *= al1;
        }

        // ---- O += P V (3 split passes), V via ldmatrix.trans ----
#pragma unroll
        for (int kb = 0; kb < 4; kb++) {
            uint32_t ph[4], pl[4];
            split2(s[2 * kb][0],     s[2 * kb][1],     ph[0], pl[0]);
            split2(s[2 * kb][2],     s[2 * kb][3],     ph[1], pl[1]);
            split2(s[2 * kb + 1][0], s[2 * kb + 1][1], ph[2], pl[2]);
            split2(s[2 * kb + 1][2], s[2 * kb + 1][3], ph[3], pl[3]);
            uint32_t vfh[4][4], vfl[4][4];
            int vr = kb * 16 + qlo * 8 + lr;
            uint32_t vrow = (uint32_t)(vr * 128);
            uint32_t vsw  = (uint32_t)((vr & 7) * 16);
#pragma unroll
            for (int np = 0; np < 4; np++) {
                ldsm_x4_t(vfh[np], sVhi + vrow + (((uint32_t)(np * 32 + qhi * 16)) ^ vsw));
                ldsm_x4_t(vfl[np], sVlo + vrow + (((uint32_t)(np * 32 + qhi * 16)) ^ vsw));
            }
#pragma unroll
            for (int nt = 0; nt < 8; nt++)
                mma_bf16(o[nt], ph, &vfh[nt >> 1][(nt & 1) * 2]);
#pragma unroll
            for (int nt = 0; nt < 8; nt++)
                mma_bf16(o[nt], pl, &vfh[nt >> 1][(nt & 1) * 2]);
#pragma unroll
            for (int nt = 0; nt < 8; nt++)
                mma_bf16(o[nt], ph, &vfl[nt >> 1][(nt & 1) * 2]);
        }
        __syncthreads();
    }

    // ---- epilogue ----
    float inv0 = 1.f / l0r, inv1 = 1.f / l1r;
    int row0 = q0 + wid * 16 + g;
    int row1 = row0 + 8;
#pragma unroll
    for (int nt = 0; nt < 8; nt++) {
        int col = h * HDIM + nt * 8 + tg * 2;
        float v00 = o[nt][0] * inv0, v01 = o[nt][1] * inv0;
        float v10 = o[nt][2] * inv1, v11 = o[nt][3] * inv1;
        if (mode == 0) {
            *(float2*)(O + (size_t)row0 * DM + col) = make_float2(v00, v01);
            *(float2*)(O + (size_t)row1 * DM + col) = make_float2(v10, v11);
        } else {
            if (mode == 1) {
                float2 a0 = *(float2*)(O + (size_t)row0 * DM + col);
                float2 a1 = *(float2*)(O + (size_t)row1 * DM + col);
                v00 += a0.x; v01 += a0.y; v10 += a1.x; v11 += a1.y;
            }
            *(__half2*)(Oh + (size_t)row0 * DM + col) = __floats2half2_rn(v00, v01);
            *(__half2*)(Oh + (size_t)row1 * DM + col) = __floats2half2_rn(v10, v11);
        }
    }
}

// ---------------- host orchestration ----------------------------------------------
extern "C" void kernel_launch(void* const* d_in, const int* in_sizes, int n_in,
                              void* d_out, int out_size) {
    const float* x     = (const float*)d_in[0];
    const float* ctx   = (const float*)d_in[1];
    const float* qkv_w = (const float*)d_in[2];
    const float* qkv_b = (const float*)d_in[3];
    const float* out_w = (const float*)d_in[4];
    const float* out_b = (const float*)d_in[5];
    const float* w1    = (const float*)d_in[6];
    const float* w3    = (const float*)d_in[7];
    const float* w2    = (const float*)d_in[8];
    const float* n1g   = (const float*)d_in[9];
    const float* n1b   = (const float*)d_in[10];
    const float* n2g   = (const float*)d_in[11];
    const float* n2b   = (const float*)d_in[12];
    float* out = (float*)d_out;

    cudaFuncSetAttribute(mma_gemm_kernel, cudaFuncAttributeMaxDynamicSharedMemorySize, GEMM_SMEM);
    cudaFuncSetAttribute(attn_mma, cudaFuncAttributeMaxDynamicSharedMemorySize, ATTN_SMEM);

    void* p;
    cudaGetSymbolAddress(&p, g_qkv);    float* qkv    = (float*)p;
    cudaGetSymbolAddress(&p, g_attn);   float* attn   = (float*)p;
    cudaGetSymbolAddress(&p, g_h1);     float* h1     = (float*)p;
    cudaGetSymbolAddress(&p, g_gateup); float* gateup = (float*)p;
    cudaGetSymbolAddress(&p, g_act_h);  __half* ah    = (__half*)p;
    cudaGetSymbolAddress(&p, g_wqkv_h); __half* wqh = (__half*)p;
    cudaGetSymbolAddress(&p, g_wqkv_l); __half* wql = (__half*)p;
    cudaGetSymbolAddress(&p, g_wout_h); __half* woh = (__half*)p;
    cudaGetSymbolAddress(&p, g_wout_l); __half* wol = (__half*)p;
    cudaGetSymbolAddress(&p, g_w13_h);  __half* w13h = (__half*)p;
    cudaGetSymbolAddress(&p, g_w13_l);  __half* w13l = (__half*)p;
    cudaGetSymbolAddress(&p, g_w2_h);   __half* w2h = (__half*)p;
    cudaGetSymbolAddress(&p, g_w2_l);   __half* w2l = (__half*)p;
    cudaGetSymbolAddress(&p, g_qx_hi);  __nv_bfloat16* qxhi = (__nv_bfloat16*)p;
    cudaGetSymbolAddress(&p, g_qx_lo);  __nv_bfloat16* qxlo = (__nv_bfloat16*)p;
    cudaGetSymbolAddress(&p, g_kx_hi);  __nv_bfloat16* kxhi = (__nv_bfloat16*)p;
    cudaGetSymbolAddress(&p, g_kx_lo);  __nv_bfloat16* kxlo = (__nv_bfloat16*)p;
    cudaGetSymbolAddress(&p, g_kc_hi);  __nv_bfloat16* kchi = (__nv_bfloat16*)p;
    cudaGetSymbolAddress(&p, g_kc_lo);  __nv_bfloat16* kclo = (__nv_bfloat16*)p;
    cudaGetSymbolAddress(&p, g_qs_hi);  __nv_bfloat16* qshi = (__nv_bfloat16*)p;
    cudaGetSymbolAddress(&p, g_qs_lo);  __nv_bfloat16* qslo = (__nv_bfloat16*)p;
    cudaGetSymbolAddress(&p, g_v_hi);   __nv_bfloat16* vhi  = (__nv_bfloat16*)p;
    cudaGetSymbolAddress(&p, g_v_lo);   __nv_bfloat16* vlo  = (__nv_bfloat16*)p;

    dim3 tb(32, 8);
    build_rope_table<<<(MAXPOS * 32 + 255) / 256, 256>>>();

    // weight transpose + fp16 split (pre-scaled); w1,w3 packed [5632][1024]
    wt_split_f16_kernel<<<dim3(3 * DM / 32, DM / 32), tb>>>(qkv_w, wqh, wql, DM, 3 * DM);
    wt_split_f16_kernel<<<dim3(DM / 32, DM / 32),     tb>>>(out_w, woh, wol, DM, DM);
    wt_split_f16_kernel<<<dim3(HID / 32, DM / 32),    tb>>>(w1, w13h, w13l, DM, HID);
    wt_split_f16_kernel<<<dim3(HID / 32, DM / 32),    tb>>>(w3, w13h + (size_t)HID * DM,
                                                            w13l + (size_t)HID * DM, DM, HID);
    wt_split_f16_kernel<<<dim3(DM / 32, HID / 32),    tb>>>(w2, w2h, w2l, HID, DM);

    // LN1 -> fp16 A buffer [LTOT][DM]
    ln_f16_kernel<<<LXX, 256>>>(x,   ah,                    n1g, n1b);
    ln_f16_kernel<<<LCC, 256>>>(ctx, ah + (size_t)LXX * DM, n1g, n1b);

    // QKV projection (fp16 2-pass)
    mma_gemm_kernel<<<dim3(3 * DM / 128, LTOT / 128), 256, GEMM_SMEM>>>(
        ah, wqh, wql, qkv, qkv_b, nullptr, nullptr, 0, LTOT, 3 * DM, DM);

    // RoPE + bf16 split (q-side pre-scaled by 1/8), V split
    rope_split_kernel<<<(LXX * 512 + 255) / 256, 256>>>(qkv, 3 * DM, qxhi, qxlo, LXX, POS_X, 0.125f);
    rope_split_kernel<<<(LXX * 512 + 255) / 256, 256>>>(qkv + DM, 3 * DM, kxhi, kxlo, LXX, POS_X, 1.f);
    rope_split_kernel<<<(LCC * 512 + 255) / 256, 256>>>(qkv + (size_t)LXX * 3 * DM + DM, 3 * DM, kchi, kclo, LCC, POS_C, 1.f);
    rope_split_kernel<<<(2048 * 512 + 255) / 256, 256>>>(qkv + (size_t)(LXX + HWSP) * 3 * DM, 3 * DM, qshi, qslo, 2048, HWSP, 0.125f);
    v_split_kernel<<<(LTOT * 512 + 255) / 256, 256>>>(qkv, vhi, vlo);

    const size_t vcoff = (size_t)LXX * DM;

    // a1 (mode 0: fp32 staging) ; a2 (mode 1: +a1, fp16 out) ; a3 (mode 2: fp16 out)
    attn_mma<<<dim3(LXX / 64, NH), 128, ATTN_SMEM>>>(qxhi, qxlo, kchi, kclo,
        vhi + vcoff, vlo + vcoff, attn, nullptr, LCC, 0, 0);
    attn_mma<<<dim3(LXX / 64, NH), 128, ATTN_SMEM>>>(qxhi, qxlo, kxhi, kxlo,
        vhi, vlo, attn, ah, LXX, 1, 1);
    attn_mma<<<dim3(2048 / 64, NH), 128, ATTN_SMEM>>>(qshi, qslo, kchi, kclo,
        vhi + vcoff, vlo + vcoff, nullptr, ah + (size_t)2048 * DM, LCC, 0, 2);

    // out projection + bias + residual
    mma_gemm_kernel<<<dim3(DM / 128, LOUT / 128), 256, GEMM_SMEM>>>(
        ah, woh, wol, h1, out_b, x, ctx, 2048, LOUT, DM, DM);

    // LN2 -> fp16
    ln_f16_kernel<<<LOUT, 256>>>(h1, ah, n2g, n2b);

    // FFN: combined w1|w3 GEMM -> gateup, fused silu*mul -> fp16, w2 GEMM
    mma_gemm_kernel<<<dim3(2 * HID / 128, LOUT / 128), 256, GEMM_SMEM>>>(
        ah, w13h, w13l, gateup, nullptr, nullptr, nullptr, 0, LOUT, 2 * HID, DM);
    silu_mul_f16_kernel<<<dim3(HID / 256, LOUT), 256>>>(gateup, ah);
    mma_gemm_kernel<<<dim3(DM / 128, LOUT / 128), 256, GEMM_SMEM>>>(
        ah, w2h, w2l, out, nullptr, h1, h1, LOUT, LOUT, DM, HID);
}

// round 8
// speedup vs baseline: 4.3489x; 1.2753x over previous
#include <cuda_runtime.h>
#include <cuda_bf16.h>
#include <cuda_fp16.h>
#include <math.h>
#include <stdint.h>

// ---------------- problem constants (from setup_inputs, deterministic) ----------
#define LXX     2048
#define LCC     4096
#define DM      1024
#define NH      16
#define HDIM    64
#define HID     2816
#define LTOT    6144
#define LOUT    4096
#define POS_X   4096
#define POS_C   0
#define HWSP    2048
#define MAXPOS  6144

#define WSCALE     64.0f
#define WSCALE_INV 0.015625f
#define KSCALE     16.0f
#define QSCALE     (0.125f / 16.0f)
#define VSCALE     64.0f
#define VSCALE_INV 0.015625f

// ---------------- scratch (device globals; no runtime allocation) ---------------
__device__ float g_qkv   [LTOT * 3 * DM];
__device__ float g_attn  [LXX * DM];          // a1 fp32 staging
__device__ float g_h1    [LOUT * DM];
__device__ float g_gateup[LOUT * 2 * HID];
__device__ float g_cos   [MAXPOS * 32];
__device__ float g_sin   [MAXPOS * 32];

// fp16 single-precision activation buffer (A operand of all weight GEMMs)
__device__ __half g_act_h[LOUT * HID];
// fp16 split weights [N][K], pre-scaled by WSCALE
__device__ __half g_wqkv_h[3 * DM * DM], g_wqkv_l[3 * DM * DM];
__device__ __half g_wout_h[DM * DM],     g_wout_l[DM * DM];
__device__ __half g_w13_h[2 * HID * DM], g_w13_l[2 * HID * DM];
__device__ __half g_w2_h [DM * HID],     g_w2_l [DM * HID];

// fp16 attention operands: Q single (pre-scaled), K hi/lo (x16), V hi/lo (x64)
__device__ __half g_qx  [LXX * DM];
__device__ __half g_qs  [2048 * DM];
__device__ __half g_kx_h[LXX * DM],  g_kx_l[LXX * DM];
__device__ __half g_kc_h[LCC * DM],  g_kc_l[LCC * DM];
__device__ __half g_v_h [LTOT * DM], g_v_l [LTOT * DM];

// ---------------- helpers (portable: sm_80+ PTX) ----------------------------------
__device__ __forceinline__ uint32_t smem_to_u32(const void* p) {
    uint32_t a;
    asm("{ .reg .u64 t; cvta.to.shared.u64 t, %1; cvt.u32.u64 %0, t; }" : "=r"(a) : "l"(p));
    return a;
}
#define SMEM_SWIZZLE_128B(b) ((b) ^ (((b) >> 3) & 0x70))

__device__ __forceinline__ void cp16(uint32_t s, const void* g) {
    asm volatile("cp.async.cg.shared.global [%0], [%1], 16;" :: "r"(s), "l"(g) : "memory");
}
__device__ __forceinline__ void cp_commit() {
    asm volatile("cp.async.commit_group;" ::: "memory");
}
template<int N> __device__ __forceinline__ void cp_wait() {
    asm volatile("cp.async.wait_group %0;" :: "n"(N) : "memory");
}

__device__ __forceinline__ void ldsm_x4(uint32_t* r, uint32_t addr) {
    asm volatile("ldmatrix.sync.aligned.m8n8.x4.shared.b16 {%0,%1,%2,%3}, [%4];"
        : "=r"(r[0]), "=r"(r[1]), "=r"(r[2]), "=r"(r[3]) : "r"(addr));
}
__device__ __forceinline__ void ldsm_x4_t(uint32_t* r, uint32_t addr) {
    asm volatile("ldmatrix.sync.aligned.m8n8.x4.trans.shared.b16 {%0,%1,%2,%3}, [%4];"
        : "=r"(r[0]), "=r"(r[1]), "=r"(r[2]), "=r"(r[3]) : "r"(addr));
}
__device__ __forceinline__ void mma_f16(float* c, const uint32_t* a, const uint32_t* b) {
    asm volatile("mma.sync.aligned.m16n8k16.row.col.f32.f16.f16.f32 "
        "{%0,%1,%2,%3}, {%4,%5,%6,%7}, {%8,%9}, {%0,%1,%2,%3};"
        : "+f"(c[0]), "+f"(c[1]), "+f"(c[2]), "+f"(c[3])
        : "r"(a[0]), "r"(a[1]), "r"(a[2]), "r"(a[3]), "r"(b[0]), "r"(b[1]));
}

// fast exp on FMA pipe (x <= 0), rel err ~2e-6
__device__ __forceinline__ float fexp(float x) {
    x = fmaxf(x, -87.0f);
    float t = x * 1.4426950408889634f;
    float r = t + 12582912.0f;
    float n = r - 12582912.0f;
    float f = t - n;
    float p = 0.0013298820f;
    p = fmaf(p, f, 0.0096181291f);
    p = fmaf(p, f, 0.0555041087f);
    p = fmaf(p, f, 0.2402265069f);
    p = fmaf(p, f, 0.6931471806f);
    p = fmaf(p, f, 1.0f);
    int ni = (int)n;
    return p * __int_as_float((ni + 127) << 23);
}

// ---------------- rope cos/sin table (fp64 angles) -------------------------------
__global__ void build_rope_table() {
    int idx = blockIdx.x * blockDim.x + threadIdx.x;
    if (idx >= MAXPOS * 32) return;
    int pos = idx >> 5, j = idx & 31;
    double inv = pow(10000.0, -((double)(2 * j)) / 64.0);
    double ang = (double)pos * inv;
    g_cos[idx] = (float)cos(ang);
    g_sin[idx] = (float)sin(ang);
}

// ---------------- LayerNorm fused with fp16 output ---------------------------------
__global__ void ln_f16_kernel(const float* __restrict__ in,
                              __half* __restrict__ out,
                              const float* __restrict__ gam,
                              const float* __restrict__ bet) {
    __shared__ float sh[32];
    __shared__ float s_mean, s_rstd;
    int row = blockIdx.x, t = threadIdx.x;
    const float* x = in + (size_t)row * DM;
    float v[4];
    float s = 0.f;
#pragma unroll
    for (int i = 0; i < 4; i++) { v[i] = x[t + 256 * i]; s += v[i]; }
#pragma unroll
    for (int o = 16; o; o >>= 1) s += __shfl_xor_sync(0xffffffffu, s, o);
    if ((t & 31) == 0) sh[t >> 5] = s;
    __syncthreads();
    if (t < 32) {
        float z = (t < 8) ? sh[t] : 0.f;
#pragma unroll
        for (int o = 4; o; o >>= 1) z += __shfl_xor_sync(0xffffffffu, z, o);
        if (t == 0) s_mean = z * (1.f / 1024.f);
    }
    __syncthreads();
    float mean = s_mean;
    float q = 0.f;
#pragma unroll
    for (int i = 0; i < 4; i++) { float d = v[i] - mean; q += d * d; }
#pragma unroll
    for (int o = 16; o; o >>= 1) q += __shfl_xor_sync(0xffffffffu, q, o);
    if ((t & 31) == 0) sh[t >> 5] = q;
    __syncthreads();
    if (t < 32) {
        float z = (t < 8) ? sh[t] : 0.f;
#pragma unroll
        for (int o = 4; o; o >>= 1) z += __shfl_xor_sync(0xffffffffu, z, o);
        if (t == 0) s_rstd = rsqrtf(z * (1.f / 1024.f) + 1e-5f);
    }
    __syncthreads();
    float rstd = s_rstd;
#pragma unroll
    for (int i = 0; i < 4; i++) {
        int c = t + 256 * i;
        float r = (v[i] - mean) * rstd * gam[c] + bet[c];
        out[(size_t)row * DM + c] = __float2half(r);
    }
}

// ---------------- RoPE -> single fp16 (Q paths) -------------------------------------
__global__ void rope_f16_kernel(const float* __restrict__ src, int lds,
                                __half* __restrict__ out,
                                int L, int pos0, float scale) {
    int idx = blockIdx.x * blockDim.x + threadIdx.x;
    if (idx >= L * 512) return;
    int j = idx & 31, h = (idx >> 5) & 15, l = idx >> 9;
    int pos = pos0 + l;
    float c = g_cos[pos * 32 + j], s = g_sin[pos * 32 + j];
    const float* p = src + (size_t)l * lds + h * HDIM;
    float t1 = p[j], t2 = p[j + 32];
    size_t o = (size_t)l * DM + h * HDIM;
    out[o + j]      = __float2half((t1 * c - t2 * s) * scale);
    out[o + j + 32] = __float2half((t2 * c + t1 * s) * scale);
}

// ---------------- RoPE -> split fp16 hi/lo (K paths, pre-scaled) --------------------
__global__ void rope_split_f16_kernel(const float* __restrict__ src, int lds,
                                      __half* __restrict__ hi,
                                      __half* __restrict__ lo,
                                      int L, int pos0, float scale) {
    int idx = blockIdx.x * blockDim.x + threadIdx.x;
    if (idx >= L * 512) return;
    int j = idx & 31, h = (idx >> 5) & 15, l = idx >> 9;
    int pos = pos0 + l;
    float c = g_cos[pos * 32 + j], s = g_sin[pos * 32 + j];
    const float* p = src + (size_t)l * lds + h * HDIM;
    float t1 = p[j], t2 = p[j + 32];
    float r1 = (t1 * c - t2 * s) * scale;
    float r2 = (t2 * c + t1 * s) * scale;
    size_t o = (size_t)l * DM + h * HDIM;
    __half h1 = __float2half(r1);
    __half h2 = __float2half(r2);
    hi[o + j]      = h1;
    hi[o + j + 32] = h2;
    lo[o + j]      = __float2half(r1 - __half2float(h1));
    lo[o + j + 32] = __float2half(r2 - __half2float(h2));
}

// ---------------- V split: strided fp32 -> contiguous fp16 hi/lo (x VSCALE) --------
__global__ void v_split_kernel(const float* __restrict__ qkv,
                               __half* __restrict__ hi,
                               __half* __restrict__ lo) {
    int i = blockIdx.x * blockDim.x + threadIdx.x;
    if (i >= LTOT * 512) return;
    int r = i >> 9, c2 = i & 511;
    float2 v = *(const float2*)(qkv + (size_t)r * 3 * DM + 2 * DM + c2 * 2);
    v.x *= VSCALE; v.y *= VSCALE;
    __half hx = __float2half(v.x), hy = __float2half(v.y);
    __half2 h(hx, hy);
    __half2 l(__float2half(v.x - __half2float(hx)),
              __float2half(v.y - __half2float(hy)));
    ((__half2*)hi)[(size_t)r * 512 + c2] = h;
    ((__half2*)lo)[(size_t)r * 512 + c2] = l;
}

// ---------------- weight transpose + fp16 split (pre-scaled by WSCALE) ------------
__global__ void wt_split_f16_kernel(const float* __restrict__ w,
                                    __half* __restrict__ hi,
                                    __half* __restrict__ lo, int K, int N) {
    __shared__ float t[32][33];
    int n0 = blockIdx.x * 32, k0 = blockIdx.y * 32;
    int tx = threadIdx.x, ty = threadIdx.y;
#pragma unroll
    for (int i = 0; i < 32; i += 8)
        t[ty + i][tx] = w[(size_t)(k0 + ty + i) * N + n0 + tx];
    __syncthreads();
#pragma unroll
    for (int i = 0; i < 32; i += 8) {
        int n = n0 + ty + i, k = k0 + tx;
        float v = t[tx][ty + i] * WSCALE;
        __half h = __float2half(v);
        hi[(size_t)n * K + k] = h;
        lo[(size_t)n * K + k] = __float2half(v - __half2float(h));
    }
}

// ---------------- silu(g)*u fused with fp16 output ---------------------------------
__global__ void silu_mul_f16_kernel(const float* __restrict__ gu,
                                    __half* __restrict__ out) {
    int col = blockIdx.x * 256 + threadIdx.x;
    int row = blockIdx.y;
    float g = gu[(size_t)row * (2 * HID) + col];
    float u = gu[(size_t)row * (2 * HID) + HID + col];
    float r = (g / (1.f + __expf(-g))) * u;
    out[(size_t)row * HID + col] = __float2half(r);
}

// ---------------- fp16 2-pass GEMM, cp.async 2-stage pipeline ----------------------
static const int GEMM_SMEM = 2 * 3 * 16384;   // 98304

__global__ void __launch_bounds__(256, 2)
mma_gemm_kernel(const __half* __restrict__ A,
                const __half* __restrict__ Bh, const __half* __restrict__ Bl,
                float* __restrict__ C, const float* __restrict__ bias,
                const float* __restrict__ res0, const float* __restrict__ res1, int split,
                int M, int N, int K) {
    extern __shared__ char smem[];
    uint32_t sbase = smem_to_u32(smem);

    int tid = threadIdx.x;
    int wid = tid >> 5, lane = tid & 31;
    int wr = wid >> 2, wc = wid & 3;
    int m0 = blockIdx.y * 128, n0 = blockIdx.x * 128;

    int lr  = lane & 7;
    int lq  = lane >> 3;
    int qlo = lq & 1, qhi = lq >> 1;

    uint32_t aoff[4];
#pragma unroll
    for (int mt = 0; mt < 4; mt++) {
        int row = wr * 64 + mt * 16 + qlo * 8 + lr;
        aoff[mt] = (uint32_t)(row * 128) + (uint32_t)((qhi * 16) ^ ((row & 7) * 16));
    }
    uint32_t boff[2];
#pragma unroll
    for (int np = 0; np < 2; np++) {
        int row = wc * 32 + np * 16 + qhi * 8 + lr;
        boff[np] = (uint32_t)(row * 128) + (uint32_t)((qlo * 16) ^ ((row & 7) * 16));
    }

    auto issue = [&](int st, int kc0) {
        uint32_t base = sbase + (uint32_t)st * 49152;
#pragma unroll
        for (int it = 0; it < 4; it++) {
            int idx = tid + it * 256;
            int r = idx >> 3, q = idx & 7;
            uint32_t so = SMEM_SWIZZLE_128B((uint32_t)(r * 128 + q * 16));
            cp16(base + so,         A  + (size_t)(m0 + r) * K + kc0 + q * 8);
            cp16(base + 16384 + so, Bh + (size_t)(n0 + r) * K + kc0 + q * 8);
            cp16(base + 32768 + so, Bl + (size_t)(n0 + r) * K + kc0 + q * 8);
        }
        cp_commit();
    };

    float acc[4][4][4] = {};
    int nchunks = K >> 6;

    issue(0, 0);
    for (int kc = 0; kc < nchunks; kc++) {
        int st = kc & 1;
        if (kc + 1 < nchunks) { issue(st ^ 1, (kc + 1) << 6); cp_wait<1>(); }
        else                  { cp_wait<0>(); }
        __syncthreads();

        uint32_t sA  = sbase + (uint32_t)st * 49152;
        uint32_t sBh = sA + 16384;
        uint32_t sBl = sBh + 16384;

#pragma unroll
        for (int ks = 0; ks < 4; ks++) {
            uint32_t kx = (uint32_t)(ks << 5);
            uint32_t bh[2][4], bl[2][4];
#pragma unroll
            for (int np = 0; np < 2; np++) {
                ldsm_x4(bh[np], sBh + (boff[np] ^ kx));
                ldsm_x4(bl[np], sBl + (boff[np] ^ kx));
            }
#pragma unroll
            for (int mt = 0; mt < 4; mt++) {
                uint32_t ah[4];
                ldsm_x4(ah, sA + (aoff[mt] ^ kx));
#pragma unroll
                for (int nt = 0; nt < 4; nt++)
                    mma_f16(acc[mt][nt], ah, &bh[nt >> 1][(nt & 1) * 2]);
#pragma unroll
                for (int nt = 0; nt < 4; nt++)
                    mma_f16(acc[mt][nt], ah, &bl[nt >> 1][(nt & 1) * 2]);
            }
        }
        __syncthreads();
    }

    int g = lane >> 2, tg = lane & 3;
#pragma unroll
    for (int mt = 0; mt < 4; mt++) {
#pragma unroll
        for (int half = 0; half < 2; half++) {
            int row = m0 + wr * 64 + mt * 16 + g + half * 8;
            const float* rp = nullptr;
            if (res0) rp = ((row < split) ? res0 : res1) + (size_t)row * N;
            float* cp = C + (size_t)row * N;
#pragma unroll
            for (int nt = 0; nt < 4; nt++) {
                int col = n0 + wc * 32 + nt * 8 + tg * 2;
                float2 v;
                v.x = acc[mt][nt][half * 2 + 0] * WSCALE_INV;
                v.y = acc[mt][nt][half * 2 + 1] * WSCALE_INV;
                if (bias) { v.x += bias[col]; v.y += bias[col + 1]; }
                if (rp)   { v.x += rp[col];   v.y += rp[col + 1]; }
                *(float2*)(cp + col) = v;
            }
        }
    }
}

// ---------------- fp16 asymmetric flash attention, cp.async 2-stage ----------------
// Q single fp16 (pre-scaled QSCALE), K fp16 hi/lo (xKSCALE), V fp16 hi/lo (xVSCALE).
// S: 2 passes; PV: 2 passes. mode 0: fp32 O; 1: +fp32 O -> fp16; 2: -> fp16.
static const int ATTN_SMEM = 2 * 4 * 8192;    // 65536

__global__ void __launch_bounds__(128)
attn_mma(const __half* __restrict__ Q,
         const __half* __restrict__ Khi, const __half* __restrict__ Klo,
         const __half* __restrict__ Vhi, const __half* __restrict__ Vlo,
         float* __restrict__ O, __half* __restrict__ Oh,
         int LK, int causal, int mode) {
    extern __shared__ char smema[];
    uint32_t sb = smem_to_u32(smema);

    int tid = threadIdx.x;
    int wid = tid >> 5, lane = tid & 31;
    int g = lane >> 2, tg = lane & 3;
    int lr = lane & 7, qlo = (lane >> 3) & 1, qhi = lane >> 4;
    int q0 = blockIdx.x * 64;
    int h  = blockIdx.y;

    // ---- stage Q (single fp16), extract fragments ----
#pragma unroll
    for (int it = 0; it < 4; it++) {
        int e = tid + it * 128;           // 0..511
        int row = e >> 3, q = e & 7;
        uint32_t off = (uint32_t)(row * 128) + (uint32_t)((q * 16) ^ ((row & 7) * 16));
        *(uint4*)(smema + off) = *(const uint4*)(Q + (size_t)(q0 + row) * DM + h * HDIM + q * 8);
    }
    __syncthreads();
    uint32_t qf[4][4];
    {
        int arow = wid * 16 + qlo * 8 + lr;
        uint32_t abase = (uint32_t)(arow * 128) + (uint32_t)((qhi * 16) ^ ((arow & 7) * 16));
#pragma unroll
        for (int ks = 0; ks < 4; ks++)
            ldsm_x4(qf[ks], sb + (abase ^ (uint32_t)(ks << 5)));
    }
    __syncthreads();

    auto issue = [&](int st, int k0) {
        uint32_t base = sb + (uint32_t)st * 32768;
#pragma unroll
        for (int it = 0; it < 4; it++) {
            int e = tid + it * 128;
            int row = e >> 3, q = e & 7;
            uint32_t off = (uint32_t)(row * 128) + (uint32_t)((q * 16) ^ ((row & 7) * 16));
            size_t gidx = (size_t)(k0 + row) * DM + h * HDIM + q * 8;
            cp16(base + off,         Khi + gidx);
            cp16(base + 8192 + off,  Klo + gidx);
            cp16(base + 16384 + off, Vhi + gidx);
            cp16(base + 24576 + off, Vlo + gidx);
        }
        cp_commit();
    };

    float o[8][4] = {};
    float m0r = -1e30f, m1r = -1e30f, l0r = 0.f, l1r = 0.f;

    int ntiles = causal ? ((int)blockIdx.x + 1) : (LK >> 6);
    issue(0, 0);
    for (int kt = 0; kt < ntiles; kt++) {
        int k0 = kt << 6;
        int st = kt & 1;
        if (kt + 1 < ntiles) { issue(st ^ 1, (kt + 1) << 6); cp_wait<1>(); }
        else                 { cp_wait<0>(); }
        __syncthreads();

        uint32_t sKhi = sb + (uint32_t)st * 32768;
        uint32_t sKlo = sKhi + 8192;
        uint32_t sVhi = sKlo + 8192;
        uint32_t sVlo = sVhi + 8192;

        // ---- S = Q (Khi + Klo)^T : 2 passes ----
        float s[8][4] = {};
#pragma unroll
        for (int ks = 0; ks < 4; ks++) {
            uint32_t kx = (uint32_t)(ks << 5);
            uint32_t bh[4][4], bl[4][4];
#pragma unroll
            for (int np = 0; np < 4; np++) {
                int br = np * 16 + qhi * 8 + lr;
                uint32_t boff = (uint32_t)(br * 128) +
                                (uint32_t)(((qlo * 16) ^ (int)kx) ^ ((br & 7) * 16));
                ldsm_x4(bh[np], sKhi + boff);
                ldsm_x4(bl[np], sKlo + boff);
            }
#pragma unroll
            for (int nt = 0; nt < 8; nt++)
                mma_f16(s[nt], qf[ks], &bh[nt >> 1][(nt & 1) * 2]);
#pragma unroll
            for (int nt = 0; nt < 8; nt++)
                mma_f16(s[nt], qf[ks], &bl[nt >> 1][(nt & 1) * 2]);
        }

        // ---- causal mask (diagonal tile only) ----
        if (causal && kt == (int)blockIdx.x) {
            int r0 = q0 + wid * 16 + g, r1 = r0 + 8;
#pragma unroll
            for (int nt = 0; nt < 8; nt++) {
                int kbase = k0 + nt * 8 + tg * 2;
                if (kbase > r0)     s[nt][0] = -1e30f;
                if (kbase + 1 > r0) s[nt][1] = -1e30f;
                if (kbase > r1)     s[nt][2] = -1e30f;
                if (kbase + 1 > r1) s[nt][3] = -1e30f;
            }
        }

        // ---- online softmax ----
        float mx0 = -1e30f, mx1 = -1e30f;
#pragma unroll
        for (int nt = 0; nt < 8; nt++) {
            mx0 = fmaxf(mx0, fmaxf(s[nt][0], s[nt][1]));
            mx1 = fmaxf(mx1, fmaxf(s[nt][2], s[nt][3]));
        }
        mx0 = fmaxf(mx0, __shfl_xor_sync(0xffffffffu, mx0, 1));
        mx0 = fmaxf(mx0, __shfl_xor_sync(0xffffffffu, mx0, 2));
        mx1 = fmaxf(mx1, __shfl_xor_sync(0xffffffffu, mx1, 1));
        mx1 = fmaxf(mx1, __shfl_xor_sync(0xffffffffu, mx1, 2));
        float mn0 = fmaxf(m0r, mx0), mn1 = fmaxf(m1r, mx1);
        float al0 = fexp(m0r - mn0), al1 = fexp(m1r - mn1);
        float sum0 = 0.f, sum1 = 0.f;
#pragma unroll
        for (int nt = 0; nt < 8; nt++) {
            s[nt][0] = fexp(s[nt][0] - mn0);
            s[nt][1] = fexp(s[nt][1] - mn0);
            s[nt][2] = fexp(s[nt][2] - mn1);
            s[nt][3] = fexp(s[nt][3] - mn1);
            sum0 += s[nt][0] + s[nt][1];
            sum1 += s[nt][2] + s[nt][3];
        }
        sum0 += __shfl_xor_sync(0xffffffffu, sum0, 1);
        sum0 += __shfl_xor_sync(0xffffffffu, sum0, 2);
        sum1 += __shfl_xor_sync(0xffffffffu, sum1, 1);
        sum1 += __shfl_xor_sync(0xffffffffu, sum1, 2);
        l0r = l0r * al0 + sum0; m0r = mn0;
        l1r = l1r * al1 + sum1; m1r = mn1;
#pragma unroll
        for (int nt = 0; nt < 8; nt++) {
            o[nt][0] *= al0; o[nt][1] *= al0;
            o[nt][2] *= al1; o[nt][3] *= al1;
        }

        // ---- O += P (Vhi + Vlo) : 2 passes, P single fp16 ----
#pragma unroll
        for (int kb = 0; kb < 4; kb++) {
            uint32_t ph[4];
            {
                __half2 p0 = __floats2half2_rn(s[2 * kb][0],     s[2 * kb][1]);
                __half2 p1 = __floats2half2_rn(s[2 * kb][2],     s[2 * kb][3]);
                __half2 p2 = __floats2half2_rn(s[2 * kb + 1][0], s[2 * kb + 1][1]);
                __half2 p3 = __floats2half2_rn(s[2 * kb + 1][2], s[2 * kb + 1][3]);
                ph[0] = *(uint32_t*)&p0; ph[1] = *(uint32_t*)&p1;
                ph[2] = *(uint32_t*)&p2; ph[3] = *(uint32_t*)&p3;
            }
            uint32_t vfh[4][4], vfl[4][4];
            int vr = kb * 16 + qlo * 8 + lr;
            uint32_t vrow = (uint32_t)(vr * 128);
            uint32_t vsw  = (uint32_t)((vr & 7) * 16);
#pragma unroll
            for (int np = 0; np < 4; np++) {
                ldsm_x4_t(vfh[np], sVhi + vrow + (((uint32_t)(np * 32 + qhi * 16)) ^ vsw));
                ldsm_x4_t(vfl[np], sVlo + vrow + (((uint32_t)(np * 32 + qhi * 16)) ^ vsw));
            }
#pragma unroll
            for (int nt = 0; nt < 8; nt++)
                mma_f16(o[nt], ph, &vfh[nt >> 1][(nt & 1) * 2]);
#pragma unroll
            for (int nt = 0; nt < 8; nt++)
                mma_f16(o[nt], ph, &vfl[nt >> 1][(nt & 1) * 2]);
        }
        __syncthreads();
    }

    // ---- epilogue (unscale V) ----
    float inv0 = VSCALE_INV / l0r, inv1 = VSCALE_INV / l1r;
    int row0 = q0 + wid * 16 + g;
    int row1 = row0 + 8;
#pragma unroll
    for (int nt = 0; nt < 8; nt++) {
        int col = h * HDIM + nt * 8 + tg * 2;
        float v00 = o[nt][0] * inv0, v01 = o[nt][1] * inv0;
        float v10 = o[nt][2] * inv1, v11 = o[nt][3] * inv1;
        if (mode == 0) {
            *(float2*)(O + (size_t)row0 * DM + col) = make_float2(v00, v01);
            *(float2*)(O + (size_t)row1 * DM + col) = make_float2(v10, v11);
        } else {
            if (mode == 1) {
                float2 a0 = *(float2*)(O + (size_t)row0 * DM + col);
                float2 a1 = *(float2*)(O + (size_t)row1 * DM + col);
                v00 += a0.x; v01 += a0.y; v10 += a1.x; v11 += a1.y;
            }
            *(__half2*)(Oh + (size_t)row0 * DM + col) = __floats2half2_rn(v00, v01);
            *(__half2*)(Oh + (size_t)row1 * DM + col) = __floats2half2_rn(v10, v11);
        }
    }
}

// ---------------- host orchestration ----------------------------------------------
extern "C" void kernel_launch(void* const* d_in, const int* in_sizes, int n_in,
                              void* d_out, int out_size) {
    const float* x     = (const float*)d_in[0];
    const float* ctx   = (const float*)d_in[1];
    const float* qkv_w = (const float*)d_in[2];
    const float* qkv_b = (const float*)d_in[3];
    const float* out_w = (const float*)d_in[4];
    const float* out_b = (const float*)d_in[5];
    const float* w1    = (const float*)d_in[6];
    const float* w3    = (const float*)d_in[7];
    const float* w2    = (const float*)d_in[8];
    const float* n1g   = (const float*)d_in[9];
    const float* n1b   = (const float*)d_in[10];
    const float* n2g   = (const float*)d_in[11];
    const float* n2b   = (const float*)d_in[12];
    float* out = (float*)d_out;

    cudaFuncSetAttribute(mma_gemm_kernel, cudaFuncAttributeMaxDynamicSharedMemorySize, GEMM_SMEM);
    cudaFuncSetAttribute(attn_mma, cudaFuncAttributeMaxDynamicSharedMemorySize, ATTN_SMEM);

    void* p;
    cudaGetSymbolAddress(&p, g_qkv);    float* qkv    = (float*)p;
    cudaGetSymbolAddress(&p, g_attn);   float* attn   = (float*)p;
    cudaGetSymbolAddress(&p, g_h1);     float* h1     = (float*)p;
    cudaGetSymbolAddress(&p, g_gateup); float* gateup = (float*)p;
    cudaGetSymbolAddress(&p, g_act_h);  __half* ah    = (__half*)p;
    cudaGetSymbolAddress(&p, g_wqkv_h); __half* wqh = (__half*)p;
    cudaGetSymbolAddress(&p, g_wqkv_l); __half* wql = (__half*)p;
    cudaGetSymbolAddress(&p, g_wout_h); __half* woh = (__half*)p;
    cudaGetSymbolAddress(&p, g_wout_l); __half* wol = (__half*)p;
    cudaGetSymbolAddress(&p, g_w13_h);  __half* w13h = (__half*)p;
    cudaGetSymbolAddress(&p, g_w13_l);  __half* w13l = (__half*)p;
    cudaGetSymbolAddress(&p, g_w2_h);   __half* w2h = (__half*)p;
    cudaGetSymbolAddress(&p, g_w2_l);   __half* w2l = (__half*)p;
    cudaGetSymbolAddress(&p, g_qx);     __half* qx  = (__half*)p;
    cudaGetSymbolAddress(&p, g_qs);     __half* qs  = (__half*)p;
    cudaGetSymbolAddress(&p, g_kx_h);   __half* kxh = (__half*)p;
    cudaGetSymbolAddress(&p, g_kx_l);   __half* kxl = (__half*)p;
    cudaGetSymbolAddress(&p, g_kc_h);   __half* kch = (__half*)p;
    cudaGetSymbolAddress(&p, g_kc_l);   __half* kcl = (__half*)p;
    cudaGetSymbolAddress(&p, g_v_h);    __half* vh  = (__half*)p;
    cudaGetSymbolAddress(&p, g_v_l);    __half* vl  = (__half*)p;

    dim3 tb(32, 8);
    build_rope_table<<<(MAXPOS * 32 + 255) / 256, 256>>>();

    // weight transpose + fp16 split (pre-scaled); w1,w3 packed [5632][1024]
    wt_split_f16_kernel<<<dim3(3 * DM / 32, DM / 32), tb>>>(qkv_w, wqh, wql, DM, 3 * DM);
    wt_split_f16_kernel<<<dim3(DM / 32, DM / 32),     tb>>>(out_w, woh, wol, DM, DM);
    wt_split_f16_kernel<<<dim3(HID / 32, DM / 32),    tb>>>(w1, w13h, w13l, DM, HID);
    wt_split_f16_kernel<<<dim3(HID / 32, DM / 32),    tb>>>(w3, w13h + (size_t)HID * DM,
                                                            w13l + (size_t)HID * DM, DM, HID);
    wt_split_f16_kernel<<<dim3(DM / 32, HID / 32),    tb>>>(w2, w2h, w2l, HID, DM);

    // LN1 -> fp16 A buffer [LTOT][DM]
    ln_f16_kernel<<<LXX, 256>>>(x,   ah,                    n1g, n1b);
    ln_f16_kernel<<<LCC, 256>>>(ctx, ah + (size_t)LXX * DM, n1g, n1b);

    // QKV projection (fp16 2-pass)
    mma_gemm_kernel<<<dim3(3 * DM / 128, LTOT / 128), 256, GEMM_SMEM>>>(
        ah, wqh, wql, qkv, qkv_b, nullptr, nullptr, 0, LTOT, 3 * DM, DM);

    // RoPE: Q single fp16 (QSCALE), K split fp16 (KSCALE); V split (VSCALE)
    rope_f16_kernel<<<(LXX * 512 + 255) / 256, 256>>>(qkv, 3 * DM, qx, LXX, POS_X, QSCALE);
    rope_f16_kernel<<<(2048 * 512 + 255) / 256, 256>>>(qkv + (size_t)(LXX + HWSP) * 3 * DM, 3 * DM, qs, 2048, HWSP, QSCALE);
    rope_split_f16_kernel<<<(LXX * 512 + 255) / 256, 256>>>(qkv + DM, 3 * DM, kxh, kxl, LXX, POS_X, KSCALE);
    rope_split_f16_kernel<<<(LCC * 512 + 255) / 256, 256>>>(qkv + (size_t)LXX * 3 * DM + DM, 3 * DM, kch, kcl, LCC, POS_C, KSCALE);
    v_split_kernel<<<(LTOT * 512 + 255) / 256, 256>>>(qkv, vh, vl);

    const size_t vcoff = (size_t)LXX * DM;

    // a1 (mode 0: fp32 staging) ; a2 (mode 1: +a1, fp16 out) ; a3 (mode 2: fp16 out)
    attn_mma<<<dim3(LXX / 64, NH), 128, ATTN_SMEM>>>(qx, kch, kcl,
        vh + vcoff, vl + vcoff, attn, nullptr, LCC, 0, 0);
    attn_mma<<<dim3(LXX / 64, NH), 128, ATTN_SMEM>>>(qx, kxh, kxl,
        vh, vl, attn, ah, LXX, 1, 1);
    attn_mma<<<dim3(2048 / 64, NH), 128, ATTN_SMEM>>>(qs, kch, kcl,
        vh + vcoff, vl + vcoff, nullptr, ah + (size_t)2048 * DM, LCC, 0, 2);

    // out projection + bias + residual
    mma_gemm_kernel<<<dim3(DM / 128, LOUT / 128), 256, GEMM_SMEM>>>(
        ah, woh, wol, h1, out_b, x, ctx, 2048, LOUT, DM, DM);

    // LN2 -> fp16
    ln_f16_kernel<<<LOUT, 256>>>(h1, ah, n2g, n2b);

    // FFN: combined w1|w3 GEMM -> gateup, fused silu*mul -> fp16, w2 GEMM
    mma_gemm_kernel<<<dim3(2 * HID / 128, LOUT / 128), 256, GEMM_SMEM>>>(
        ah, w13h, w13l, gateup, nullptr, nullptr, nullptr, 0, LOUT, 2 * HID, DM);
    silu_mul_f16_kernel<<<dim3(HID / 256, LOUT), 256>>>(gateup, ah);
    mma_gemm_kernel<<<dim3(DM / 128, LOUT / 128), 256, GEMM_SMEM>>>(
        ah, w2h, w2l, out, nullptr, h1, h1, LOUT, LOUT, DM, HID);
}

// round 9
// speedup vs baseline: 6.3913x; 1.4696x over previous
#include <cuda_runtime.h>
#include <cuda_fp16.h>
#include <math.h>
#include <stdint.h>

// ---------------- problem constants (from setup_inputs, deterministic) ----------
#define LXX     2048
#define LCC     4096
#define DM      1024
#define NH      16
#define HDIM    64
#define HID     2816
#define LTOT    6144
#define LOUT    4096
#define POS_X   4096
#define POS_C   0
#define HWSP    2048
#define MAXPOS  6144

#define WSCALE     64.0f
#define WSCALE_INV 0.015625f
#define QSCALE     0.125f

// ---------------- scratch (device globals; no runtime allocation) ---------------
__device__ float  g_attn  [LXX * DM];          // a1 fp32 staging
__device__ float  g_h1    [LOUT * DM];
__device__ float  g_cos   [MAXPOS * 32];
__device__ float  g_sin   [MAXPOS * 32];

__device__ __half g_qkv_h [LTOT * 3 * DM];     // QKV projection, fp16
__device__ __half g_gateup[LOUT * 2 * HID];    // FFN1 output, fp16
__device__ __half g_act_h [LOUT * HID];        // A operand of weight GEMMs

// single fp16 weights [N][K], pre-scaled by WSCALE
__device__ __half g_wqkv[3 * DM * DM];
__device__ __half g_wout[DM * DM];
__device__ __half g_w13 [2 * HID * DM];
__device__ __half g_w2  [DM * HID];

// fp16 attention operands (Q pre-scaled by QSCALE)
__device__ __half g_qx[LXX * DM];
__device__ __half g_qs[2048 * DM];
__device__ __half g_kx[LXX * DM];
__device__ __half g_kc[LCC * DM];

// ---------------- helpers (portable: sm_80+ PTX) ----------------------------------
__device__ __forceinline__ uint32_t smem_to_u32(const void* p) {
    uint32_t a;
    asm("{ .reg .u64 t; cvta.to.shared.u64 t, %1; cvt.u32.u64 %0, t; }" : "=r"(a) : "l"(p));
    return a;
}
#define SMEM_SWIZZLE_128B(b) ((b) ^ (((b) >> 3) & 0x70))

__device__ __forceinline__ void cp16(uint32_t s, const void* g) {
    asm volatile("cp.async.cg.shared.global [%0], [%1], 16;" :: "r"(s), "l"(g) : "memory");
}
__device__ __forceinline__ void cp_commit() {
    asm volatile("cp.async.commit_group;" ::: "memory");
}
template<int N> __device__ __forceinline__ void cp_wait() {
    asm volatile("cp.async.wait_group %0;" :: "n"(N) : "memory");
}

__device__ __forceinline__ void ldsm_x4(uint32_t* r, uint32_t addr) {
    asm volatile("ldmatrix.sync.aligned.m8n8.x4.shared.b16 {%0,%1,%2,%3}, [%4];"
        : "=r"(r[0]), "=r"(r[1]), "=r"(r[2]), "=r"(r[3]) : "r"(addr));
}
__device__ __forceinline__ void ldsm_x4_t(uint32_t* r, uint32_t addr) {
    asm volatile("ldmatrix.sync.aligned.m8n8.x4.trans.shared.b16 {%0,%1,%2,%3}, [%4];"
        : "=r"(r[0]), "=r"(r[1]), "=r"(r[2]), "=r"(r[3]) : "r"(addr));
}
__device__ __forceinline__ void mma_f16(float* c, const uint32_t* a, const uint32_t* b) {
    asm volatile("mma.sync.aligned.m16n8k16.row.col.f32.f16.f16.f32 "
        "{%0,%1,%2,%3}, {%4,%5,%6,%7}, {%8,%9}, {%0,%1,%2,%3};"
        : "+f"(c[0]), "+f"(c[1]), "+f"(c[2]), "+f"(c[3])
        : "r"(a[0]), "r"(a[1]), "r"(a[2]), "r"(a[3]), "r"(b[0]), "r"(b[1]));
}

// fast exp on FMA pipe (x <= 0), rel err ~2e-6
__device__ __forceinline__ float fexp(float x) {
    x = fmaxf(x, -87.0f);
    float t = x * 1.4426950408889634f;
    float r = t + 12582912.0f;
    float n = r - 12582912.0f;
    float f = t - n;
    float p = 0.0013298820f;
    p = fmaf(p, f, 0.0096181291f);
    p = fmaf(p, f, 0.0555041087f);
    p = fmaf(p, f, 0.2402265069f);
    p = fmaf(p, f, 0.6931471806f);
    p = fmaf(p, f, 1.0f);
    int ni = (int)n;
    return p * __int_as_float((ni + 127) << 23);
}

// ---------------- rope cos/sin table (fp64 angles) -------------------------------
__global__ void build_rope_table() {
    int idx = blockIdx.x * blockDim.x + threadIdx.x;
    if (idx >= MAXPOS * 32) return;
    int pos = idx >> 5, j = idx & 31;
    double inv = pow(10000.0, -((double)(2 * j)) / 64.0);
    double ang = (double)pos * inv;
    g_cos[idx] = (float)cos(ang);
    g_sin[idx] = (float)sin(ang);
}

// ---------------- LayerNorm fused with fp16 output ---------------------------------
__global__ void ln_f16_kernel(const float* __restrict__ in,
                              __half* __restrict__ out,
                              const float* __restrict__ gam,
                              const float* __restrict__ bet) {
    __shared__ float sh[32];
    __shared__ float s_mean, s_rstd;
    int row = blockIdx.x, t = threadIdx.x;
    const float* x = in + (size_t)row * DM;
    float v[4];
    float s = 0.f;
#pragma unroll
    for (int i = 0; i < 4; i++) { v[i] = x[t + 256 * i]; s += v[i]; }
#pragma unroll
    for (int o = 16; o; o >>= 1) s += __shfl_xor_sync(0xffffffffu, s, o);
    if ((t & 31) == 0) sh[t >> 5] = s;
    __syncthreads();
    if (t < 32) {
        float z = (t < 8) ? sh[t] : 0.f;
#pragma unroll
        for (int o = 4; o; o >>= 1) z += __shfl_xor_sync(0xffffffffu, z, o);
        if (t == 0) s_mean = z * (1.f / 1024.f);
    }
    __syncthreads();
    float mean = s_mean;
    float q = 0.f;
#pragma unroll
    for (int i = 0; i < 4; i++) { float d = v[i] - mean; q += d * d; }
#pragma unroll
    for (int o = 16; o; o >>= 1) q += __shfl_xor_sync(0xffffffffu, q, o);
    if ((t & 31) == 0) sh[t >> 5] = q;
    __syncthreads();
    if (t < 32) {
        float z = (t < 8) ? sh[t] : 0.f;
#pragma unroll
        for (int o = 4; o; o >>= 1) z += __shfl_xor_sync(0xffffffffu, z, o);
        if (t == 0) s_rstd = rsqrtf(z * (1.f / 1024.f) + 1e-5f);
    }
    __syncthreads();
    float rstd = s_rstd;
#pragma unroll
    for (int i = 0; i < 4; i++) {
        int c = t + 256 * i;
        float r = (v[i] - mean) * rstd * gam[c] + bet[c];
        out[(size_t)row * DM + c] = __float2half(r);
    }
}

// ---------------- RoPE: fp16 strided in -> fp16 contiguous out ---------------------
__global__ void rope_f16_kernel(const __half* __restrict__ src, int lds,
                                __half* __restrict__ out,
                                int L, int pos0, float scale) {
    int idx = blockIdx.x * blockDim.x + threadIdx.x;
    if (idx >= L * 512) return;
    int j = idx & 31, h = (idx >> 5) & 15, l = idx >> 9;
    int pos = pos0 + l;
    float c = g_cos[pos * 32 + j], s = g_sin[pos * 32 + j];
    const __half* p = src + (size_t)l * lds + h * HDIM;
    float t1 = __half2float(p[j]), t2 = __half2float(p[j + 32]);
    size_t o = (size_t)l * DM + h * HDIM;
    out[o + j]      = __float2half((t1 * c - t2 * s) * scale);
    out[o + j + 32] = __float2half((t2 * c + t1 * s) * scale);
}

// ---------------- weight transpose + single fp16 (pre-scaled by WSCALE) ------------
__global__ void wt_f16_kernel(const float* __restrict__ w,
                              __half* __restrict__ o, int K, int N) {
    __shared__ float t[32][33];
    int n0 = blockIdx.x * 32, k0 = blockIdx.y * 32;
    int tx = threadIdx.x, ty = threadIdx.y;
#pragma unroll
    for (int i = 0; i < 32; i += 8)
        t[ty + i][tx] = w[(size_t)(k0 + ty + i) * N + n0 + tx];
    __syncthreads();
#pragma unroll
    for (int i = 0; i < 32; i += 8) {
        int n = n0 + ty + i, k = k0 + tx;
        o[(size_t)n * K + k] = __float2half(t[tx][ty + i] * WSCALE);
    }
}

// ---------------- silu(g)*u (fp16 in) fused with fp16 output ------------------------
__global__ void silu_mul_f16_kernel(const __half* __restrict__ gu,
                                    __half* __restrict__ out) {
    int col = blockIdx.x * 256 + threadIdx.x;
    int row = blockIdx.y;
    float g = __half2float(gu[(size_t)row * (2 * HID) + col]);
    float u = __half2float(gu[(size_t)row * (2 * HID) + HID + col]);
    float r = (g / (1.f + __expf(-g))) * u;
    out[(size_t)row * HID + col] = __float2half(r);
}

// ---------------- fp16 single-pass GEMM, cp.async 2-stage pipeline ------------------
// C = (1/WSCALE) * A[M][K] * B[N][K]^T (+bias). Out fp32 (+residual) or fp16 (Ch).
static const int GEMM_SMEM = 2 * 2 * 16384;   // 65536

__global__ void __launch_bounds__(256, 2)
mma_gemm_kernel(const __half* __restrict__ A, const __half* __restrict__ B,
                float* __restrict__ C, __half* __restrict__ Ch,
                const float* __restrict__ bias,
                const float* __restrict__ res0, const float* __restrict__ res1, int split,
                int M, int N, int K) {
    extern __shared__ char smem[];
    uint32_t sbase = smem_to_u32(smem);

    int tid = threadIdx.x;
    int wid = tid >> 5, lane = tid & 31;
    int wr = wid >> 2, wc = wid & 3;
    int m0 = blockIdx.y * 128, n0 = blockIdx.x * 128;

    int lr  = lane & 7;
    int lq  = lane >> 3;
    int qlo = lq & 1, qhi = lq >> 1;

    uint32_t aoff[4];
#pragma unroll
    for (int mt = 0; mt < 4; mt++) {
        int row = wr * 64 + mt * 16 + qlo * 8 + lr;
        aoff[mt] = (uint32_t)(row * 128) + (uint32_t)((qhi * 16) ^ ((row & 7) * 16));
    }
    uint32_t boff[2];
#pragma unroll
    for (int np = 0; np < 2; np++) {
        int row = wc * 32 + np * 16 + qhi * 8 + lr;
        boff[np] = (uint32_t)(row * 128) + (uint32_t)((qlo * 16) ^ ((row & 7) * 16));
    }

    auto issue = [&](int st, int kc0) {
        uint32_t base = sbase + (uint32_t)st * 32768;
#pragma unroll
        for (int it = 0; it < 4; it++) {
            int idx = tid + it * 256;
            int r = idx >> 3, q = idx & 7;
            uint32_t so = SMEM_SWIZZLE_128B((uint32_t)(r * 128 + q * 16));
            cp16(base + so,         A + (size_t)(m0 + r) * K + kc0 + q * 8);
            cp16(base + 16384 + so, B + (size_t)(n0 + r) * K + kc0 + q * 8);
        }
        cp_commit();
    };

    float acc[4][4][4] = {};
    int nchunks = K >> 6;

    issue(0, 0);
    for (int kc = 0; kc < nchunks; kc++) {
        int st = kc & 1;
        if (kc + 1 < nchunks) { issue(st ^ 1, (kc + 1) << 6); cp_wait<1>(); }
        else                  { cp_wait<0>(); }
        __syncthreads();

        uint32_t sA = sbase + (uint32_t)st * 32768;
        uint32_t sB = sA + 16384;

#pragma unroll
        for (int ks = 0; ks < 4; ks++) {
            uint32_t kx = (uint32_t)(ks << 5);
            uint32_t bh[2][4];
#pragma unroll
            for (int np = 0; np < 2; np++)
                ldsm_x4(bh[np], sB + (boff[np] ^ kx));
#pragma unroll
            for (int mt = 0; mt < 4; mt++) {
                uint32_t ah[4];
                ldsm_x4(ah, sA + (aoff[mt] ^ kx));
#pragma unroll
                for (int nt = 0; nt < 4; nt++)
                    mma_f16(acc[mt][nt], ah, &bh[nt >> 1][(nt & 1) * 2]);
            }
        }
        __syncthreads();
    }

    int g = lane >> 2, tg = lane & 3;
#pragma unroll
    for (int mt = 0; mt < 4; mt++) {
#pragma unroll
        for (int half = 0; half < 2; half++) {
            int row = m0 + wr * 64 + mt * 16 + g + half * 8;
            const float* rp = nullptr;
            if (res0) rp = ((row < split) ? res0 : res1) + (size_t)row * N;
#pragma unroll
            for (int nt = 0; nt < 4; nt++) {
                int col = n0 + wc * 32 + nt * 8 + tg * 2;
                float vx = acc[mt][nt][half * 2 + 0] * WSCALE_INV;
                float vy = acc[mt][nt][half * 2 + 1] * WSCALE_INV;
                if (bias) { vx += bias[col]; vy += bias[col + 1]; }
                if (Ch) {
                    *(__half2*)(Ch + (size_t)row * N + col) = __floats2half2_rn(vx, vy);
                } else {
                    if (rp) { vx += rp[col]; vy += rp[col + 1]; }
                    *(float2*)(C + (size_t)row * N + col) = make_float2(vx, vy);
                }
            }
        }
    }
}

// ---------------- fp16 single-pass flash attention, cp.async 2-stage ----------------
// Q single fp16 (pre-scaled QSCALE), K single fp16, V single fp16 (strided ldv).
// mode 0: write fp32 O; 1: read fp32 O, add, write fp16; 2: write fp16.
static const int ATTN_SMEM = 2 * 2 * 8192;    // 32768

__global__ void __launch_bounds__(128)
attn_mma(const __half* __restrict__ Q, const __half* __restrict__ K,
         const __half* __restrict__ V, int ldv,
         float* __restrict__ O, __half* __restrict__ Oh,
         int LK, int causal, int mode) {
    extern __shared__ char smema[];
    uint32_t sb = smem_to_u32(smema);

    int tid = threadIdx.x;
    int wid = tid >> 5, lane = tid & 31;
    int g = lane >> 2, tg = lane & 3;
    int lr = lane & 7, qlo = (lane >> 3) & 1, qhi = lane >> 4;
    int q0 = blockIdx.x * 64;
    int h  = blockIdx.y;

    // ---- stage Q, extract fragments ----
#pragma unroll
    for (int it = 0; it < 4; it++) {
        int e = tid + it * 128;           // 0..511
        int row = e >> 3, q = e & 7;
        uint32_t off = (uint32_t)(row * 128) + (uint32_t)((q * 16) ^ ((row & 7) * 16));
        *(uint4*)(smema + off) = *(const uint4*)(Q + (size_t)(q0 + row) * DM + h * HDIM + q * 8);
    }
    __syncthreads();
    uint32_t qf[4][4];
    {
        int arow = wid * 16 + qlo * 8 + lr;
        uint32_t abase = (uint32_t)(arow * 128) + (uint32_t)((qhi * 16) ^ ((arow & 7) * 16));
#pragma unroll
        for (int ks = 0; ks < 4; ks++)
            ldsm_x4(qf[ks], sb + (abase ^ (uint32_t)(ks << 5)));
    }
    __syncthreads();

    auto issue = [&](int st, int k0) {
        uint32_t base = sb + (uint32_t)st * 16384;
#pragma unroll
        for (int it = 0; it < 4; it++) {
            int e = tid + it * 128;
            int row = e >> 3, q = e & 7;
            uint32_t off = (uint32_t)(row * 128) + (uint32_t)((q * 16) ^ ((row & 7) * 16));
            cp16(base + off,        K + (size_t)(k0 + row) * DM + h * HDIM + q * 8);
            cp16(base + 8192 + off, V + (size_t)(k0 + row) * ldv + h * HDIM + q * 8);
        }
        cp_commit();
    };

    float o[8][4] = {};
    float m0r = -1e30f, m1r = -1e30f, l0r = 0.f, l1r = 0.f;

    int ntiles = causal ? ((int)blockIdx.x + 1) : (LK >> 6);
    issue(0, 0);
    for (int kt = 0; kt < ntiles; kt++) {
        int k0 = kt << 6;
        int st = kt & 1;
        if (kt + 1 < ntiles) { issue(st ^ 1, (kt + 1) << 6); cp_wait<1>(); }
        else                 { cp_wait<0>(); }
        __syncthreads();

        uint32_t sK = sb + (uint32_t)st * 16384;
        uint32_t sV = sK + 8192;

        // ---- S = Q K^T (single pass) ----
        float s[8][4] = {};
#pragma unroll
        for (int ks = 0; ks < 4; ks++) {
            uint32_t kx = (uint32_t)(ks << 5);
            uint32_t bf[4][4];
#pragma unroll
            for (int np = 0; np < 4; np++) {
                int br = np * 16 + qhi * 8 + lr;
                uint32_t boff = (uint32_t)(br * 128) +
                                (uint32_t)(((qlo * 16) ^ (int)kx) ^ ((br & 7) * 16));
                ldsm_x4(bf[np], sK + boff);
            }
#pragma unroll
            for (int nt = 0; nt < 8; nt++)
                mma_f16(s[nt], qf[ks], &bf[nt >> 1][(nt & 1) * 2]);
        }

        // ---- causal mask (diagonal tile only) ----
        if (causal && kt == (int)blockIdx.x) {
            int r0 = q0 + wid * 16 + g, r1 = r0 + 8;
#pragma unroll
            for (int nt = 0; nt < 8; nt++) {
                int kbase = k0 + nt * 8 + tg * 2;
                if (kbase > r0)     s[nt][0] = -1e30f;
                if (kbase + 1 > r0) s[nt][1] = -1e30f;
                if (kbase > r1)     s[nt][2] = -1e30f;
                if (kbase + 1 > r1) s[nt][3] = -1e30f;
            }
        }

        // ---- online softmax ----
        float mx0 = -1e30f, mx1 = -1e30f;
#pragma unroll
        for (int nt = 0; nt < 8; nt++) {
            mx0 = fmaxf(mx0, fmaxf(s[nt][0], s[nt][1]));
            mx1 = fmaxf(mx1, fmaxf(s[nt][2], s[nt][3]));
        }
        mx0 = fmaxf(mx0, __shfl_xor_sync(0xffffffffu, mx0, 1));
        mx0 = fmaxf(mx0, __shfl_xor_sync(0xffffffffu, mx0, 2));
        mx1 = fmaxf(mx1, __shfl_xor_sync(0xffffffffu, mx1, 1));
        mx1 = fmaxf(mx1, __shfl_xor_sync(0xffffffffu, mx1, 2));
        float mn0 = fmaxf(m0r, mx0), mn1 = fmaxf(m1r, mx1);
        float al0 = fexp(m0r - mn0), al1 = fexp(m1r - mn1);
        float sum0 = 0.f, sum1 = 0.f;
#pragma unroll
        for (int nt = 0; nt < 8; nt++) {
            s[nt][0] = fexp(s[nt][0] - mn0);
            s[nt][1] = fexp(s[nt][1] - mn0);
            s[nt][2] = fexp(s[nt][2] - mn1);
            s[nt][3] = fexp(s[nt][3] - mn1);
            sum0 += s[nt][0] + s[nt][1];
            sum1 += s[nt][2] + s[nt][3];
        }
        sum0 += __shfl_xor_sync(0xffffffffu, sum0, 1);
        sum0 += __shfl_xor_sync(0xffffffffu, sum0, 2);
        sum1 += __shfl_xor_sync(0xffffffffu, sum1, 1);
        sum1 += __shfl_xor_sync(0xffffffffu, sum1, 2);
        l0r = l0r * al0 + sum0; m0r = mn0;
        l1r = l1r * al1 + sum1; m1r = mn1;
#pragma unroll
        for (int nt = 0; nt < 8; nt++) {
            o[nt][0] *= al0; o[nt][1] *= al0;
            o[nt][2] *= al1; o[nt][3] *= al1;
        }

        // ---- O += P V (single pass), V via ldmatrix.trans ----
#pragma unroll
        for (int kb = 0; kb < 4; kb++) {
            uint32_t ph[4];
            {
                __half2 p0 = __floats2half2_rn(s[2 * kb][0],     s[2 * kb][1]);
                __half2 p1 = __floats2half2_rn(s[2 * kb][2],     s[2 * kb][3]);
                __half2 p2 = __floats2half2_rn(s[2 * kb + 1][0], s[2 * kb + 1][1]);
                __half2 p3 = __floats2half2_rn(s[2 * kb + 1][2], s[2 * kb + 1][3]);
                ph[0] = *(uint32_t*)&p0; ph[1] = *(uint32_t*)&p1;
                ph[2] = *(uint32_t*)&p2; ph[3] = *(uint32_t*)&p3;
            }
            uint32_t vf[4][4];
            int vr = kb * 16 + qlo * 8 + lr;
            uint32_t vrow = (uint32_t)(vr * 128);
            uint32_t vsw  = (uint32_t)((vr & 7) * 16);
#pragma unroll
            for (int np = 0; np < 4; np++)
                ldsm_x4_t(vf[np], sV + vrow + (((uint32_t)(np * 32 + qhi * 16)) ^ vsw));
#pragma unroll
            for (int nt = 0; nt < 8; nt++)
                mma_f16(o[nt], ph, &vf[nt >> 1][(nt & 1) * 2]);
        }
        __syncthreads();
    }

    // ---- epilogue ----
    float inv0 = 1.f / l0r, inv1 = 1.f / l1r;
    int row0 = q0 + wid * 16 + g;
    int row1 = row0 + 8;
#pragma unroll
    for (int nt = 0; nt < 8; nt++) {
        int col = h * HDIM + nt * 8 + tg * 2;
        float v00 = o[nt][0] * inv0, v01 = o[nt][1] * inv0;
        float v10 = o[nt][2] * inv1, v11 = o[nt][3] * inv1;
        if (mode == 0) {
            *(float2*)(O + (size_t)row0 * DM + col) = make_float2(v00, v01);
            *(float2*)(O + (size_t)row1 * DM + col) = make_float2(v10, v11);
        } else {
            if (mode == 1) {
                float2 a0 = *(float2*)(O + (size_t)row0 * DM + col);
                float2 a1 = *(float2*)(O + (size_t)row1 * DM + col);
                v00 += a0.x; v01 += a0.y; v10 += a1.x; v11 += a1.y;
            }
            *(__half2*)(Oh + (size_t)row0 * DM + col) = __floats2half2_rn(v00, v01);
            *(__half2*)(Oh + (size_t)row1 * DM + col) = __floats2half2_rn(v10, v11);
        }
    }
}

// ---------------- host orchestration ----------------------------------------------
extern "C" void kernel_launch(void* const* d_in, const int* in_sizes, int n_in,
                              void* d_out, int out_size) {
    const float* x     = (const float*)d_in[0];
    const float* ctx   = (const float*)d_in[1];
    const float* qkv_w = (const float*)d_in[2];
    const float* qkv_b = (const float*)d_in[3];
    const float* out_w = (const float*)d_in[4];
    const float* out_b = (const float*)d_in[5];
    const float* w1    = (const float*)d_in[6];
    const float* w3    = (const float*)d_in[7];
    const float* w2    = (const float*)d_in[8];
    const float* n1g   = (const float*)d_in[9];
    const float* n1b   = (const float*)d_in[10];
    const float* n2g   = (const float*)d_in[11];
    const float* n2b   = (const float*)d_in[12];
    float* out = (float*)d_out;

    cudaFuncSetAttribute(mma_gemm_kernel, cudaFuncAttributeMaxDynamicSharedMemorySize, GEMM_SMEM);
    cudaFuncSetAttribute(attn_mma, cudaFuncAttributeMaxDynamicSharedMemorySize, ATTN_SMEM);

    void* p;
    cudaGetSymbolAddress(&p, g_attn);   float* attn   = (float*)p;
    cudaGetSymbolAddress(&p, g_h1);     float* h1     = (float*)p;
    cudaGetSymbolAddress(&p, g_qkv_h);  __half* qkvh  = (__half*)p;
    cudaGetSymbolAddress(&p, g_gateup); __half* gateup = (__half*)p;
    cudaGetSymbolAddress(&p, g_act_h);  __half* ah    = (__half*)p;
    cudaGetSymbolAddress(&p, g_wqkv);   __half* wq  = (__half*)p;
    cudaGetSymbolAddress(&p, g_wout);   __half* wo  = (__half*)p;
    cudaGetSymbolAddress(&p, g_w13);    __half* w13 = (__half*)p;
    cudaGetSymbolAddress(&p, g_w2);     __half* w2p = (__half*)p;
    cudaGetSymbolAddress(&p, g_qx);     __half* qx  = (__half*)p;
    cudaGetSymbolAddress(&p, g_qs);     __half* qs  = (__half*)p;
    cudaGetSymbolAddress(&p, g_kx);     __half* kx  = (__half*)p;
    cudaGetSymbolAddress(&p, g_kc);     __half* kc  = (__half*)p;

    dim3 tb(32, 8);
    build_rope_table<<<(MAXPOS * 32 + 255) / 256, 256>>>();

    // weight transpose + single fp16 (pre-scaled); w1,w3 packed [5632][1024]
    wt_f16_kernel<<<dim3(3 * DM / 32, DM / 32), tb>>>(qkv_w, wq, DM, 3 * DM);
    wt_f16_kernel<<<dim3(DM / 32, DM / 32),     tb>>>(out_w, wo, DM, DM);
    wt_f16_kernel<<<dim3(HID / 32, DM / 32),    tb>>>(w1, w13, DM, HID);
    wt_f16_kernel<<<dim3(HID / 32, DM / 32),    tb>>>(w3, w13 + (size_t)HID * DM, DM, HID);
    wt_f16_kernel<<<dim3(DM / 32, HID / 32),    tb>>>(w2, w2p, HID, DM);

    // LN1 -> fp16 A buffer [LTOT][DM]
    ln_f16_kernel<<<LXX, 256>>>(x,   ah,                    n1g, n1b);
    ln_f16_kernel<<<LCC, 256>>>(ctx, ah + (size_t)LXX * DM, n1g, n1b);

    // QKV projection (fp16 out, bias)
    mma_gemm_kernel<<<dim3(3 * DM / 128, LTOT / 128), 256, GEMM_SMEM>>>(
        ah, wq, nullptr, qkvh, qkv_b, nullptr, nullptr, 0, LTOT, 3 * DM, DM);

    // RoPE: Q (QSCALE) and K (1.0) to contiguous fp16; V stays in qkvh (strided)
    rope_f16_kernel<<<(LXX * 512 + 255) / 256, 256>>>(qkvh, 3 * DM, qx, LXX, POS_X, QSCALE);
    rope_f16_kernel<<<(2048 * 512 + 255) / 256, 256>>>(qkvh + (size_t)(LXX + HWSP) * 3 * DM, 3 * DM, qs, 2048, HWSP, QSCALE);
    rope_f16_kernel<<<(LXX * 512 + 255) / 256, 256>>>(qkvh + DM, 3 * DM, kx, LXX, POS_X, 1.f);
    rope_f16_kernel<<<(LCC * 512 + 255) / 256, 256>>>(qkvh + (size_t)LXX * 3 * DM + DM, 3 * DM, kc, LCC, POS_C, 1.f);

    const __half* vx = qkvh + 2 * DM;                          // rows 0..2047 (strided)
    const __half* vc = qkvh + (size_t)LXX * 3 * DM + 2 * DM;   // rows 2048..6143 (strided)

    // a1 (mode 0: fp32 staging) ; a2 (mode 1: +a1 -> fp16) ; a3 (mode 2: fp16)
    attn_mma<<<dim3(LXX / 64, NH), 128, ATTN_SMEM>>>(qx, kc, vc, 3 * DM,
        attn, nullptr, LCC, 0, 0);
    attn_mma<<<dim3(LXX / 64, NH), 128, ATTN_SMEM>>>(qx, kx, vx, 3 * DM,
        attn, ah, LXX, 1, 1);
    attn_mma<<<dim3(2048 / 64, NH), 128, ATTN_SMEM>>>(qs, kc, vc, 3 * DM,
        nullptr, ah + (size_t)2048 * DM, LCC, 0, 2);

    // out projection + bias + residual -> h1 (fp32)
    mma_gemm_kernel<<<dim3(DM / 128, LOUT / 128), 256, GEMM_SMEM>>>(
        ah, wo, h1, nullptr, out_b, x, ctx, 2048, LOUT, DM, DM);

    // LN2 -> fp16
    ln_f16_kernel<<<LOUT, 256>>>(h1, ah, n2g, n2b);

    // FFN: combined w1|w3 GEMM -> gateup (fp16), fused silu*mul -> fp16, w2 GEMM
    mma_gemm_kernel<<<dim3(2 * HID / 128, LOUT / 128), 256, GEMM_SMEM>>>(
        ah, w13, nullptr, gateup, nullptr, nullptr, nullptr, 0, LOUT, 2 * HID, DM);
    silu_mul_f16_kernel<<<dim3(HID / 256, LOUT), 256>>>(gateup, ah);
    mma_gemm_kernel<<<dim3(DM / 128, LOUT / 128), 256, GEMM_SMEM>>>(
        ah, w2p, out, nullptr, nullptr, h1, h1, LOUT, LOUT, DM, HID);
}